// round 1
// baseline (speedup 1.0000x reference)
#include <cuda_runtime.h>
#include <math_constants.h>

#define BSZ   2
#define SEQ   2048
#define DIM   4096
#define NH    32
#define NKV   8
#define HD    128
#define MROWS (BSZ*SEQ)   /* 4096 */
#define QW    (NH*HD)     /* 4096 */
#define KW    (NKV*HD)    /* 1024 */

// Scratch (static device memory — no allocations allowed)
__device__ float g_q[(size_t)MROWS * QW];     // 64 MB
__device__ float g_k[(size_t)MROWS * KW];     // 16 MB
__device__ float g_v[(size_t)MROWS * KW];     // 16 MB
__device__ float g_attn[(size_t)MROWS * QW];  // 64 MB

// ---------------------------------------------------------------------------
// SGEMM: C[M,N] = A[M,K] @ B[K,N], all row-major, M%128==0, N%128==0, K%16==0
// 128x128 block tile, BK=16, 256 threads, 8x8 register tile per thread.
// ---------------------------------------------------------------------------
__global__ __launch_bounds__(256)
void sgemm_kernel(const float* __restrict__ A, const float* __restrict__ B,
                  float* __restrict__ C, int M, int N, int K)
{
    __shared__ float As[16][128];   // transposed A tile: As[k][m]
    __shared__ float Bs[16][128];   // Bs[k][n]

    const int tid = threadIdx.x;
    const int m0  = blockIdx.y * 128;
    const int n0  = blockIdx.x * 128;
    const int tr  = tid >> 4;       // 0..15
    const int tc  = tid & 15;       // 0..15

    const int arow = tid >> 2;            // 0..63
    const int acol = (tid & 3) << 2;      // 0,4,8,12
    const int brow = tid >> 5;            // 0..7
    const int bcol = (tid & 31) << 2;     // 0..124

    const float* Ap = A + (size_t)(m0 + arow) * K + acol;
    const float* Bp = B + (size_t)brow * N + (n0 + bcol);

    float acc[8][8];
#pragma unroll
    for (int i = 0; i < 8; i++)
#pragma unroll
        for (int j = 0; j < 8; j++) acc[i][j] = 0.0f;

    for (int k0 = 0; k0 < K; k0 += 16) {
        float4 a0 = *(const float4*)(Ap + k0);
        float4 a1 = *(const float4*)(Ap + (size_t)64 * K + k0);
        float4 b0 = *(const float4*)(Bp + (size_t)k0 * N);
        float4 b1 = *(const float4*)(Bp + (size_t)(k0 + 8) * N);

        As[acol + 0][arow] = a0.x; As[acol + 1][arow] = a0.y;
        As[acol + 2][arow] = a0.z; As[acol + 3][arow] = a0.w;
        As[acol + 0][arow + 64] = a1.x; As[acol + 1][arow + 64] = a1.y;
        As[acol + 2][arow + 64] = a1.z; As[acol + 3][arow + 64] = a1.w;
        *(float4*)&Bs[brow][bcol]     = b0;
        *(float4*)&Bs[brow + 8][bcol] = b1;
        __syncthreads();

#pragma unroll
        for (int k = 0; k < 16; k++) {
            float4 am0 = *(const float4*)&As[k][tr * 8];
            float4 am1 = *(const float4*)&As[k][tr * 8 + 4];
            float4 bn0 = *(const float4*)&Bs[k][tc * 8];
            float4 bn1 = *(const float4*)&Bs[k][tc * 8 + 4];
            float rm[8] = {am0.x, am0.y, am0.z, am0.w, am1.x, am1.y, am1.z, am1.w};
            float rn[8] = {bn0.x, bn0.y, bn0.z, bn0.w, bn1.x, bn1.y, bn1.z, bn1.w};
#pragma unroll
            for (int i = 0; i < 8; i++)
#pragma unroll
                for (int j = 0; j < 8; j++)
                    acc[i][j] = fmaf(rm[i], rn[j], acc[i][j]);
        }
        __syncthreads();
    }

#pragma unroll
    for (int i = 0; i < 8; i++) {
        float* cp = C + (size_t)(m0 + tr * 8 + i) * N + n0 + tc * 8;
        *(float4*)cp       = make_float4(acc[i][0], acc[i][1], acc[i][2], acc[i][3]);
        *(float4*)(cp + 4) = make_float4(acc[i][4], acc[i][5], acc[i][6], acc[i][7]);
    }
}

// ---------------------------------------------------------------------------
// RoPE applied in place to g_q and g_k. One thread per (row, head, pair).
// ---------------------------------------------------------------------------
__global__ void rope_kernel(const float* __restrict__ fc, const float* __restrict__ fs)
{
    const int QP = MROWS * NH * (HD / 2);   // 8,388,608
    const int KP = MROWS * NKV * (HD / 2);  // 2,097,152
    int idx = blockIdx.x * blockDim.x + threadIdx.x;
    if (idx >= QP + KP) return;

    float2* p;
    int i, s;
    if (idx < QP) {
        i = idx & 63;
        int rest = idx >> 6;
        int hh   = rest & 31;
        int row  = rest >> 5;
        s = row & (SEQ - 1);
        p = (float2*)(g_q + (size_t)row * QW + hh * HD) + i;
    } else {
        int li = idx - QP;
        i = li & 63;
        int rest = li >> 6;
        int hh   = rest & 7;
        int row  = rest >> 3;
        s = row & (SEQ - 1);
        p = (float2*)(g_k + (size_t)row * KW + hh * HD) + i;
    }
    float c  = fc[s * 64 + i];
    float sn = fs[s * 64 + i];
    float2 v = *p;
    float2 o;
    o.x = v.x * c - v.y * sn;
    o.y = v.x * sn + v.y * c;
    *p = o;
}

// ---------------------------------------------------------------------------
// Flash attention (causal). Block = 64 query rows of one (b,h). 256 threads.
// Online softmax with K tiles of 64. GQA: kv head = h/4.
// smem (floats): Qs[128][64] | Ks[128][64] | Vs[64][128] | Ps[64][68]
//                | red1[64][4] | red2[64][4] | m[64] | l[64] | corr[64]
// ---------------------------------------------------------------------------
#define FA_SMEM_FLOATS 29632

__global__ __launch_bounds__(256)
void flash_kernel()
{
    extern __shared__ float sm[];
    float* Qs     = sm;            // d-major [128][64]
    float* Ks     = sm + 8192;     // d-major [128][64]
    float* Vs     = sm + 16384;    // [64][128]
    float* Ps     = sm + 24576;    // [64][68]
    float* red1   = sm + 28928;    // [64][4]
    float* red2   = sm + 29184;    // [64][4]
    float* m_s    = sm + 29440;    // [64]
    float* l_s    = sm + 29504;    // [64]
    float* corr_s = sm + 29568;    // [64]

    const int qb  = blockIdx.x;   // 0..31
    const int h   = blockIdx.y;   // 0..31
    const int b   = blockIdx.z;   // 0..1
    const int kvh = h >> 2;
    const int tid = threadIdx.x;

    const int lr = tid >> 2;      // 0..63 (load row)
    const int lf = tid & 3;       // 0..3

    const float SCALE = 0.08838834764831845f;  // 1/sqrt(128)

    // Load Q tile, transposed to d-major, pre-scaled
    const float* qbase = g_q + (size_t)(b * SEQ + qb * 64) * QW + h * HD;
#pragma unroll
    for (int it = 0; it < 8; it++) {
        int d = (lf + it * 4) << 2;
        float4 v = *(const float4*)(qbase + (size_t)lr * QW + d);
        Qs[(d + 0) * 64 + lr] = v.x * SCALE;
        Qs[(d + 1) * 64 + lr] = v.y * SCALE;
        Qs[(d + 2) * 64 + lr] = v.z * SCALE;
        Qs[(d + 3) * 64 + lr] = v.w * SCALE;
    }
    if (tid < 64) { m_s[tid] = -CUDART_INF_F; l_s[tid] = 0.0f; }

    const int tr = tid >> 4, tc = tid & 15;
    const int r0 = tr * 4;        // O/S rows
    const int c0 = tc * 4;        // S cols
    const int cv = tc * 8;        // O cols
    const int rowid = tid >> 2, part = tid & 3;

    float O[4][8];
#pragma unroll
    for (int i = 0; i < 4; i++)
#pragma unroll
        for (int j = 0; j < 8; j++) O[i][j] = 0.0f;

    for (int kb = 0; kb <= qb; kb++) {
        __syncthreads();  // protect Ks/Vs (prev PV) and Qs/m/l init (first iter)

        const float* kbase = g_k + (size_t)(b * SEQ + kb * 64) * KW + kvh * HD;
        const float* vbase = g_v + (size_t)(b * SEQ + kb * 64) * KW + kvh * HD;
#pragma unroll
        for (int it = 0; it < 8; it++) {
            int d = (lf + it * 4) << 2;
            float4 v = *(const float4*)(kbase + (size_t)lr * KW + d);
            Ks[(d + 0) * 64 + lr] = v.x; Ks[(d + 1) * 64 + lr] = v.y;
            Ks[(d + 2) * 64 + lr] = v.z; Ks[(d + 3) * 64 + lr] = v.w;
        }
#pragma unroll
        for (int it = 0; it < 8; it++) {
            int lin = tid + it * 256;
            int j = lin >> 5, d4 = (lin & 31) << 2;
            *(float4*)&Vs[j * 128 + d4] = *(const float4*)(vbase + (size_t)j * KW + d4);
        }
        __syncthreads();

        // S = (Q*scale) @ K^T  (4x4 per thread)
        float acc[4][4];
#pragma unroll
        for (int i = 0; i < 4; i++)
#pragma unroll
            for (int j = 0; j < 4; j++) acc[i][j] = 0.0f;
#pragma unroll 8
        for (int d = 0; d < 128; d++) {
            float4 q4 = *(const float4*)&Qs[d * 64 + r0];
            float4 k4 = *(const float4*)&Ks[d * 64 + c0];
            float rq[4] = {q4.x, q4.y, q4.z, q4.w};
            float rk[4] = {k4.x, k4.y, k4.z, k4.w};
#pragma unroll
            for (int i = 0; i < 4; i++)
#pragma unroll
                for (int j = 0; j < 4; j++)
                    acc[i][j] = fmaf(rq[i], rk[j], acc[i][j]);
        }

        // write S with causal mask (only bites on the diagonal tile)
        const int gq0 = qb * 64 + r0;
        const int gk0 = kb * 64 + c0;
#pragma unroll
        for (int i = 0; i < 4; i++)
#pragma unroll
            for (int j = 0; j < 4; j++) {
                float s = acc[i][j];
                if (gk0 + j > gq0 + i) s = -1e9f;
                Ps[(r0 + i) * 68 + c0 + j] = s;
            }
        __syncthreads();

        // online softmax: 4 threads per row
        float pm = -CUDART_INF_F;
#pragma unroll
        for (int i = 0; i < 16; i++)
            pm = fmaxf(pm, Ps[rowid * 68 + part * 16 + i]);
        red1[rowid * 4 + part] = pm;
        __syncthreads();

        float m_old = m_s[rowid];
        float m_new = fmaxf(fmaxf(red1[rowid * 4 + 0], red1[rowid * 4 + 1]),
                            fmaxf(red1[rowid * 4 + 2], red1[rowid * 4 + 3]));
        m_new = fmaxf(m_new, m_old);
        float psum = 0.0f;
#pragma unroll
        for (int i = 0; i < 16; i++) {
            float p = __expf(Ps[rowid * 68 + part * 16 + i] - m_new);
            Ps[rowid * 68 + part * 16 + i] = p;
            psum += p;
        }
        red2[rowid * 4 + part] = psum;
        __syncthreads();

        if (part == 0) {
            float corr = __expf(m_old - m_new);
            corr_s[rowid] = corr;
            l_s[rowid] = l_s[rowid] * corr +
                         red2[rowid * 4 + 0] + red2[rowid * 4 + 1] +
                         red2[rowid * 4 + 2] + red2[rowid * 4 + 3];
            m_s[rowid] = m_new;
        }
        __syncthreads();

        // rescale O, then O += P @ V (4x8 per thread)
#pragma unroll
        for (int i = 0; i < 4; i++) {
            float cr = corr_s[r0 + i];
#pragma unroll
            for (int j = 0; j < 8; j++) O[i][j] *= cr;
        }
#pragma unroll 4
        for (int jj = 0; jj < 64; jj++) {
            float4 v0 = *(const float4*)&Vs[jj * 128 + cv];
            float4 v1 = *(const float4*)&Vs[jj * 128 + cv + 4];
            float vv[8] = {v0.x, v0.y, v0.z, v0.w, v1.x, v1.y, v1.z, v1.w};
            float pp[4];
#pragma unroll
            for (int i = 0; i < 4; i++) pp[i] = Ps[(r0 + i) * 68 + jj];
#pragma unroll
            for (int i = 0; i < 4; i++)
#pragma unroll
                for (int j = 0; j < 8; j++)
                    O[i][j] = fmaf(pp[i], vv[j], O[i][j]);
        }
    }

    // epilogue: divide by l and store to g_attn in (b,s,h,d) layout
    float* obase = g_attn + (size_t)(b * SEQ + qb * 64) * QW + h * HD;
#pragma unroll
    for (int i = 0; i < 4; i++) {
        float inv = 1.0f / l_s[r0 + i];
        float* op = obase + (size_t)(r0 + i) * QW + cv;
        *(float4*)op       = make_float4(O[i][0] * inv, O[i][1] * inv, O[i][2] * inv, O[i][3] * inv);
        *(float4*)(op + 4) = make_float4(O[i][4] * inv, O[i][5] * inv, O[i][6] * inv, O[i][7] * inv);
    }
}

// ---------------------------------------------------------------------------
// Launch: QKV GEMMs -> RoPE -> flash attention -> output GEMM
// ---------------------------------------------------------------------------
extern "C" void kernel_launch(void* const* d_in, const int* in_sizes, int n_in,
                              void* d_out, int out_size)
{
    const float* x  = (const float*)d_in[0];
    const float* wq = (const float*)d_in[1];
    const float* wk = (const float*)d_in[2];
    const float* wv = (const float*)d_in[3];
    const float* wo = (const float*)d_in[4];
    const float* fc = (const float*)d_in[7];
    const float* fs = (const float*)d_in[8];
    float* out = (float*)d_out;

    float *pq, *pk, *pv, *pa;
    cudaGetSymbolAddress((void**)&pq, g_q);
    cudaGetSymbolAddress((void**)&pk, g_k);
    cudaGetSymbolAddress((void**)&pv, g_v);
    cudaGetSymbolAddress((void**)&pa, g_attn);

    sgemm_kernel<<<dim3(QW / 128, MROWS / 128), 256>>>(x, wq, pq, MROWS, QW, DIM);
    sgemm_kernel<<<dim3(KW / 128, MROWS / 128), 256>>>(x, wk, pk, MROWS, KW, DIM);
    sgemm_kernel<<<dim3(KW / 128, MROWS / 128), 256>>>(x, wv, pv, MROWS, KW, DIM);

    const int total_pairs = MROWS * NH * (HD / 2) + MROWS * NKV * (HD / 2);
    rope_kernel<<<(total_pairs + 255) / 256, 256>>>(fc, fs);

    const size_t smem = FA_SMEM_FLOATS * sizeof(float);
    cudaFuncSetAttribute(flash_kernel, cudaFuncAttributeMaxDynamicSharedMemorySize, (int)smem);
    flash_kernel<<<dim3(SEQ / 64, NH, BSZ), 256, smem>>>();

    sgemm_kernel<<<dim3(DIM / 128, MROWS / 128), 256>>>(pa, wo, out, MROWS, DIM, DIM);
}

// round 3
// speedup vs baseline: 1.6122x; 1.6122x over previous
#include <cuda_runtime.h>
#include <cuda_bf16.h>
#include <math_constants.h>
#include <cstdint>

#define BSZ   2
#define SEQ   2048
#define DIM   4096
#define NH    32
#define NKV   8
#define HD    128
#define MROWS (BSZ*SEQ)   /* 4096 */
#define QW    (NH*HD)     /* 4096 */
#define KW    (NKV*HD)    /* 1024 */

// ---------------------------------------------------------------------------
// Static device scratch
// ---------------------------------------------------------------------------
__device__ float g_q[(size_t)MROWS * QW];
__device__ float g_k[(size_t)MROWS * KW];
__device__ float g_v[(size_t)MROWS * KW];
__device__ float g_attn[(size_t)MROWS * QW];

__device__ __nv_bfloat16 g_ah[(size_t)MROWS * DIM];
__device__ __nv_bfloat16 g_al[(size_t)MROWS * DIM];
__device__ __nv_bfloat16 g_wqh[(size_t)QW * DIM],  g_wql[(size_t)QW * DIM];
__device__ __nv_bfloat16 g_wkh[(size_t)KW * DIM],  g_wkl[(size_t)KW * DIM];
__device__ __nv_bfloat16 g_wvh[(size_t)KW * DIM],  g_wvl[(size_t)KW * DIM];
__device__ __nv_bfloat16 g_woh[(size_t)DIM * QW],  g_wol[(size_t)DIM * QW];

// ---------------------------------------------------------------------------
// PTX helpers (all sm_80/90-era: valid under compute_103 virtual target)
// ---------------------------------------------------------------------------
__device__ __forceinline__ uint32_t smem_u32(const void* p) {
    uint32_t a;
    asm("{ .reg .u64 t; cvta.to.shared.u64 t, %1; cvt.u32.u64 %0, t; }" : "=r"(a) : "l"(p));
    return a;
}
#define CP_ASYNC16(dst, src) \
    asm volatile("cp.async.cg.shared.global [%0], [%1], 16;" :: "r"(dst), "l"(src))
#define CP_COMMIT() asm volatile("cp.async.commit_group;" ::: "memory")
#define CP_WAIT(n)  asm volatile("cp.async.wait_group %0;" :: "n"(n) : "memory")

#define LDSM4(R0, R1, R2, R3, addr) \
    asm volatile("ldmatrix.sync.aligned.m8n8.x4.shared.b16 {%0,%1,%2,%3}, [%4];" \
        : "=r"(R0), "=r"(R1), "=r"(R2), "=r"(R3) : "r"(addr))

#define MMA16816(D, A, B0, B1) \
    asm volatile("mma.sync.aligned.m16n8k16.row.col.f32.bf16.bf16.f32 " \
        "{%0,%1,%2,%3},{%4,%5,%6,%7},{%8,%9},{%0,%1,%2,%3};" \
        : "+f"((D)[0]), "+f"((D)[1]), "+f"((D)[2]), "+f"((D)[3]) \
        : "r"((A)[0]), "r"((A)[1]), "r"((A)[2]), "r"((A)[3]), "r"(B0), "r"(B1))

// ---------------------------------------------------------------------------
// convert_split: fp32 -> bf16 hi + lo
// ---------------------------------------------------------------------------
__global__ void convert_split(const float* __restrict__ in,
                              __nv_bfloat16* __restrict__ oh,
                              __nv_bfloat16* __restrict__ ol, int n4)
{
    int i = blockIdx.x * blockDim.x + threadIdx.x;
    if (i >= n4) return;
    float4 v = ((const float4*)in)[i];
    union { __nv_bfloat16 b[4]; uint2 u; } H, L;
    float f[4] = {v.x, v.y, v.z, v.w};
#pragma unroll
    for (int q = 0; q < 4; q++) {
        __nv_bfloat16 h = __float2bfloat16_rn(f[q]);
        H.b[q] = h;
        L.b[q] = __float2bfloat16_rn(f[q] - __bfloat162float(h));
    }
    ((uint2*)oh)[i] = H.u;
    ((uint2*)ol)[i] = L.u;
}

// ---------------------------------------------------------------------------
// transpose_split: fp32 [R,C] -> bf16 [C,R] hi + lo
// ---------------------------------------------------------------------------
__global__ void transpose_split(const float* __restrict__ in,
                                __nv_bfloat16* __restrict__ oh,
                                __nv_bfloat16* __restrict__ ol, int R, int C)
{
    __shared__ float t[32][33];
    int c0 = blockIdx.x * 32, r0 = blockIdx.y * 32;
    int tx = threadIdx.x, ty = threadIdx.y;
#pragma unroll
    for (int i = 0; i < 4; i++)
        t[ty + 8 * i][tx] = in[(size_t)(r0 + ty + 8 * i) * C + c0 + tx];
    __syncthreads();
#pragma unroll
    for (int i = 0; i < 4; i++) {
        float v = t[tx][ty + 8 * i];
        __nv_bfloat16 h = __float2bfloat16_rn(v);
        __nv_bfloat16 l = __float2bfloat16_rn(v - __bfloat162float(h));
        size_t o = (size_t)(c0 + ty + 8 * i) * R + r0 + tx;
        oh[o] = h;
        ol[o] = l;
    }
}

// ---------------------------------------------------------------------------
// bf16 split GEMM via mma.sync: C[M,N] = (Ah+Al)[M,K] @ (Bh+Bl)[N,K]^T
// 3-term: Ah*Bh + Ah*Bl + Al*Bh, fp32 accum.
// Block 128x128, BK=32, 256 threads (8 warps as 2x4, warp tile 64x32).
// 4-stage cp.async pipeline, 40KB/stage, 160KB dynamic smem.
// smem stage layout (pitch 80B/row): Ah[128] +0 | Al +10240 | Bh +20480 | Bl +30720
// ---------------------------------------------------------------------------
#define GSTG_B  40960u
#define GSMEM_B (4u * GSTG_B)

__global__ __launch_bounds__(256, 1)
void gemm_mma(const __nv_bfloat16* __restrict__ Ah, const __nv_bfloat16* __restrict__ Al,
              const __nv_bfloat16* __restrict__ Bh, const __nv_bfloat16* __restrict__ Bl,
              float* __restrict__ C, int M, int N, int K)
{
    extern __shared__ char smc[];
    const uint32_t sb = smem_u32(smc);
    const int tid  = threadIdx.x;
    const int lane = tid & 31;
    const int wid  = tid >> 5;
    const int warp_m = wid >> 2;      // 0..1
    const int warp_n = wid & 3;       // 0..3
    const int m0 = blockIdx.y * 128;
    const int n0 = blockIdx.x * 128;
    const int NT = K >> 5;            // K/32 chunks

    // per-thread cp.async assignment: 8 chunks of 16B per stage
    // chunk c = tid + 256*j ; buf = c>>9 ; idx = c&511 ; row = idx>>2 ; kc = idx&3
    const __nv_bfloat16* srcbase[4];
    uint32_t dstoff[8];
    const __nv_bfloat16* srcrow[8];
#pragma unroll
    for (int j = 0; j < 8; j++) {
        int c   = tid + 256 * j;
        int buf = c >> 9;
        int idx = c & 511;
        int row = idx >> 2;
        int kc  = idx & 3;
        dstoff[j] = (uint32_t)buf * 10240u + (uint32_t)row * 80u + (uint32_t)kc * 16u;
        const __nv_bfloat16* base =
            (buf == 0) ? Ah + (size_t)(m0 + row) * K :
            (buf == 1) ? Al + (size_t)(m0 + row) * K :
            (buf == 2) ? Bh + (size_t)(n0 + row) * K :
                         Bl + (size_t)(n0 + row) * K;
        srcrow[j] = base + kc * 8;
    }
    (void)srcbase;

#define ISSUE_STAGE(kt) do { \
        uint32_t stb = sb + (uint32_t)((kt) & 3) * GSTG_B; \
        const int kel = (kt) << 5; \
        _Pragma("unroll") \
        for (int j = 0; j < 8; j++) \
            CP_ASYNC16(stb + dstoff[j], srcrow[j] + kel); \
        CP_COMMIT(); \
    } while (0)

    float acc[4][4][4];
#pragma unroll
    for (int a = 0; a < 4; a++)
#pragma unroll
        for (int b = 0; b < 4; b++)
#pragma unroll
            for (int d = 0; d < 4; d++) acc[a][b][d] = 0.0f;

    ISSUE_STAGE(0);
    ISSUE_STAGE(1);

    const uint32_t a_lrow = (uint32_t)(warp_m * 64 + (lane & 15)) * 80u + (uint32_t)(lane >> 4) * 16u;
    const uint32_t b_lrow = (uint32_t)(warp_n * 32 + (lane & 15)) * 80u + (uint32_t)(lane >> 4) * 16u;

    for (int kt = 0; kt < NT; kt++) {
        if (kt + 2 < NT) { ISSUE_STAGE(kt + 2); CP_WAIT(2); }
        else if (kt + 1 < NT) { CP_WAIT(1); }
        else { CP_WAIT(0); }
        __syncthreads();

        const uint32_t stb = sb + (uint32_t)(kt & 3) * GSTG_B;
#pragma unroll
        for (int k16 = 0; k16 < 2; k16++) {
            const uint32_t koff = (uint32_t)k16 * 32u;
            uint32_t ah[4][4], al[4][4];
#pragma unroll
            for (int mt = 0; mt < 4; mt++) {
                uint32_t addr = stb + a_lrow + (uint32_t)mt * (16u * 80u) + koff;
                LDSM4(ah[mt][0], ah[mt][1], ah[mt][2], ah[mt][3], addr);
                LDSM4(al[mt][0], al[mt][1], al[mt][2], al[mt][3], addr + 10240u);
            }
            uint32_t bh[2][4], bl[2][4];
#pragma unroll
            for (int bt = 0; bt < 2; bt++) {
                uint32_t addr = stb + 20480u + b_lrow + (uint32_t)bt * (16u * 80u) + koff;
                LDSM4(bh[bt][0], bh[bt][1], bh[bt][2], bh[bt][3], addr);
                LDSM4(bl[bt][0], bl[bt][1], bl[bt][2], bl[bt][3], addr + 10240u);
            }
#pragma unroll
            for (int mt = 0; mt < 4; mt++) {
#pragma unroll
                for (int nt = 0; nt < 4; nt++) {
                    const int bt = nt >> 1, hf = nt & 1;
                    MMA16816(acc[mt][nt], ah[mt], bh[bt][hf], bh[bt][hf + 2]);
                    MMA16816(acc[mt][nt], ah[mt], bl[bt][hf], bl[bt][hf + 2]);
                    MMA16816(acc[mt][nt], al[mt], bh[bt][hf], bh[bt][hf + 2]);
                }
            }
        }
    }

    // epilogue
#pragma unroll
    for (int mt = 0; mt < 4; mt++) {
        int row = m0 + warp_m * 64 + mt * 16 + (lane >> 2);
#pragma unroll
        for (int nt = 0; nt < 4; nt++) {
            int col = n0 + warp_n * 32 + nt * 8 + (lane & 3) * 2;
            *(float2*)(C + (size_t)row * N + col) =
                make_float2(acc[mt][nt][0], acc[mt][nt][1]);
            *(float2*)(C + (size_t)(row + 8) * N + col) =
                make_float2(acc[mt][nt][2], acc[mt][nt][3]);
        }
    }
#undef ISSUE_STAGE
}

// ---------------------------------------------------------------------------
// RoPE in place on g_q and g_k
// ---------------------------------------------------------------------------
__global__ void rope_kernel(const float* __restrict__ fc, const float* __restrict__ fs)
{
    const int QP = MROWS * NH * (HD / 2);
    const int KP = MROWS * NKV * (HD / 2);
    int idx = blockIdx.x * blockDim.x + threadIdx.x;
    if (idx >= QP + KP) return;

    float2* p;
    int i, s;
    if (idx < QP) {
        i = idx & 63;
        int rest = idx >> 6;
        int hh = rest & 31, row = rest >> 5;
        s = row & (SEQ - 1);
        p = (float2*)(g_q + (size_t)row * QW + hh * HD) + i;
    } else {
        int li = idx - QP;
        i = li & 63;
        int rest = li >> 6;
        int hh = rest & 7, row = rest >> 3;
        s = row & (SEQ - 1);
        p = (float2*)(g_k + (size_t)row * KW + hh * HD) + i;
    }
    float c = fc[s * 64 + i], sn = fs[s * 64 + i];
    float2 v = *p, o;
    o.x = v.x * c - v.y * sn;
    o.y = v.x * sn + v.y * c;
    *p = o;
}

// ---------------------------------------------------------------------------
// Flash attention (causal, fp32) — unchanged (known correct)
// ---------------------------------------------------------------------------
#define FA_SMEM_FLOATS 29632

__global__ __launch_bounds__(256)
void flash_kernel()
{
    extern __shared__ float sm[];
    float* Qs     = sm;
    float* Ks     = sm + 8192;
    float* Vs     = sm + 16384;
    float* Ps     = sm + 24576;
    float* red1   = sm + 28928;
    float* red2   = sm + 29184;
    float* m_s    = sm + 29440;
    float* l_s    = sm + 29504;
    float* corr_s = sm + 29568;

    const int qb = blockIdx.x, h = blockIdx.y, b = blockIdx.z;
    const int kvh = h >> 2;
    const int tid = threadIdx.x;
    const int lr = tid >> 2, lf = tid & 3;
    const float SCALE = 0.08838834764831845f;

    const float* qbase = g_q + (size_t)(b * SEQ + qb * 64) * QW + h * HD;
#pragma unroll
    for (int it = 0; it < 8; it++) {
        int d = (lf + it * 4) << 2;
        float4 v = *(const float4*)(qbase + (size_t)lr * QW + d);
        Qs[(d + 0) * 64 + lr] = v.x * SCALE;
        Qs[(d + 1) * 64 + lr] = v.y * SCALE;
        Qs[(d + 2) * 64 + lr] = v.z * SCALE;
        Qs[(d + 3) * 64 + lr] = v.w * SCALE;
    }
    if (tid < 64) { m_s[tid] = -CUDART_INF_F; l_s[tid] = 0.0f; }

    const int tr = tid >> 4, tc = tid & 15;
    const int r0 = tr * 4, c0 = tc * 4, cv = tc * 8;
    const int rowid = tid >> 2, part = tid & 3;

    float O[4][8];
#pragma unroll
    for (int i = 0; i < 4; i++)
#pragma unroll
        for (int j = 0; j < 8; j++) O[i][j] = 0.0f;

    for (int kb = 0; kb <= qb; kb++) {
        __syncthreads();

        const float* kbase = g_k + (size_t)(b * SEQ + kb * 64) * KW + kvh * HD;
        const float* vbase = g_v + (size_t)(b * SEQ + kb * 64) * KW + kvh * HD;
#pragma unroll
        for (int it = 0; it < 8; it++) {
            int d = (lf + it * 4) << 2;
            float4 v = *(const float4*)(kbase + (size_t)lr * KW + d);
            Ks[(d + 0) * 64 + lr] = v.x; Ks[(d + 1) * 64 + lr] = v.y;
            Ks[(d + 2) * 64 + lr] = v.z; Ks[(d + 3) * 64 + lr] = v.w;
        }
#pragma unroll
        for (int it = 0; it < 8; it++) {
            int lin = tid + it * 256;
            int j = lin >> 5, d4 = (lin & 31) << 2;
            *(float4*)&Vs[j * 128 + d4] = *(const float4*)(vbase + (size_t)j * KW + d4);
        }
        __syncthreads();

        float acc[4][4];
#pragma unroll
        for (int i = 0; i < 4; i++)
#pragma unroll
            for (int j = 0; j < 4; j++) acc[i][j] = 0.0f;
#pragma unroll 8
        for (int d = 0; d < 128; d++) {
            float4 q4 = *(const float4*)&Qs[d * 64 + r0];
            float4 k4 = *(const float4*)&Ks[d * 64 + c0];
            float rq[4] = {q4.x, q4.y, q4.z, q4.w};
            float rk[4] = {k4.x, k4.y, k4.z, k4.w};
#pragma unroll
            for (int i = 0; i < 4; i++)
#pragma unroll
                for (int j = 0; j < 4; j++)
                    acc[i][j] = fmaf(rq[i], rk[j], acc[i][j]);
        }

        const int gq0 = qb * 64 + r0, gk0 = kb * 64 + c0;
#pragma unroll
        for (int i = 0; i < 4; i++)
#pragma unroll
            for (int j = 0; j < 4; j++) {
                float s = acc[i][j];
                if (gk0 + j > gq0 + i) s = -1e9f;
                Ps[(r0 + i) * 68 + c0 + j] = s;
            }
        __syncthreads();

        float pm = -CUDART_INF_F;
#pragma unroll
        for (int i = 0; i < 16; i++)
            pm = fmaxf(pm, Ps[rowid * 68 + part * 16 + i]);
        red1[rowid * 4 + part] = pm;
        __syncthreads();

        float m_old = m_s[rowid];
        float m_new = fmaxf(fmaxf(red1[rowid * 4 + 0], red1[rowid * 4 + 1]),
                            fmaxf(red1[rowid * 4 + 2], red1[rowid * 4 + 3]));
        m_new = fmaxf(m_new, m_old);
        float psum = 0.0f;
#pragma unroll
        for (int i = 0; i < 16; i++) {
            float p = __expf(Ps[rowid * 68 + part * 16 + i] - m_new);
            Ps[rowid * 68 + part * 16 + i] = p;
            psum += p;
        }
        red2[rowid * 4 + part] = psum;
        __syncthreads();

        if (part == 0) {
            float corr = __expf(m_old - m_new);
            corr_s[rowid] = corr;
            l_s[rowid] = l_s[rowid] * corr +
                         red2[rowid * 4 + 0] + red2[rowid * 4 + 1] +
                         red2[rowid * 4 + 2] + red2[rowid * 4 + 3];
            m_s[rowid] = m_new;
        }
        __syncthreads();

#pragma unroll
        for (int i = 0; i < 4; i++) {
            float cr = corr_s[r0 + i];
#pragma unroll
            for (int j = 0; j < 8; j++) O[i][j] *= cr;
        }
#pragma unroll 4
        for (int jj = 0; jj < 64; jj++) {
            float4 v0 = *(const float4*)&Vs[jj * 128 + cv];
            float4 v1 = *(const float4*)&Vs[jj * 128 + cv + 4];
            float vv[8] = {v0.x, v0.y, v0.z, v0.w, v1.x, v1.y, v1.z, v1.w};
            float pp[4];
#pragma unroll
            for (int i = 0; i < 4; i++) pp[i] = Ps[(r0 + i) * 68 + jj];
#pragma unroll
            for (int i = 0; i < 4; i++)
#pragma unroll
                for (int j = 0; j < 8; j++)
                    O[i][j] = fmaf(pp[i], vv[j], O[i][j]);
        }
    }

    float* obase = g_attn + (size_t)(b * SEQ + qb * 64) * QW + h * HD;
#pragma unroll
    for (int i = 0; i < 4; i++) {
        float inv = 1.0f / l_s[r0 + i];
        float* op = obase + (size_t)(r0 + i) * QW + cv;
        *(float4*)op       = make_float4(O[i][0] * inv, O[i][1] * inv, O[i][2] * inv, O[i][3] * inv);
        *(float4*)(op + 4) = make_float4(O[i][4] * inv, O[i][5] * inv, O[i][6] * inv, O[i][7] * inv);
    }
}

// ---------------------------------------------------------------------------
// Launch
// ---------------------------------------------------------------------------
extern "C" void kernel_launch(void* const* d_in, const int* in_sizes, int n_in,
                              void* d_out, int out_size)
{
    const float* x  = (const float*)d_in[0];
    const float* wq = (const float*)d_in[1];
    const float* wk = (const float*)d_in[2];
    const float* wv = (const float*)d_in[3];
    const float* wo = (const float*)d_in[4];
    const float* fc = (const float*)d_in[7];
    const float* fs = (const float*)d_in[8];
    float* out = (float*)d_out;

    float *pq, *pk, *pv, *pa;
    cudaGetSymbolAddress((void**)&pq, g_q);
    cudaGetSymbolAddress((void**)&pk, g_k);
    cudaGetSymbolAddress((void**)&pv, g_v);
    cudaGetSymbolAddress((void**)&pa, g_attn);
    __nv_bfloat16 *pah, *pal, *pwqh, *pwql, *pwkh, *pwkl, *pwvh, *pwvl, *pwoh, *pwol;
    cudaGetSymbolAddress((void**)&pah, g_ah);
    cudaGetSymbolAddress((void**)&pal, g_al);
    cudaGetSymbolAddress((void**)&pwqh, g_wqh);
    cudaGetSymbolAddress((void**)&pwql, g_wql);
    cudaGetSymbolAddress((void**)&pwkh, g_wkh);
    cudaGetSymbolAddress((void**)&pwkl, g_wkl);
    cudaGetSymbolAddress((void**)&pwvh, g_wvh);
    cudaGetSymbolAddress((void**)&pwvl, g_wvl);
    cudaGetSymbolAddress((void**)&pwoh, g_woh);
    cudaGetSymbolAddress((void**)&pwol, g_wol);

    cudaFuncSetAttribute(gemm_mma, cudaFuncAttributeMaxDynamicSharedMemorySize, (int)GSMEM_B);
    cudaFuncSetAttribute(flash_kernel, cudaFuncAttributeMaxDynamicSharedMemorySize,
                         FA_SMEM_FLOATS * (int)sizeof(float));

    // split x, transpose+split weights
    convert_split<<<(MROWS * DIM / 4 + 255) / 256, 256>>>(x, pah, pal, MROWS * DIM / 4);
    transpose_split<<<dim3(QW / 32, DIM / 32), dim3(32, 8)>>>(wq, pwqh, pwql, DIM, QW);
    transpose_split<<<dim3(KW / 32, DIM / 32), dim3(32, 8)>>>(wk, pwkh, pwkl, DIM, KW);
    transpose_split<<<dim3(KW / 32, DIM / 32), dim3(32, 8)>>>(wv, pwvh, pwvl, DIM, KW);
    transpose_split<<<dim3(DIM / 32, QW / 32), dim3(32, 8)>>>(wo, pwoh, pwol, QW, DIM);

    // QKV projections on tensor cores (mma.sync bf16 split)
    gemm_mma<<<dim3(QW / 128, MROWS / 128), 256, GSMEM_B>>>(pah, pal, pwqh, pwql, pq, MROWS, QW, DIM);
    gemm_mma<<<dim3(KW / 128, MROWS / 128), 256, GSMEM_B>>>(pah, pal, pwkh, pwkl, pk, MROWS, KW, DIM);
    gemm_mma<<<dim3(KW / 128, MROWS / 128), 256, GSMEM_B>>>(pah, pal, pwvh, pwvl, pv, MROWS, KW, DIM);

    const int total_pairs = MROWS * NH * (HD / 2) + MROWS * NKV * (HD / 2);
    rope_kernel<<<(total_pairs + 255) / 256, 256>>>(fc, fs);

    flash_kernel<<<dim3(SEQ / 64, NH, BSZ), 256, FA_SMEM_FLOATS * sizeof(float)>>>();

    // split attention output, output projection
    convert_split<<<(MROWS * QW / 4 + 255) / 256, 256>>>(pa, pah, pal, MROWS * QW / 4);
    gemm_mma<<<dim3(DIM / 128, MROWS / 128), 256, GSMEM_B>>>(pah, pal, pwoh, pwol, out, MROWS, DIM, DIM);
}

// round 4
// speedup vs baseline: 2.2558x; 1.3992x over previous
#include <cuda_runtime.h>
#include <cuda_bf16.h>
#include <math_constants.h>
#include <cstdint>

#define BSZ   2
#define SEQ   2048
#define DIM   4096
#define NH    32
#define NKV   8
#define HD    128
#define MROWS (BSZ*SEQ)   /* 4096 */
#define QW    (NH*HD)     /* 4096 */
#define KW    (NKV*HD)    /* 1024 */

// ---------------------------------------------------------------------------
// Static device scratch
// ---------------------------------------------------------------------------
__device__ float g_q[(size_t)MROWS * QW];
__device__ float g_k[(size_t)MROWS * KW];
__device__ float g_v[(size_t)MROWS * KW];
__device__ float g_attn[(size_t)MROWS * QW];

__device__ __nv_bfloat16 g_ah[(size_t)MROWS * DIM];   // x-split, then Q-split, then attn-split
__device__ __nv_bfloat16 g_al[(size_t)MROWS * DIM];
__device__ __nv_bfloat16 g_kh[(size_t)MROWS * KW], g_kl[(size_t)MROWS * KW];
__device__ __nv_bfloat16 g_vh[(size_t)MROWS * KW], g_vl[(size_t)MROWS * KW];
__device__ __nv_bfloat16 g_wqh[(size_t)QW * DIM],  g_wql[(size_t)QW * DIM];
__device__ __nv_bfloat16 g_wkh[(size_t)KW * DIM],  g_wkl[(size_t)KW * DIM];
__device__ __nv_bfloat16 g_wvh[(size_t)KW * DIM],  g_wvl[(size_t)KW * DIM];
__device__ __nv_bfloat16 g_woh[(size_t)DIM * QW],  g_wol[(size_t)DIM * QW];

// ---------------------------------------------------------------------------
// PTX helpers (sm_80-era — valid under the compute_103 virtual target)
// ---------------------------------------------------------------------------
__device__ __forceinline__ uint32_t smem_u32(const void* p) {
    uint32_t a;
    asm("{ .reg .u64 t; cvta.to.shared.u64 t, %1; cvt.u32.u64 %0, t; }" : "=r"(a) : "l"(p));
    return a;
}
#define CP_ASYNC16(dst, src) \
    asm volatile("cp.async.cg.shared.global [%0], [%1], 16;" :: "r"(dst), "l"(src))
#define CP_COMMIT() asm volatile("cp.async.commit_group;" ::: "memory")
#define CP_WAIT(n)  asm volatile("cp.async.wait_group %0;" :: "n"(n) : "memory")

#define LDSM4(R0, R1, R2, R3, addr) \
    asm volatile("ldmatrix.sync.aligned.m8n8.x4.shared.b16 {%0,%1,%2,%3}, [%4];" \
        : "=r"(R0), "=r"(R1), "=r"(R2), "=r"(R3) : "r"(addr))
#define LDSM4T(R0, R1, R2, R3, addr) \
    asm volatile("ldmatrix.sync.aligned.m8n8.x4.trans.shared.b16 {%0,%1,%2,%3}, [%4];" \
        : "=r"(R0), "=r"(R1), "=r"(R2), "=r"(R3) : "r"(addr))

#define MMA16816(D, A, B0, B1) \
    asm volatile("mma.sync.aligned.m16n8k16.row.col.f32.bf16.bf16.f32 " \
        "{%0,%1,%2,%3},{%4,%5,%6,%7},{%8,%9},{%0,%1,%2,%3};" \
        : "+f"((D)[0]), "+f"((D)[1]), "+f"((D)[2]), "+f"((D)[3]) \
        : "r"((A)[0]), "r"((A)[1]), "r"((A)[2]), "r"((A)[3]), "r"(B0), "r"(B1))

__device__ __forceinline__ uint32_t pack_bf16(__nv_bfloat16 a, __nv_bfloat16 b) {
    union { __nv_bfloat16 h[2]; uint32_t u; } t;
    t.h[0] = a; t.h[1] = b;
    return t.u;
}

// ---------------------------------------------------------------------------
// convert_split: fp32 -> bf16 hi + lo
// ---------------------------------------------------------------------------
__global__ void convert_split(const float* __restrict__ in,
                              __nv_bfloat16* __restrict__ oh,
                              __nv_bfloat16* __restrict__ ol, int n4)
{
    int i = blockIdx.x * blockDim.x + threadIdx.x;
    if (i >= n4) return;
    float4 v = ((const float4*)in)[i];
    union { __nv_bfloat16 b[4]; uint2 u; } H, L;
    float f[4] = {v.x, v.y, v.z, v.w};
#pragma unroll
    for (int q = 0; q < 4; q++) {
        __nv_bfloat16 h = __float2bfloat16_rn(f[q]);
        H.b[q] = h;
        L.b[q] = __float2bfloat16_rn(f[q] - __bfloat162float(h));
    }
    ((uint2*)oh)[i] = H.u;
    ((uint2*)ol)[i] = L.u;
}

// ---------------------------------------------------------------------------
// transpose_split: fp32 [R,C] -> bf16 [C,R] hi + lo
// ---------------------------------------------------------------------------
__global__ void transpose_split(const float* __restrict__ in,
                                __nv_bfloat16* __restrict__ oh,
                                __nv_bfloat16* __restrict__ ol, int R, int C)
{
    __shared__ float t[32][33];
    int c0 = blockIdx.x * 32, r0 = blockIdx.y * 32;
    int tx = threadIdx.x, ty = threadIdx.y;
#pragma unroll
    for (int i = 0; i < 4; i++)
        t[ty + 8 * i][tx] = in[(size_t)(r0 + ty + 8 * i) * C + c0 + tx];
    __syncthreads();
#pragma unroll
    for (int i = 0; i < 4; i++) {
        float v = t[tx][ty + 8 * i];
        __nv_bfloat16 h = __float2bfloat16_rn(v);
        __nv_bfloat16 l = __float2bfloat16_rn(v - __bfloat162float(h));
        size_t o = (size_t)(c0 + ty + 8 * i) * R + r0 + tx;
        oh[o] = h;
        ol[o] = l;
    }
}

// ---------------------------------------------------------------------------
// bf16 split GEMM via mma.sync (unchanged from R3 — verified correct)
// ---------------------------------------------------------------------------
#define GSTG_B  40960u
#define GSMEM_B (4u * GSTG_B)

__global__ __launch_bounds__(256, 1)
void gemm_mma(const __nv_bfloat16* __restrict__ Ah, const __nv_bfloat16* __restrict__ Al,
              const __nv_bfloat16* __restrict__ Bh, const __nv_bfloat16* __restrict__ Bl,
              float* __restrict__ C, int M, int N, int K)
{
    extern __shared__ char smc[];
    const uint32_t sb = smem_u32(smc);
    const int tid  = threadIdx.x;
    const int lane = tid & 31;
    const int wid  = tid >> 5;
    const int warp_m = wid >> 2;
    const int warp_n = wid & 3;
    const int m0 = blockIdx.y * 128;
    const int n0 = blockIdx.x * 128;
    const int NT = K >> 5;

    uint32_t dstoff[8];
    const __nv_bfloat16* srcrow[8];
#pragma unroll
    for (int j = 0; j < 8; j++) {
        int c   = tid + 256 * j;
        int buf = c >> 9;
        int idx = c & 511;
        int row = idx >> 2;
        int kc  = idx & 3;
        dstoff[j] = (uint32_t)buf * 10240u + (uint32_t)row * 80u + (uint32_t)kc * 16u;
        const __nv_bfloat16* base =
            (buf == 0) ? Ah + (size_t)(m0 + row) * K :
            (buf == 1) ? Al + (size_t)(m0 + row) * K :
            (buf == 2) ? Bh + (size_t)(n0 + row) * K :
                         Bl + (size_t)(n0 + row) * K;
        srcrow[j] = base + kc * 8;
    }

#define ISSUE_STAGE(kt) do { \
        uint32_t stb = sb + (uint32_t)((kt) & 3) * GSTG_B; \
        const int kel = (kt) << 5; \
        _Pragma("unroll") \
        for (int j = 0; j < 8; j++) \
            CP_ASYNC16(stb + dstoff[j], srcrow[j] + kel); \
        CP_COMMIT(); \
    } while (0)

    float acc[4][4][4];
#pragma unroll
    for (int a = 0; a < 4; a++)
#pragma unroll
        for (int b = 0; b < 4; b++)
#pragma unroll
            for (int d = 0; d < 4; d++) acc[a][b][d] = 0.0f;

    ISSUE_STAGE(0);
    ISSUE_STAGE(1);

    const uint32_t a_lrow = (uint32_t)(warp_m * 64 + (lane & 15)) * 80u + (uint32_t)(lane >> 4) * 16u;
    const uint32_t b_lrow = (uint32_t)(warp_n * 32 + (lane & 15)) * 80u + (uint32_t)(lane >> 4) * 16u;

    for (int kt = 0; kt < NT; kt++) {
        if (kt + 2 < NT) { ISSUE_STAGE(kt + 2); CP_WAIT(2); }
        else if (kt + 1 < NT) { CP_WAIT(1); }
        else { CP_WAIT(0); }
        __syncthreads();

        const uint32_t stb = sb + (uint32_t)(kt & 3) * GSTG_B;
#pragma unroll
        for (int k16 = 0; k16 < 2; k16++) {
            const uint32_t koff = (uint32_t)k16 * 32u;
            uint32_t ah[4][4], al[4][4];
#pragma unroll
            for (int mt = 0; mt < 4; mt++) {
                uint32_t addr = stb + a_lrow + (uint32_t)mt * (16u * 80u) + koff;
                LDSM4(ah[mt][0], ah[mt][1], ah[mt][2], ah[mt][3], addr);
                LDSM4(al[mt][0], al[mt][1], al[mt][2], al[mt][3], addr + 10240u);
            }
            uint32_t bh[2][4], bl[2][4];
#pragma unroll
            for (int bt = 0; bt < 2; bt++) {
                uint32_t addr = stb + 20480u + b_lrow + (uint32_t)bt * (16u * 80u) + koff;
                LDSM4(bh[bt][0], bh[bt][1], bh[bt][2], bh[bt][3], addr);
                LDSM4(bl[bt][0], bl[bt][1], bl[bt][2], bl[bt][3], addr + 10240u);
            }
#pragma unroll
            for (int mt = 0; mt < 4; mt++) {
#pragma unroll
                for (int nt = 0; nt < 4; nt++) {
                    const int bt = nt >> 1, hf = nt & 1;
                    MMA16816(acc[mt][nt], ah[mt], bh[bt][hf], bh[bt][hf + 2]);
                    MMA16816(acc[mt][nt], ah[mt], bl[bt][hf], bl[bt][hf + 2]);
                    MMA16816(acc[mt][nt], al[mt], bh[bt][hf], bh[bt][hf + 2]);
                }
            }
        }
    }

#pragma unroll
    for (int mt = 0; mt < 4; mt++) {
        int row = m0 + warp_m * 64 + mt * 16 + (lane >> 2);
#pragma unroll
        for (int nt = 0; nt < 4; nt++) {
            int col = n0 + warp_n * 32 + nt * 8 + (lane & 3) * 2;
            *(float2*)(C + (size_t)row * N + col) =
                make_float2(acc[mt][nt][0], acc[mt][nt][1]);
            *(float2*)(C + (size_t)(row + 8) * N + col) =
                make_float2(acc[mt][nt][2], acc[mt][nt][3]);
        }
    }
#undef ISSUE_STAGE
}

// ---------------------------------------------------------------------------
// RoPE + bf16 hi/lo split: reads fp32 g_q/g_k, writes Q-split to g_ah/g_al,
// K-split to g_kh/g_kl. One thread per (row, head, pair).
// ---------------------------------------------------------------------------
__global__ void rope_split_kernel(const float* __restrict__ fc, const float* __restrict__ fs)
{
    const int QP = MROWS * NH * (HD / 2);
    const int KP = MROWS * NKV * (HD / 2);
    int idx = blockIdx.x * blockDim.x + threadIdx.x;
    if (idx >= QP + KP) return;

    const float* src;
    uint32_t *dh, *dl;
    int i, s;
    size_t off;
    if (idx < QP) {
        i = idx & 63;
        int rest = idx >> 6;
        int hh = rest & 31, row = rest >> 5;
        s = row & (SEQ - 1);
        off = ((size_t)row * QW + (size_t)hh * HD) / 2 + i;
        src = g_q; dh = (uint32_t*)g_ah; dl = (uint32_t*)g_al;
    } else {
        int li = idx - QP;
        i = li & 63;
        int rest = li >> 6;
        int hh = rest & 7, row = rest >> 3;
        s = row & (SEQ - 1);
        off = ((size_t)row * KW + (size_t)hh * HD) / 2 + i;
        src = g_k; dh = (uint32_t*)g_kh; dl = (uint32_t*)g_kl;
    }
    float2 v = ((const float2*)src)[off];
    float c = fc[s * 64 + i], sn = fs[s * 64 + i];
    float ox = v.x * c - v.y * sn;
    float oy = v.x * sn + v.y * c;
    __nv_bfloat16 hx = __float2bfloat16_rn(ox);
    __nv_bfloat16 hy = __float2bfloat16_rn(oy);
    __nv_bfloat16 lx = __float2bfloat16_rn(ox - __bfloat162float(hx));
    __nv_bfloat16 ly = __float2bfloat16_rn(oy - __bfloat162float(hy));
    dh[off] = pack_bf16(hx, hy);
    dl[off] = pack_bf16(lx, ly);
}

// ---------------------------------------------------------------------------
// flash_mma: causal flash attention on tensor cores (bf16 hi/lo split).
// Block = 64 q-rows of one (b,h). 256 threads = 8 warps (4m x 2n).
// QK^T: 3-term mma; softmax fp32; P packed to bf16 hi/lo; PV: 3-term mma.
// smem byte map (pitch 272B for 128-col bf16 tiles, 144B for P):
//  Qh 0 | Ql 17408 | Kh 34816 | Kl 52224 | Vh 69632 | Vl 87040
//  Sp(f32 64x68) 104448 | Ph 121856 | Pl 131072
//  red1 140288 | red2 141312 | m 142336 | l 142592 | corr 142848  (end 143104)
// ---------------------------------------------------------------------------
#define FA2_SMEM 143104

__global__ __launch_bounds__(256, 1)
void flash_mma()
{
    extern __shared__ char sm2[];
    const uint32_t sb = smem_u32(sm2);
    const uint32_t oQh = 0, oQl = 17408, oKh = 34816, oKl = 52224,
                   oVh = 69632, oVl = 87040, oSp = 104448,
                   oPh = 121856, oPl = 131072,
                   oR1 = 140288, oR2 = 141312, oM = 142336, oL = 142592, oC = 142848;

    float* Sp     = (float*)(sm2 + oSp);
    float* red1   = (float*)(sm2 + oR1);
    float* red2   = (float*)(sm2 + oR2);
    float* m_s    = (float*)(sm2 + oM);
    float* l_s    = (float*)(sm2 + oL);
    float* corr_s = (float*)(sm2 + oC);

    const int qb = blockIdx.x, h = blockIdx.y, b = blockIdx.z;
    const int kvh = h >> 2;
    const int tid  = threadIdx.x;
    const int lane = tid & 31;
    const int wid  = tid >> 5;
    const int warp_m = wid >> 1;   // 0..3
    const int warp_n = wid & 1;    // 0..1
    const float SCALE = 0.08838834764831845f;

    // ---- load Q tile (bf16 hi/lo), rows 64 x 128 cols, pitch 272B ----
    {
        const __nv_bfloat16* qh = g_ah + (size_t)(b * SEQ + qb * 64) * QW + h * HD;
        const __nv_bfloat16* ql = g_al + (size_t)(b * SEQ + qb * 64) * QW + h * HD;
#pragma unroll
        for (int j = 0; j < 4; j++) {
            int g = tid + 256 * j;
            int row = g >> 4, c16 = g & 15;
            *(uint4*)(sm2 + oQh + row * 272 + c16 * 16) = *(const uint4*)(qh + (size_t)row * QW + c16 * 8);
            *(uint4*)(sm2 + oQl + row * 272 + c16 * 16) = *(const uint4*)(ql + (size_t)row * QW + c16 * 8);
        }
    }
    if (tid < 64) { m_s[tid] = -CUDART_INF_F; l_s[tid] = 0.0f; }

    const int r_lo = warp_m * 16 + (lane >> 2);    // acc row (and +8)
    const int rowid = tid >> 2, part = tid & 3;    // softmax mapping

    float acc_o[8][4];
#pragma unroll
    for (int n = 0; n < 8; n++)
#pragma unroll
        for (int d = 0; d < 4; d++) acc_o[n][d] = 0.0f;

    const uint32_t qa_base = sb + oQh + (uint32_t)(warp_m * 16 + (lane & 15)) * 272u + (uint32_t)(lane >> 4) * 16u;
    const uint32_t kb_base = sb + oKh + (uint32_t)(warp_n * 32 + (lane & 15)) * 272u + (uint32_t)(lane >> 4) * 16u;
    const uint32_t pa_base = sb + oPh + (uint32_t)(warp_m * 16 + (lane & 15)) * 144u + (uint32_t)(lane >> 4) * 16u;
    const uint32_t vb_base = sb + oVh + (uint32_t)(lane & 15) * 272u + (uint32_t)(warp_n * 64) * 2u + (uint32_t)(lane >> 4) * 16u;

    for (int kb = 0; kb <= qb; kb++) {
        __syncthreads();   // previous iter done with K/V/P smem

        // ---- load K/V hi/lo tiles ----
        {
            const size_t rb = (size_t)(b * SEQ + kb * 64) * KW + kvh * HD;
            const __nv_bfloat16* s0 = g_kh + rb;
            const __nv_bfloat16* s1 = g_kl + rb;
            const __nv_bfloat16* s2 = g_vh + rb;
            const __nv_bfloat16* s3 = g_vl + rb;
#pragma unroll
            for (int j = 0; j < 4; j++) {
                int g = tid + 256 * j;
                int row = g >> 4, c16 = g & 15;
                uint32_t d_off = row * 272 + c16 * 16;
                size_t s_off = (size_t)row * KW + c16 * 8;
                *(uint4*)(sm2 + oKh + d_off) = *(const uint4*)(s0 + s_off);
                *(uint4*)(sm2 + oKl + d_off) = *(const uint4*)(s1 + s_off);
                *(uint4*)(sm2 + oVh + d_off) = *(const uint4*)(s2 + s_off);
                *(uint4*)(sm2 + oVl + d_off) = *(const uint4*)(s3 + s_off);
            }
        }
        __syncthreads();

        // ---- S = Q K^T (3-term split), warp tile 16x32 ----
        float acc_s[4][4];
#pragma unroll
        for (int n = 0; n < 4; n++)
#pragma unroll
            for (int d = 0; d < 4; d++) acc_s[n][d] = 0.0f;

#pragma unroll
        for (int k16 = 0; k16 < 8; k16++) {
            const uint32_t ko = (uint32_t)k16 * 32u;
            uint32_t qh_f[4], ql_f[4];
            LDSM4(qh_f[0], qh_f[1], qh_f[2], qh_f[3], qa_base + ko);
            LDSM4(ql_f[0], ql_f[1], ql_f[2], ql_f[3], qa_base + 17408u + ko);
            uint32_t kh_f[2][4], kl_f[2][4];
#pragma unroll
            for (int ng = 0; ng < 2; ng++) {
                uint32_t addr = kb_base + (uint32_t)ng * (16u * 272u) + ko;
                LDSM4(kh_f[ng][0], kh_f[ng][1], kh_f[ng][2], kh_f[ng][3], addr);
                LDSM4(kl_f[ng][0], kl_f[ng][1], kl_f[ng][2], kl_f[ng][3], addr + 17408u);
            }
#pragma unroll
            for (int nt = 0; nt < 4; nt++) {
                const int ng = nt >> 1, hf = nt & 1;
                MMA16816(acc_s[nt], qh_f, kh_f[ng][hf], kh_f[ng][hf + 2]);
                MMA16816(acc_s[nt], qh_f, kl_f[ng][hf], kl_f[ng][hf + 2]);
                MMA16816(acc_s[nt], ql_f, kh_f[ng][hf], kh_f[ng][hf + 2]);
            }
        }

        // ---- scale + causal mask + write to Sp ----
        {
            const int gq_lo = qb * 64 + r_lo;
#pragma unroll
            for (int nt = 0; nt < 4; nt++) {
                int col = warp_n * 32 + nt * 8 + (lane & 3) * 2;
                int gk = kb * 64 + col;
                float s0 = acc_s[nt][0] * SCALE, s1 = acc_s[nt][1] * SCALE;
                float s2 = acc_s[nt][2] * SCALE, s3 = acc_s[nt][3] * SCALE;
                if (gk     > gq_lo)     s0 = -1e9f;
                if (gk + 1 > gq_lo)     s1 = -1e9f;
                if (gk     > gq_lo + 8) s2 = -1e9f;
                if (gk + 1 > gq_lo + 8) s3 = -1e9f;
                *(float2*)&Sp[r_lo * 68 + col]       = make_float2(s0, s1);
                *(float2*)&Sp[(r_lo + 8) * 68 + col] = make_float2(s2, s3);
            }
        }
        __syncthreads();

        // ---- online softmax: 4 threads per row, 16 cols each ----
        {
            float* sprow = Sp + rowid * 68 + part * 16;
            float pm = -CUDART_INF_F;
#pragma unroll
            for (int i = 0; i < 16; i++) pm = fmaxf(pm, sprow[i]);
            red1[rowid * 4 + part] = pm;
            __syncthreads();

            float m_old = m_s[rowid];
            float m_new = fmaxf(fmaxf(red1[rowid * 4 + 0], red1[rowid * 4 + 1]),
                                fmaxf(red1[rowid * 4 + 2], red1[rowid * 4 + 3]));
            m_new = fmaxf(m_new, m_old);
            float psum = 0.0f;
            uint32_t* ph_row = (uint32_t*)(sm2 + oPh + rowid * 144) + part * 8;
            uint32_t* pl_row = (uint32_t*)(sm2 + oPl + rowid * 144) + part * 8;
#pragma unroll
            for (int i = 0; i < 16; i += 2) {
                float p0 = __expf(sprow[i]     - m_new);
                float p1 = __expf(sprow[i + 1] - m_new);
                psum += p0 + p1;
                __nv_bfloat16 h0 = __float2bfloat16_rn(p0);
                __nv_bfloat16 h1 = __float2bfloat16_rn(p1);
                __nv_bfloat16 l0 = __float2bfloat16_rn(p0 - __bfloat162float(h0));
                __nv_bfloat16 l1 = __float2bfloat16_rn(p1 - __bfloat162float(h1));
                ph_row[i >> 1] = pack_bf16(h0, h1);
                pl_row[i >> 1] = pack_bf16(l0, l1);
            }
            red2[rowid * 4 + part] = psum;
            __syncthreads();

            if (part == 0) {
                float corr = __expf(m_old - m_new);
                corr_s[rowid] = corr;
                l_s[rowid] = l_s[rowid] * corr +
                             red2[rowid * 4 + 0] + red2[rowid * 4 + 1] +
                             red2[rowid * 4 + 2] + red2[rowid * 4 + 3];
                m_s[rowid] = m_new;
            }
            __syncthreads();
        }

        // ---- rescale O, then O += P V (3-term split), warp tile 16x64 ----
        {
            float c_lo = corr_s[r_lo], c_hi = corr_s[r_lo + 8];
#pragma unroll
            for (int nt = 0; nt < 8; nt++) {
                acc_o[nt][0] *= c_lo; acc_o[nt][1] *= c_lo;
                acc_o[nt][2] *= c_hi; acc_o[nt][3] *= c_hi;
            }
#pragma unroll
            for (int kk = 0; kk < 4; kk++) {
                uint32_t ph_f[4], pl_f[4];
                LDSM4(ph_f[0], ph_f[1], ph_f[2], ph_f[3], pa_base + kk * 32u);
                LDSM4(pl_f[0], pl_f[1], pl_f[2], pl_f[3], pa_base + 9216u + kk * 32u);
#pragma unroll
                for (int g = 0; g < 4; g++) {
                    uint32_t addr = vb_base + (uint32_t)kk * (16u * 272u) + (uint32_t)g * 32u;
                    uint32_t vh_f[4], vl_f[4];
                    LDSM4T(vh_f[0], vh_f[1], vh_f[2], vh_f[3], addr);
                    LDSM4T(vl_f[0], vl_f[1], vl_f[2], vl_f[3], addr + 17408u);
                    const int nt0 = g * 2;
                    MMA16816(acc_o[nt0], ph_f, vh_f[0], vh_f[1]);
                    MMA16816(acc_o[nt0], ph_f, vl_f[0], vl_f[1]);
                    MMA16816(acc_o[nt0], pl_f, vh_f[0], vh_f[1]);
                    MMA16816(acc_o[nt0 + 1], ph_f, vh_f[2], vh_f[3]);
                    MMA16816(acc_o[nt0 + 1], ph_f, vl_f[2], vl_f[3]);
                    MMA16816(acc_o[nt0 + 1], pl_f, vh_f[2], vh_f[3]);
                }
            }
        }
    }

    // ---- epilogue: divide by l, store fp32 to g_attn ----
    {
        float inv_lo = 1.0f / l_s[r_lo];
        float inv_hi = 1.0f / l_s[r_lo + 8];
        float* ob = g_attn + (size_t)(b * SEQ + qb * 64) * QW + h * HD;
#pragma unroll
        for (int nt = 0; nt < 8; nt++) {
            int col = warp_n * 64 + nt * 8 + (lane & 3) * 2;
            *(float2*)(ob + (size_t)r_lo * QW + col) =
                make_float2(acc_o[nt][0] * inv_lo, acc_o[nt][1] * inv_lo);
            *(float2*)(ob + (size_t)(r_lo + 8) * QW + col) =
                make_float2(acc_o[nt][2] * inv_hi, acc_o[nt][3] * inv_hi);
        }
    }
}

// ---------------------------------------------------------------------------
// Launch
// ---------------------------------------------------------------------------
extern "C" void kernel_launch(void* const* d_in, const int* in_sizes, int n_in,
                              void* d_out, int out_size)
{
    const float* x  = (const float*)d_in[0];
    const float* wq = (const float*)d_in[1];
    const float* wk = (const float*)d_in[2];
    const float* wv = (const float*)d_in[3];
    const float* wo = (const float*)d_in[4];
    const float* fc = (const float*)d_in[7];
    const float* fs = (const float*)d_in[8];
    float* out = (float*)d_out;

    float *pq, *pk, *pv, *pa;
    cudaGetSymbolAddress((void**)&pq, g_q);
    cudaGetSymbolAddress((void**)&pk, g_k);
    cudaGetSymbolAddress((void**)&pv, g_v);
    cudaGetSymbolAddress((void**)&pa, g_attn);
    __nv_bfloat16 *pah, *pal, *pvh, *pvl;
    __nv_bfloat16 *pwqh, *pwql, *pwkh, *pwkl, *pwvh, *pwvl, *pwoh, *pwol;
    cudaGetSymbolAddress((void**)&pah, g_ah);
    cudaGetSymbolAddress((void**)&pal, g_al);
    cudaGetSymbolAddress((void**)&pvh, g_vh);
    cudaGetSymbolAddress((void**)&pvl, g_vl);
    cudaGetSymbolAddress((void**)&pwqh, g_wqh);
    cudaGetSymbolAddress((void**)&pwql, g_wql);
    cudaGetSymbolAddress((void**)&pwkh, g_wkh);
    cudaGetSymbolAddress((void**)&pwkl, g_wkl);
    cudaGetSymbolAddress((void**)&pwvh, g_wvh);
    cudaGetSymbolAddress((void**)&pwvl, g_wvl);
    cudaGetSymbolAddress((void**)&pwoh, g_woh);
    cudaGetSymbolAddress((void**)&pwol, g_wol);

    cudaFuncSetAttribute(gemm_mma, cudaFuncAttributeMaxDynamicSharedMemorySize, (int)GSMEM_B);
    cudaFuncSetAttribute(flash_mma, cudaFuncAttributeMaxDynamicSharedMemorySize, FA2_SMEM);

    // split x, transpose+split weights
    convert_split<<<(MROWS * DIM / 4 + 255) / 256, 256>>>(x, pah, pal, MROWS * DIM / 4);
    transpose_split<<<dim3(QW / 32, DIM / 32), dim3(32, 8)>>>(wq, pwqh, pwql, DIM, QW);
    transpose_split<<<dim3(KW / 32, DIM / 32), dim3(32, 8)>>>(wk, pwkh, pwkl, DIM, KW);
    transpose_split<<<dim3(KW / 32, DIM / 32), dim3(32, 8)>>>(wv, pwvh, pwvl, DIM, KW);
    transpose_split<<<dim3(DIM / 32, QW / 32), dim3(32, 8)>>>(wo, pwoh, pwol, QW, DIM);

    // QKV projections on tensor cores
    gemm_mma<<<dim3(QW / 128, MROWS / 128), 256, GSMEM_B>>>(pah, pal, pwqh, pwql, pq, MROWS, QW, DIM);
    gemm_mma<<<dim3(KW / 128, MROWS / 128), 256, GSMEM_B>>>(pah, pal, pwkh, pwkl, pk, MROWS, KW, DIM);
    gemm_mma<<<dim3(KW / 128, MROWS / 128), 256, GSMEM_B>>>(pah, pal, pwvh, pwvl, pv, MROWS, KW, DIM);

    // RoPE + split Q (into g_ah/g_al) and K (into g_kh/g_kl); split V
    const int total_pairs = MROWS * NH * (HD / 2) + MROWS * NKV * (HD / 2);
    rope_split_kernel<<<(total_pairs + 255) / 256, 256>>>(fc, fs);
    convert_split<<<(MROWS * KW / 4 + 255) / 256, 256>>>(pv, pvh, pvl, MROWS * KW / 4);

    // flash attention on tensor cores
    flash_mma<<<dim3(SEQ / 64, NH, BSZ), 256, FA2_SMEM>>>();

    // split attention output, output projection
    convert_split<<<(MROWS * QW / 4 + 255) / 256, 256>>>(pa, pah, pal, MROWS * QW / 4);
    gemm_mma<<<dim3(DIM / 128, MROWS / 128), 256, GSMEM_B>>>(pah, pal, pwoh, pwol, out, MROWS, DIM, DIM);
}

// round 5
// speedup vs baseline: 2.4171x; 1.0715x over previous
#include <cuda_runtime.h>
#include <cuda_bf16.h>
#include <math_constants.h>
#include <cstdint>

#define BSZ   2
#define SEQ   2048
#define DIM   4096
#define NH    32
#define NKV   8
#define HD    128
#define MROWS (BSZ*SEQ)   /* 4096 */
#define QW    (NH*HD)     /* 4096 */
#define KW    (NKV*HD)    /* 1024 */

// ---------------------------------------------------------------------------
// Static device scratch
// ---------------------------------------------------------------------------
__device__ float g_q[(size_t)MROWS * QW];
__device__ float g_k[(size_t)MROWS * KW];

__device__ __nv_bfloat16 g_ah[(size_t)MROWS * DIM];   // x-split -> Q-split -> O-split
__device__ __nv_bfloat16 g_al[(size_t)MROWS * DIM];
__device__ __nv_bfloat16 g_kh[(size_t)MROWS * KW], g_kl[(size_t)MROWS * KW];
__device__ __nv_bfloat16 g_vh[(size_t)MROWS * KW], g_vl[(size_t)MROWS * KW];
__device__ __nv_bfloat16 g_wqh[(size_t)QW * DIM],  g_wql[(size_t)QW * DIM];
__device__ __nv_bfloat16 g_wkh[(size_t)KW * DIM],  g_wkl[(size_t)KW * DIM];
__device__ __nv_bfloat16 g_wvh[(size_t)KW * DIM],  g_wvl[(size_t)KW * DIM];
__device__ __nv_bfloat16 g_woh[(size_t)DIM * QW],  g_wol[(size_t)DIM * QW];

// ---------------------------------------------------------------------------
// PTX helpers
// ---------------------------------------------------------------------------
__device__ __forceinline__ uint32_t smem_u32(const void* p) {
    uint32_t a;
    asm("{ .reg .u64 t; cvta.to.shared.u64 t, %1; cvt.u32.u64 %0, t; }" : "=r"(a) : "l"(p));
    return a;
}
#define CP_ASYNC16(dst, src) \
    asm volatile("cp.async.cg.shared.global [%0], [%1], 16;" :: "r"(dst), "l"(src))
#define CP_COMMIT() asm volatile("cp.async.commit_group;" ::: "memory")
#define CP_WAIT(n)  asm volatile("cp.async.wait_group %0;" :: "n"(n) : "memory")

#define LDSM4(R0, R1, R2, R3, addr) \
    asm volatile("ldmatrix.sync.aligned.m8n8.x4.shared.b16 {%0,%1,%2,%3}, [%4];" \
        : "=r"(R0), "=r"(R1), "=r"(R2), "=r"(R3) : "r"(addr))
#define LDSM4T(R0, R1, R2, R3, addr) \
    asm volatile("ldmatrix.sync.aligned.m8n8.x4.trans.shared.b16 {%0,%1,%2,%3}, [%4];" \
        : "=r"(R0), "=r"(R1), "=r"(R2), "=r"(R3) : "r"(addr))

#define MMA16816(D, A, B0, B1) \
    asm volatile("mma.sync.aligned.m16n8k16.row.col.f32.bf16.bf16.f32 " \
        "{%0,%1,%2,%3},{%4,%5,%6,%7},{%8,%9},{%0,%1,%2,%3};" \
        : "+f"((D)[0]), "+f"((D)[1]), "+f"((D)[2]), "+f"((D)[3]) \
        : "r"((A)[0]), "r"((A)[1]), "r"((A)[2]), "r"((A)[3]), "r"(B0), "r"(B1))

__device__ __forceinline__ uint32_t pack_bf16(__nv_bfloat16 a, __nv_bfloat16 b) {
    union { __nv_bfloat16 h[2]; uint32_t u; } t;
    t.h[0] = a; t.h[1] = b;
    return t.u;
}
__device__ __forceinline__ uint32_t split_hi(float a, float b) {
    return pack_bf16(__float2bfloat16_rn(a), __float2bfloat16_rn(b));
}
__device__ __forceinline__ uint32_t split_lo(float a, float b) {
    __nv_bfloat16 ha = __float2bfloat16_rn(a), hb = __float2bfloat16_rn(b);
    return pack_bf16(__float2bfloat16_rn(a - __bfloat162float(ha)),
                     __float2bfloat16_rn(b - __bfloat162float(hb)));
}

// ---------------------------------------------------------------------------
// convert_split: fp32 -> bf16 hi + lo
// ---------------------------------------------------------------------------
__global__ void convert_split(const float* __restrict__ in,
                              __nv_bfloat16* __restrict__ oh,
                              __nv_bfloat16* __restrict__ ol, int n4)
{
    int i = blockIdx.x * blockDim.x + threadIdx.x;
    if (i >= n4) return;
    float4 v = ((const float4*)in)[i];
    uint2 H, L;
    H.x = split_hi(v.x, v.y); H.y = split_hi(v.z, v.w);
    L.x = split_lo(v.x, v.y); L.y = split_lo(v.z, v.w);
    ((uint2*)oh)[i] = H;
    ((uint2*)ol)[i] = L;
}

// ---------------------------------------------------------------------------
// transpose_split: fp32 [R,C] -> bf16 [C,R] hi + lo
// ---------------------------------------------------------------------------
__global__ void transpose_split(const float* __restrict__ in,
                                __nv_bfloat16* __restrict__ oh,
                                __nv_bfloat16* __restrict__ ol, int R, int C)
{
    __shared__ float t[32][33];
    int c0 = blockIdx.x * 32, r0 = blockIdx.y * 32;
    int tx = threadIdx.x, ty = threadIdx.y;
#pragma unroll
    for (int i = 0; i < 4; i++)
        t[ty + 8 * i][tx] = in[(size_t)(r0 + ty + 8 * i) * C + c0 + tx];
    __syncthreads();
#pragma unroll
    for (int i = 0; i < 4; i++) {
        float v = t[tx][ty + 8 * i];
        __nv_bfloat16 h = __float2bfloat16_rn(v);
        __nv_bfloat16 l = __float2bfloat16_rn(v - __bfloat162float(h));
        size_t o = (size_t)(c0 + ty + 8 * i) * R + r0 + tx;
        oh[o] = h;
        ol[o] = l;
    }
}

// ---------------------------------------------------------------------------
// Shared GEMM machinery: 128x128 tile, BK=32, 8 warps (2x4), 3-term split.
// ---------------------------------------------------------------------------
#define GSTG_B  40960u
#define GSMEM_B (4u * GSTG_B)

// gemm_mma: generic C fp32 output (used for the wo projection)
__global__ __launch_bounds__(256, 1)
void gemm_mma(const __nv_bfloat16* __restrict__ Ah, const __nv_bfloat16* __restrict__ Al,
              const __nv_bfloat16* __restrict__ Bh, const __nv_bfloat16* __restrict__ Bl,
              float* __restrict__ C, int M, int N, int K)
{
    extern __shared__ char smc[];
    const uint32_t sb = smem_u32(smc);
    const int tid  = threadIdx.x;
    const int lane = tid & 31;
    const int wid  = tid >> 5;
    const int warp_m = wid >> 2;
    const int warp_n = wid & 3;
    const int m0 = blockIdx.y * 128;
    const int n0 = blockIdx.x * 128;
    const int NT = K >> 5;

    uint32_t dstoff[8];
    const __nv_bfloat16* srcrow[8];
#pragma unroll
    for (int j = 0; j < 8; j++) {
        int c   = tid + 256 * j;
        int buf = c >> 9;
        int idx = c & 511;
        int row = idx >> 2;
        int kc  = idx & 3;
        dstoff[j] = (uint32_t)buf * 10240u + (uint32_t)row * 80u + (uint32_t)kc * 16u;
        const __nv_bfloat16* base =
            (buf == 0) ? Ah + (size_t)(m0 + row) * K :
            (buf == 1) ? Al + (size_t)(m0 + row) * K :
            (buf == 2) ? Bh + (size_t)(n0 + row) * K :
                         Bl + (size_t)(n0 + row) * K;
        srcrow[j] = base + kc * 8;
    }

#define ISSUE_STAGE(kt) do { \
        uint32_t stb = sb + (uint32_t)((kt) & 3) * GSTG_B; \
        const int kel = (kt) << 5; \
        _Pragma("unroll") \
        for (int j = 0; j < 8; j++) \
            CP_ASYNC16(stb + dstoff[j], srcrow[j] + kel); \
        CP_COMMIT(); \
    } while (0)

    float acc[4][4][4];
#pragma unroll
    for (int a = 0; a < 4; a++)
#pragma unroll
        for (int b = 0; b < 4; b++)
#pragma unroll
            for (int d = 0; d < 4; d++) acc[a][b][d] = 0.0f;

    ISSUE_STAGE(0);
    ISSUE_STAGE(1);

    const uint32_t a_lrow = (uint32_t)(warp_m * 64 + (lane & 15)) * 80u + (uint32_t)(lane >> 4) * 16u;
    const uint32_t b_lrow = (uint32_t)(warp_n * 32 + (lane & 15)) * 80u + (uint32_t)(lane >> 4) * 16u;

    for (int kt = 0; kt < NT; kt++) {
        if (kt + 2 < NT) { ISSUE_STAGE(kt + 2); CP_WAIT(2); }
        else if (kt + 1 < NT) { CP_WAIT(1); }
        else { CP_WAIT(0); }
        __syncthreads();

        const uint32_t stb = sb + (uint32_t)(kt & 3) * GSTG_B;
#pragma unroll
        for (int k16 = 0; k16 < 2; k16++) {
            const uint32_t koff = (uint32_t)k16 * 32u;
            uint32_t ah[4][4], al[4][4];
#pragma unroll
            for (int mt = 0; mt < 4; mt++) {
                uint32_t addr = stb + a_lrow + (uint32_t)mt * (16u * 80u) + koff;
                LDSM4(ah[mt][0], ah[mt][1], ah[mt][2], ah[mt][3], addr);
                LDSM4(al[mt][0], al[mt][1], al[mt][2], al[mt][3], addr + 10240u);
            }
            uint32_t bh[2][4], bl[2][4];
#pragma unroll
            for (int bt = 0; bt < 2; bt++) {
                uint32_t addr = stb + 20480u + b_lrow + (uint32_t)bt * (16u * 80u) + koff;
                LDSM4(bh[bt][0], bh[bt][1], bh[bt][2], bh[bt][3], addr);
                LDSM4(bl[bt][0], bl[bt][1], bl[bt][2], bl[bt][3], addr + 10240u);
            }
#pragma unroll
            for (int mt = 0; mt < 4; mt++) {
#pragma unroll
                for (int nt = 0; nt < 4; nt++) {
                    const int bt = nt >> 1, hf = nt & 1;
                    MMA16816(acc[mt][nt], ah[mt], bh[bt][hf], bh[bt][hf + 2]);
                    MMA16816(acc[mt][nt], ah[mt], bl[bt][hf], bl[bt][hf + 2]);
                    MMA16816(acc[mt][nt], al[mt], bh[bt][hf], bh[bt][hf + 2]);
                }
            }
        }
    }

#pragma unroll
    for (int mt = 0; mt < 4; mt++) {
        int row = m0 + warp_m * 64 + mt * 16 + (lane >> 2);
#pragma unroll
        for (int nt = 0; nt < 4; nt++) {
            int col = n0 + warp_n * 32 + nt * 8 + (lane & 3) * 2;
            *(float2*)(C + (size_t)row * N + col) =
                make_float2(acc[mt][nt][0], acc[mt][nt][1]);
            *(float2*)(C + (size_t)(row + 8) * N + col) =
                make_float2(acc[mt][nt][2], acc[mt][nt][3]);
        }
    }
#undef ISSUE_STAGE
}

// gemm_qkv: fused Q/K/V projection. Virtual N = 6144 (cols 0..4095 -> Q fp32,
// 4096..5119 -> K fp32, 5120..6143 -> V written directly as bf16 hi/lo split).
__global__ __launch_bounds__(256, 1)
void gemm_qkv()
{
    extern __shared__ char smc[];
    const uint32_t sb = smem_u32(smc);
    const int tid  = threadIdx.x;
    const int lane = tid & 31;
    const int wid  = tid >> 5;
    const int warp_m = wid >> 2;
    const int warp_n = wid & 3;
    const int m0 = blockIdx.y * 128;
    const int n0 = blockIdx.x * 128;
    const int K = DIM;
    const int NT = K >> 5;

    const __nv_bfloat16 *Bh, *Bl;
    if (n0 < 4096)      { Bh = g_wqh + (size_t)n0 * K;          Bl = g_wql + (size_t)n0 * K; }
    else if (n0 < 5120) { Bh = g_wkh + (size_t)(n0 - 4096) * K; Bl = g_wkl + (size_t)(n0 - 4096) * K; }
    else                { Bh = g_wvh + (size_t)(n0 - 5120) * K; Bl = g_wvl + (size_t)(n0 - 5120) * K; }

    uint32_t dstoff[8];
    const __nv_bfloat16* srcrow[8];
#pragma unroll
    for (int j = 0; j < 8; j++) {
        int c   = tid + 256 * j;
        int buf = c >> 9;
        int idx = c & 511;
        int row = idx >> 2;
        int kc  = idx & 3;
        dstoff[j] = (uint32_t)buf * 10240u + (uint32_t)row * 80u + (uint32_t)kc * 16u;
        const __nv_bfloat16* base =
            (buf == 0) ? g_ah + (size_t)(m0 + row) * K :
            (buf == 1) ? g_al + (size_t)(m0 + row) * K :
            (buf == 2) ? Bh + (size_t)row * K :
                         Bl + (size_t)row * K;
        srcrow[j] = base + kc * 8;
    }

#define ISSUE_STAGE(kt) do { \
        uint32_t stb = sb + (uint32_t)((kt) & 3) * GSTG_B; \
        const int kel = (kt) << 5; \
        _Pragma("unroll") \
        for (int j = 0; j < 8; j++) \
            CP_ASYNC16(stb + dstoff[j], srcrow[j] + kel); \
        CP_COMMIT(); \
    } while (0)

    float acc[4][4][4];
#pragma unroll
    for (int a = 0; a < 4; a++)
#pragma unroll
        for (int b = 0; b < 4; b++)
#pragma unroll
            for (int d = 0; d < 4; d++) acc[a][b][d] = 0.0f;

    ISSUE_STAGE(0);
    ISSUE_STAGE(1);

    const uint32_t a_lrow = (uint32_t)(warp_m * 64 + (lane & 15)) * 80u + (uint32_t)(lane >> 4) * 16u;
    const uint32_t b_lrow = (uint32_t)(warp_n * 32 + (lane & 15)) * 80u + (uint32_t)(lane >> 4) * 16u;

    for (int kt = 0; kt < NT; kt++) {
        if (kt + 2 < NT) { ISSUE_STAGE(kt + 2); CP_WAIT(2); }
        else if (kt + 1 < NT) { CP_WAIT(1); }
        else { CP_WAIT(0); }
        __syncthreads();

        const uint32_t stb = sb + (uint32_t)(kt & 3) * GSTG_B;
#pragma unroll
        for (int k16 = 0; k16 < 2; k16++) {
            const uint32_t koff = (uint32_t)k16 * 32u;
            uint32_t ah[4][4], al[4][4];
#pragma unroll
            for (int mt = 0; mt < 4; mt++) {
                uint32_t addr = stb + a_lrow + (uint32_t)mt * (16u * 80u) + koff;
                LDSM4(ah[mt][0], ah[mt][1], ah[mt][2], ah[mt][3], addr);
                LDSM4(al[mt][0], al[mt][1], al[mt][2], al[mt][3], addr + 10240u);
            }
            uint32_t bh[2][4], bl[2][4];
#pragma unroll
            for (int bt = 0; bt < 2; bt++) {
                uint32_t addr = stb + 20480u + b_lrow + (uint32_t)bt * (16u * 80u) + koff;
                LDSM4(bh[bt][0], bh[bt][1], bh[bt][2], bh[bt][3], addr);
                LDSM4(bl[bt][0], bl[bt][1], bl[bt][2], bl[bt][3], addr + 10240u);
            }
#pragma unroll
            for (int mt = 0; mt < 4; mt++) {
#pragma unroll
                for (int nt = 0; nt < 4; nt++) {
                    const int bt = nt >> 1, hf = nt & 1;
                    MMA16816(acc[mt][nt], ah[mt], bh[bt][hf], bh[bt][hf + 2]);
                    MMA16816(acc[mt][nt], ah[mt], bl[bt][hf], bl[bt][hf + 2]);
                    MMA16816(acc[mt][nt], al[mt], bh[bt][hf], bh[bt][hf + 2]);
                }
            }
        }
    }

#pragma unroll
    for (int mt = 0; mt < 4; mt++) {
        int row = m0 + warp_m * 64 + mt * 16 + (lane >> 2);
#pragma unroll
        for (int nt = 0; nt < 4; nt++) {
            int coll = warp_n * 32 + nt * 8 + (lane & 3) * 2;
            if (n0 < 4096) {
                int col = n0 + coll;
                *(float2*)(g_q + (size_t)row * QW + col) =
                    make_float2(acc[mt][nt][0], acc[mt][nt][1]);
                *(float2*)(g_q + (size_t)(row + 8) * QW + col) =
                    make_float2(acc[mt][nt][2], acc[mt][nt][3]);
            } else if (n0 < 5120) {
                int col = n0 - 4096 + coll;
                *(float2*)(g_k + (size_t)row * KW + col) =
                    make_float2(acc[mt][nt][0], acc[mt][nt][1]);
                *(float2*)(g_k + (size_t)(row + 8) * KW + col) =
                    make_float2(acc[mt][nt][2], acc[mt][nt][3]);
            } else {
                int col = n0 - 5120 + coll;
                uint32_t* vh32 = (uint32_t*)g_vh;
                uint32_t* vl32 = (uint32_t*)g_vl;
                size_t o0 = ((size_t)row * KW + col) >> 1;
                size_t o1 = ((size_t)(row + 8) * KW + col) >> 1;
                vh32[o0] = split_hi(acc[mt][nt][0], acc[mt][nt][1]);
                vl32[o0] = split_lo(acc[mt][nt][0], acc[mt][nt][1]);
                vh32[o1] = split_hi(acc[mt][nt][2], acc[mt][nt][3]);
                vl32[o1] = split_lo(acc[mt][nt][2], acc[mt][nt][3]);
            }
        }
    }
#undef ISSUE_STAGE
}

// ---------------------------------------------------------------------------
// RoPE + split: fp32 g_q/g_k -> bf16 hi/lo (Q into g_ah/g_al, K into g_kh/g_kl)
// ---------------------------------------------------------------------------
__global__ void rope_split_kernel(const float* __restrict__ fc, const float* __restrict__ fs)
{
    const int QP = MROWS * NH * (HD / 2);
    const int KP = MROWS * NKV * (HD / 2);
    int idx = blockIdx.x * blockDim.x + threadIdx.x;
    if (idx >= QP + KP) return;

    const float* src;
    uint32_t *dh, *dl;
    int i, s;
    size_t off;
    if (idx < QP) {
        i = idx & 63;
        int rest = idx >> 6;
        int hh = rest & 31, row = rest >> 5;
        s = row & (SEQ - 1);
        off = ((size_t)row * QW + (size_t)hh * HD) / 2 + i;
        src = g_q; dh = (uint32_t*)g_ah; dl = (uint32_t*)g_al;
    } else {
        int li = idx - QP;
        i = li & 63;
        int rest = li >> 6;
        int hh = rest & 7, row = rest >> 3;
        s = row & (SEQ - 1);
        off = ((size_t)row * KW + (size_t)hh * HD) / 2 + i;
        src = g_k; dh = (uint32_t*)g_kh; dl = (uint32_t*)g_kl;
    }
    float2 v = ((const float2*)src)[off];
    float c = fc[s * 64 + i], sn = fs[s * 64 + i];
    float ox = v.x * c - v.y * sn;
    float oy = v.x * sn + v.y * c;
    dh[off] = split_hi(ox, oy);
    dl[off] = split_lo(ox, oy);
}

// ---------------------------------------------------------------------------
// flash_mma2: FA2-style causal attention. Br=128, Bc=64, 8 warps, 256 thr.
// Each warp owns 16 q-rows x full 64 kv-cols; S and P live in registers;
// softmax via quad shuffles; K/V double-buffered cp.async; O written as
// bf16 hi/lo split directly into g_ah/g_al (in place over Q-split).
// smem: Qh 0 | Ql 34816 | stage s at 69632+s*69632 {Kh, Kl+17408, Vh+34816,
// Vl+52224}. Total 208896 B. Row pitch 272 B.
// ---------------------------------------------------------------------------
#define FA3_SMEM 208896

__global__ __launch_bounds__(256, 1)
void flash_mma2()
{
    extern __shared__ char sm2[];
    const uint32_t sb = smem_u32(sm2);
    const int qb = blockIdx.x, h = blockIdx.y, b = blockIdx.z;
    const int kvh = h >> 2;
    const int tid = threadIdx.x, lane = tid & 31, w = tid >> 5;
    const float SC = 0.08838834764831845f;
    const uint32_t oQl = 34816u, oKV0 = 69632u, KVST = 69632u;

    // ---- Q tile (128 rows x 128 cols, hi+lo) via cp.async ----
    {
        const size_t qrb = (size_t)(b * SEQ + qb * 128) * QW + h * HD;
#pragma unroll
        for (int j = 0; j < 16; j++) {
            int g = tid + 256 * j;
            int buf = g >> 11, idx = g & 2047;
            int row = idx >> 4, c16 = idx & 15;
            const __nv_bfloat16* src = (buf ? g_al : g_ah) + qrb + (size_t)row * QW + c16 * 8;
            CP_ASYNC16(sb + (uint32_t)buf * oQl + (uint32_t)row * 272u + (uint32_t)c16 * 16u, src);
        }
    }

#define ISSUE_KV(kb_) do { \
        const size_t rb_ = (size_t)(b * SEQ + (kb_) * 64) * KW + kvh * HD; \
        const uint32_t st_ = sb + oKV0 + (uint32_t)((kb_) & 1) * KVST; \
        _Pragma("unroll") \
        for (int j = 0; j < 16; j++) { \
            int g = tid + 256 * j; \
            int buf = g >> 10, idx = g & 1023; \
            int row = idx >> 4, c16 = idx & 15; \
            const __nv_bfloat16* src = \
                (buf == 0 ? g_kh : buf == 1 ? g_kl : buf == 2 ? g_vh : g_vl) \
                + rb_ + (size_t)row * KW + c16 * 8; \
            CP_ASYNC16(st_ + (uint32_t)buf * 17408u + (uint32_t)row * 272u + (uint32_t)c16 * 16u, src); \
        } \
        CP_COMMIT(); \
    } while (0)

    ISSUE_KV(0);   // commits Q loads too

    float acc_o[16][4];
#pragma unroll
    for (int n = 0; n < 16; n++)
#pragma unroll
        for (int d = 0; d < 4; d++) acc_o[n][d] = 0.0f;
    float mA = -CUDART_INF_F, mB = -CUDART_INF_F, lA = 0.0f, lB = 0.0f;

    const int growA = qb * 128 + w * 16 + (lane >> 2);   // rows growA, growA+8
    const uint32_t qa  = sb + (uint32_t)(w * 16 + (lane & 15)) * 272u + (uint32_t)(lane >> 4) * 16u;
    const uint32_t lrw = (uint32_t)(lane & 15) * 272u + (uint32_t)(lane >> 4) * 16u;

    const int NT = 2 * qb + 2;
    for (int kb = 0; kb < NT; kb++) {
        CP_WAIT(0);
        __syncthreads();
        if (kb + 1 < NT) ISSUE_KV(kb + 1);

        // warp-uniform skip: all 16 rows of this warp masked for this kv tile
        if (kb * 64 > qb * 128 + w * 16 + 15) continue;

        const uint32_t kvst = sb + oKV0 + (uint32_t)(kb & 1) * KVST;
        const uint32_t kvb  = kvst + lrw;            // K rows
        const uint32_t vvb  = kvst + 34816u + lrw;   // V rows

        // ---- S = Q K^T (3-term), 8 n-tiles in registers ----
        float accs[8][4];
#pragma unroll
        for (int n = 0; n < 8; n++)
#pragma unroll
            for (int d = 0; d < 4; d++) accs[n][d] = 0.0f;

#pragma unroll
        for (int k16 = 0; k16 < 8; k16++) {
            const uint32_t ko = (uint32_t)k16 * 32u;
            uint32_t qh[4], ql[4];
            LDSM4(qh[0], qh[1], qh[2], qh[3], qa + ko);
            LDSM4(ql[0], ql[1], ql[2], ql[3], qa + oQl + ko);
#pragma unroll
            for (int g4 = 0; g4 < 4; g4++) {
                uint32_t ka = kvb + (uint32_t)g4 * (16u * 272u) + ko;
                uint32_t kh[4], kl[4];
                LDSM4(kh[0], kh[1], kh[2], kh[3], ka);
                LDSM4(kl[0], kl[1], kl[2], kl[3], ka + 17408u);
#pragma unroll
                for (int hf = 0; hf < 2; hf++) {
                    const int nt = g4 * 2 + hf;
                    MMA16816(accs[nt], qh, kh[hf], kh[hf + 2]);
                    MMA16816(accs[nt], qh, kl[hf], kl[hf + 2]);
                    MMA16816(accs[nt], ql, kh[hf], kh[hf + 2]);
                }
            }
        }

        // ---- scale + causal mask in registers ----
        const bool need_mask = (kb * 64 + 63 > qb * 128 + w * 16);
#pragma unroll
        for (int nt = 0; nt < 8; nt++) {
            int col = kb * 64 + nt * 8 + (lane & 3) * 2;
            float s0 = accs[nt][0] * SC, s1 = accs[nt][1] * SC;
            float s2 = accs[nt][2] * SC, s3 = accs[nt][3] * SC;
            if (need_mask) {
                if (col     > growA)     s0 = -1e9f;
                if (col + 1 > growA)     s1 = -1e9f;
                if (col     > growA + 8) s2 = -1e9f;
                if (col + 1 > growA + 8) s3 = -1e9f;
            }
            accs[nt][0] = s0; accs[nt][1] = s1; accs[nt][2] = s2; accs[nt][3] = s3;
        }

        // ---- online softmax (quad shuffles) ----
        float mrA = -CUDART_INF_F, mrB = -CUDART_INF_F;
#pragma unroll
        for (int nt = 0; nt < 8; nt++) {
            mrA = fmaxf(mrA, fmaxf(accs[nt][0], accs[nt][1]));
            mrB = fmaxf(mrB, fmaxf(accs[nt][2], accs[nt][3]));
        }
        mrA = fmaxf(mrA, __shfl_xor_sync(0xffffffffu, mrA, 1));
        mrA = fmaxf(mrA, __shfl_xor_sync(0xffffffffu, mrA, 2));
        mrB = fmaxf(mrB, __shfl_xor_sync(0xffffffffu, mrB, 1));
        mrB = fmaxf(mrB, __shfl_xor_sync(0xffffffffu, mrB, 2));
        float mnA = fmaxf(mA, mrA), mnB = fmaxf(mB, mrB);
        float corrA = __expf(mA - mnA), corrB = __expf(mB - mnB);
        mA = mnA; mB = mnB;

        float sumA = 0.0f, sumB = 0.0f;
#pragma unroll
        for (int nt = 0; nt < 8; nt++) {
            float p0 = __expf(accs[nt][0] - mnA);
            float p1 = __expf(accs[nt][1] - mnA);
            float p2 = __expf(accs[nt][2] - mnB);
            float p3 = __expf(accs[nt][3] - mnB);
            sumA += p0 + p1; sumB += p2 + p3;
            accs[nt][0] = p0; accs[nt][1] = p1; accs[nt][2] = p2; accs[nt][3] = p3;
        }
        sumA += __shfl_xor_sync(0xffffffffu, sumA, 1);
        sumA += __shfl_xor_sync(0xffffffffu, sumA, 2);
        sumB += __shfl_xor_sync(0xffffffffu, sumB, 1);
        sumB += __shfl_xor_sync(0xffffffffu, sumB, 2);
        lA = lA * corrA + sumA;
        lB = lB * corrB + sumB;

        // ---- rescale O ----
#pragma unroll
        for (int nt = 0; nt < 16; nt++) {
            acc_o[nt][0] *= corrA; acc_o[nt][1] *= corrA;
            acc_o[nt][2] *= corrB; acc_o[nt][3] *= corrB;
        }

        // ---- O += P V (P from registers, 3-term) ----
#pragma unroll
        for (int kk = 0; kk < 4; kk++) {
            uint32_t aH[4], aL[4];
            aH[0] = split_hi(accs[2*kk][0], accs[2*kk][1]);
            aH[1] = split_hi(accs[2*kk][2], accs[2*kk][3]);
            aH[2] = split_hi(accs[2*kk+1][0], accs[2*kk+1][1]);
            aH[3] = split_hi(accs[2*kk+1][2], accs[2*kk+1][3]);
            aL[0] = split_lo(accs[2*kk][0], accs[2*kk][1]);
            aL[1] = split_lo(accs[2*kk][2], accs[2*kk][3]);
            aL[2] = split_lo(accs[2*kk+1][0], accs[2*kk+1][1]);
            aL[3] = split_lo(accs[2*kk+1][2], accs[2*kk+1][3]);
#pragma unroll
            for (int g = 0; g < 8; g++) {
                uint32_t va = vvb + (uint32_t)kk * (16u * 272u) + (uint32_t)g * 32u;
                uint32_t vh[4], vl[4];
                LDSM4T(vh[0], vh[1], vh[2], vh[3], va);
                LDSM4T(vl[0], vl[1], vl[2], vl[3], va + 17408u);
                MMA16816(acc_o[2*g],   aH, vh[0], vh[1]);
                MMA16816(acc_o[2*g],   aH, vl[0], vl[1]);
                MMA16816(acc_o[2*g],   aL, vh[0], vh[1]);
                MMA16816(acc_o[2*g+1], aH, vh[2], vh[3]);
                MMA16816(acc_o[2*g+1], aH, vl[2], vl[3]);
                MMA16816(acc_o[2*g+1], aL, vh[2], vh[3]);
            }
        }
    }

    // ---- epilogue: O/l -> bf16 hi/lo split directly into g_ah/g_al ----
    {
        float invA = 1.0f / lA, invB = 1.0f / lB;
        uint32_t* oh32 = (uint32_t*)g_ah;
        uint32_t* ol32 = (uint32_t*)g_al;
        size_t rowA = (size_t)(b * SEQ + qb * 128 + w * 16 + (lane >> 2));
#pragma unroll
        for (int nt = 0; nt < 16; nt++) {
            int col = h * HD + nt * 8 + (lane & 3) * 2;
            size_t o0 = (rowA * QW + col) >> 1;
            size_t o1 = ((rowA + 8) * QW + col) >> 1;
            float v0 = acc_o[nt][0] * invA, v1 = acc_o[nt][1] * invA;
            float v2 = acc_o[nt][2] * invB, v3 = acc_o[nt][3] * invB;
            oh32[o0] = split_hi(v0, v1);
            ol32[o0] = split_lo(v0, v1);
            oh32[o1] = split_hi(v2, v3);
            ol32[o1] = split_lo(v2, v3);
        }
    }
#undef ISSUE_KV
}

// ---------------------------------------------------------------------------
// Launch
// ---------------------------------------------------------------------------
extern "C" void kernel_launch(void* const* d_in, const int* in_sizes, int n_in,
                              void* d_out, int out_size)
{
    const float* x  = (const float*)d_in[0];
    const float* wq = (const float*)d_in[1];
    const float* wk = (const float*)d_in[2];
    const float* wv = (const float*)d_in[3];
    const float* wo = (const float*)d_in[4];
    const float* fc = (const float*)d_in[7];
    const float* fs = (const float*)d_in[8];
    float* out = (float*)d_out;

    __nv_bfloat16 *pah, *pal;
    __nv_bfloat16 *pwqh, *pwql, *pwkh, *pwkl, *pwvh, *pwvl, *pwoh, *pwol;
    cudaGetSymbolAddress((void**)&pah, g_ah);
    cudaGetSymbolAddress((void**)&pal, g_al);
    cudaGetSymbolAddress((void**)&pwqh, g_wqh);
    cudaGetSymbolAddress((void**)&pwql, g_wql);
    cudaGetSymbolAddress((void**)&pwkh, g_wkh);
    cudaGetSymbolAddress((void**)&pwkl, g_wkl);
    cudaGetSymbolAddress((void**)&pwvh, g_wvh);
    cudaGetSymbolAddress((void**)&pwvl, g_wvl);
    cudaGetSymbolAddress((void**)&pwoh, g_woh);
    cudaGetSymbolAddress((void**)&pwol, g_wol);

    cudaFuncSetAttribute(gemm_mma, cudaFuncAttributeMaxDynamicSharedMemorySize, (int)GSMEM_B);
    cudaFuncSetAttribute(gemm_qkv, cudaFuncAttributeMaxDynamicSharedMemorySize, (int)GSMEM_B);
    cudaFuncSetAttribute(flash_mma2, cudaFuncAttributeMaxDynamicSharedMemorySize, FA3_SMEM);

    // split x, transpose+split weights
    convert_split<<<(MROWS * DIM / 4 + 255) / 256, 256>>>(x, pah, pal, MROWS * DIM / 4);
    transpose_split<<<dim3(QW / 32, DIM / 32), dim3(32, 8)>>>(wq, pwqh, pwql, DIM, QW);
    transpose_split<<<dim3(KW / 32, DIM / 32), dim3(32, 8)>>>(wk, pwkh, pwkl, DIM, KW);
    transpose_split<<<dim3(KW / 32, DIM / 32), dim3(32, 8)>>>(wv, pwvh, pwvl, DIM, KW);
    transpose_split<<<dim3(DIM / 32, QW / 32), dim3(32, 8)>>>(wo, pwoh, pwol, QW, DIM);

    // fused QKV projection (V written pre-split)
    gemm_qkv<<<dim3(6144 / 128, MROWS / 128), 256, GSMEM_B>>>();

    // RoPE + split Q -> g_ah/g_al, K -> g_kh/g_kl
    const int total_pairs = MROWS * NH * (HD / 2) + MROWS * NKV * (HD / 2);
    rope_split_kernel<<<(total_pairs + 255) / 256, 256>>>(fc, fs);

    // flash attention (writes O-split in place into g_ah/g_al)
    flash_mma2<<<dim3(SEQ / 128, NH, BSZ), 256, FA3_SMEM>>>();

    // output projection
    gemm_mma<<<dim3(DIM / 128, MROWS / 128), 256, GSMEM_B>>>(pah, pal, pwoh, pwol, out, MROWS, DIM, DIM);
}

// round 6
// speedup vs baseline: 3.3980x; 1.4058x over previous
#include <cuda_runtime.h>
#include <cuda_fp16.h>
#include <math_constants.h>
#include <cstdint>

#define BSZ   2
#define SEQ   2048
#define DIM   4096
#define NH    32
#define NKV   8
#define HD    128
#define MROWS (BSZ*SEQ)   /* 4096 */
#define QW    (NH*HD)     /* 4096 */
#define KW    (NKV*HD)    /* 1024 */

// ---------------------------------------------------------------------------
// Static device scratch
// ---------------------------------------------------------------------------
__device__ float g_q[(size_t)MROWS * QW];     // fp32 Q pre-RoPE
__device__ float g_k[(size_t)MROWS * KW];     // fp32 K pre-RoPE

__device__ __half g_ah[(size_t)MROWS * DIM];  // x-split -> Q-split -> O-split (hi)
__device__ __half g_al[(size_t)MROWS * DIM];  // (lo)
__device__ __half g_kf[(size_t)MROWS * KW];   // K post-RoPE, single fp16
__device__ __half g_vf[(size_t)MROWS * KW];   // V, single fp16
__device__ __half g_wq[(size_t)QW * DIM];     // transposed weights, single fp16
__device__ __half g_wk[(size_t)KW * DIM];
__device__ __half g_wv[(size_t)KW * DIM];
__device__ __half g_wo[(size_t)DIM * QW];

// ---------------------------------------------------------------------------
// PTX helpers
// ---------------------------------------------------------------------------
__device__ __forceinline__ uint32_t smem_u32(const void* p) {
    uint32_t a;
    asm("{ .reg .u64 t; cvta.to.shared.u64 t, %1; cvt.u32.u64 %0, t; }" : "=r"(a) : "l"(p));
    return a;
}
#define CP_ASYNC16(dst, src) \
    asm volatile("cp.async.cg.shared.global [%0], [%1], 16;" :: "r"(dst), "l"(src))
#define CP_COMMIT() asm volatile("cp.async.commit_group;" ::: "memory")
#define CP_WAIT(n)  asm volatile("cp.async.wait_group %0;" :: "n"(n) : "memory")

#define LDSM4(R0, R1, R2, R3, addr) \
    asm volatile("ldmatrix.sync.aligned.m8n8.x4.shared.b16 {%0,%1,%2,%3}, [%4];" \
        : "=r"(R0), "=r"(R1), "=r"(R2), "=r"(R3) : "r"(addr))
#define LDSM4T(R0, R1, R2, R3, addr) \
    asm volatile("ldmatrix.sync.aligned.m8n8.x4.trans.shared.b16 {%0,%1,%2,%3}, [%4];" \
        : "=r"(R0), "=r"(R1), "=r"(R2), "=r"(R3) : "r"(addr))

#define MMA16816(D, A, B0, B1) \
    asm volatile("mma.sync.aligned.m16n8k16.row.col.f32.f16.f16.f32 " \
        "{%0,%1,%2,%3},{%4,%5,%6,%7},{%8,%9},{%0,%1,%2,%3};" \
        : "+f"((D)[0]), "+f"((D)[1]), "+f"((D)[2]), "+f"((D)[3]) \
        : "r"((A)[0]), "r"((A)[1]), "r"((A)[2]), "r"((A)[3]), "r"(B0), "r"(B1))

__device__ __forceinline__ uint32_t pack_h(__half a, __half b) {
    union { __half h[2]; uint32_t u; } t;
    t.h[0] = a; t.h[1] = b;
    return t.u;
}
__device__ __forceinline__ uint32_t hsplit_hi(float a, float b) {
    return pack_h(__float2half_rn(a), __float2half_rn(b));
}
__device__ __forceinline__ uint32_t hsplit_lo(float a, float b) {
    __half ha = __float2half_rn(a), hb = __float2half_rn(b);
    return pack_h(__float2half_rn(a - __half2float(ha)),
                  __float2half_rn(b - __half2float(hb)));
}

// ---------------------------------------------------------------------------
// convert_split: fp32 -> fp16 hi + lo
// ---------------------------------------------------------------------------
__global__ void convert_split(const float* __restrict__ in,
                              __half* __restrict__ oh,
                              __half* __restrict__ ol, int n4)
{
    int i = blockIdx.x * blockDim.x + threadIdx.x;
    if (i >= n4) return;
    float4 v = ((const float4*)in)[i];
    uint2 H, L;
    H.x = hsplit_hi(v.x, v.y); H.y = hsplit_hi(v.z, v.w);
    L.x = hsplit_lo(v.x, v.y); L.y = hsplit_lo(v.z, v.w);
    ((uint2*)oh)[i] = H;
    ((uint2*)ol)[i] = L;
}

// ---------------------------------------------------------------------------
// transpose_half: fp32 [R,C] -> fp16 [C,R] single
// ---------------------------------------------------------------------------
__global__ void transpose_half(const float* __restrict__ in,
                               __half* __restrict__ o, int R, int C)
{
    __shared__ float t[32][33];
    int c0 = blockIdx.x * 32, r0 = blockIdx.y * 32;
    int tx = threadIdx.x, ty = threadIdx.y;
#pragma unroll
    for (int i = 0; i < 4; i++)
        t[ty + 8 * i][tx] = in[(size_t)(r0 + ty + 8 * i) * C + c0 + tx];
    __syncthreads();
#pragma unroll
    for (int i = 0; i < 4; i++)
        o[(size_t)(c0 + ty + 8 * i) * R + r0 + tx] = __float2half_rn(t[tx][ty + 8 * i]);
}

// ---------------------------------------------------------------------------
// fp16 2-term GEMM machinery: 128x128 tile, BK=32, 8 warps (2x4).
// A split (hi/lo), B single. Stage: Ah 0 | Al 10240 | B 20480 (pitch 80B).
// 4 stages x 30720B = 122880B dynamic smem.
// ---------------------------------------------------------------------------
#define GSTG_H  30720u
#define GSMEM_H (4u * GSTG_H)

// gemm_mma: generic fp32 C output (used for wo projection)
__global__ __launch_bounds__(256, 1)
void gemm_mma(const __half* __restrict__ Ah, const __half* __restrict__ Al,
              const __half* __restrict__ B, float* __restrict__ C,
              int M, int N, int K)
{
    extern __shared__ char smc[];
    const uint32_t sb = smem_u32(smc);
    const int tid  = threadIdx.x;
    const int lane = tid & 31;
    const int wid  = tid >> 5;
    const int warp_m = wid >> 2;
    const int warp_n = wid & 3;
    const int m0 = blockIdx.y * 128;
    const int n0 = blockIdx.x * 128;
    const int NT = K >> 5;

    uint32_t dstoff[6];
    const __half* srcrow[6];
#pragma unroll
    for (int j = 0; j < 6; j++) {
        int c   = tid + 256 * j;        // 0..1535
        int buf = c >> 9;               // 0 Ah, 1 Al, 2 B
        int idx = c & 511;
        int row = idx >> 2;
        int kc  = idx & 3;
        dstoff[j] = (uint32_t)buf * 10240u + (uint32_t)row * 80u + (uint32_t)kc * 16u;
        const __half* base =
            (buf == 0) ? Ah + (size_t)(m0 + row) * K :
            (buf == 1) ? Al + (size_t)(m0 + row) * K :
                         B + (size_t)(n0 + row) * K;
        srcrow[j] = base + kc * 8;
    }

#define ISSUE_STAGE(kt) do { \
        uint32_t stb = sb + (uint32_t)((kt) & 3) * GSTG_H; \
        const int kel = (kt) << 5; \
        _Pragma("unroll") \
        for (int j = 0; j < 6; j++) \
            CP_ASYNC16(stb + dstoff[j], srcrow[j] + kel); \
        CP_COMMIT(); \
    } while (0)

    float acc[4][4][4];
#pragma unroll
    for (int a = 0; a < 4; a++)
#pragma unroll
        for (int b = 0; b < 4; b++)
#pragma unroll
            for (int d = 0; d < 4; d++) acc[a][b][d] = 0.0f;

    ISSUE_STAGE(0);
    ISSUE_STAGE(1);

    const uint32_t a_lrow = (uint32_t)(warp_m * 64 + (lane & 15)) * 80u + (uint32_t)(lane >> 4) * 16u;
    const uint32_t b_lrow = (uint32_t)(warp_n * 32 + (lane & 15)) * 80u + (uint32_t)(lane >> 4) * 16u;

    for (int kt = 0; kt < NT; kt++) {
        if (kt + 2 < NT) { ISSUE_STAGE(kt + 2); CP_WAIT(2); }
        else if (kt + 1 < NT) { CP_WAIT(1); }
        else { CP_WAIT(0); }
        __syncthreads();

        const uint32_t stb = sb + (uint32_t)(kt & 3) * GSTG_H;
#pragma unroll
        for (int k16 = 0; k16 < 2; k16++) {
            const uint32_t koff = (uint32_t)k16 * 32u;
            uint32_t ah[4][4], al[4][4];
#pragma unroll
            for (int mt = 0; mt < 4; mt++) {
                uint32_t addr = stb + a_lrow + (uint32_t)mt * (16u * 80u) + koff;
                LDSM4(ah[mt][0], ah[mt][1], ah[mt][2], ah[mt][3], addr);
                LDSM4(al[mt][0], al[mt][1], al[mt][2], al[mt][3], addr + 10240u);
            }
            uint32_t bh[2][4];
#pragma unroll
            for (int bt = 0; bt < 2; bt++) {
                uint32_t addr = stb + 20480u + b_lrow + (uint32_t)bt * (16u * 80u) + koff;
                LDSM4(bh[bt][0], bh[bt][1], bh[bt][2], bh[bt][3], addr);
            }
#pragma unroll
            for (int mt = 0; mt < 4; mt++) {
#pragma unroll
                for (int nt = 0; nt < 4; nt++) {
                    const int bt = nt >> 1, hf = nt & 1;
                    MMA16816(acc[mt][nt], ah[mt], bh[bt][hf], bh[bt][hf + 2]);
                    MMA16816(acc[mt][nt], al[mt], bh[bt][hf], bh[bt][hf + 2]);
                }
            }
        }
    }

#pragma unroll
    for (int mt = 0; mt < 4; mt++) {
        int row = m0 + warp_m * 64 + mt * 16 + (lane >> 2);
#pragma unroll
        for (int nt = 0; nt < 4; nt++) {
            int col = n0 + warp_n * 32 + nt * 8 + (lane & 3) * 2;
            *(float2*)(C + (size_t)row * N + col) =
                make_float2(acc[mt][nt][0], acc[mt][nt][1]);
            *(float2*)(C + (size_t)(row + 8) * N + col) =
                make_float2(acc[mt][nt][2], acc[mt][nt][3]);
        }
    }
#undef ISSUE_STAGE
}

// gemm_qkv: fused QKV projection, virtual N = 6144.
// cols 0..4095 -> Q fp32, 4096..5119 -> K fp32, 5120..6143 -> V fp16 single.
__global__ __launch_bounds__(256, 1)
void gemm_qkv()
{
    extern __shared__ char smc[];
    const uint32_t sb = smem_u32(smc);
    const int tid  = threadIdx.x;
    const int lane = tid & 31;
    const int wid  = tid >> 5;
    const int warp_m = wid >> 2;
    const int warp_n = wid & 3;
    const int m0 = blockIdx.y * 128;
    const int n0 = blockIdx.x * 128;
    const int K = DIM;
    const int NT = K >> 5;

    const __half* B;
    if (n0 < 4096)      B = g_wq + (size_t)n0 * K;
    else if (n0 < 5120) B = g_wk + (size_t)(n0 - 4096) * K;
    else                B = g_wv + (size_t)(n0 - 5120) * K;

    uint32_t dstoff[6];
    const __half* srcrow[6];
#pragma unroll
    for (int j = 0; j < 6; j++) {
        int c   = tid + 256 * j;
        int buf = c >> 9;
        int idx = c & 511;
        int row = idx >> 2;
        int kc  = idx & 3;
        dstoff[j] = (uint32_t)buf * 10240u + (uint32_t)row * 80u + (uint32_t)kc * 16u;
        const __half* base =
            (buf == 0) ? g_ah + (size_t)(m0 + row) * K :
            (buf == 1) ? g_al + (size_t)(m0 + row) * K :
                         B + (size_t)row * K;
        srcrow[j] = base + kc * 8;
    }

#define ISSUE_STAGE(kt) do { \
        uint32_t stb = sb + (uint32_t)((kt) & 3) * GSTG_H; \
        const int kel = (kt) << 5; \
        _Pragma("unroll") \
        for (int j = 0; j < 6; j++) \
            CP_ASYNC16(stb + dstoff[j], srcrow[j] + kel); \
        CP_COMMIT(); \
    } while (0)

    float acc[4][4][4];
#pragma unroll
    for (int a = 0; a < 4; a++)
#pragma unroll
        for (int b = 0; b < 4; b++)
#pragma unroll
            for (int d = 0; d < 4; d++) acc[a][b][d] = 0.0f;

    ISSUE_STAGE(0);
    ISSUE_STAGE(1);

    const uint32_t a_lrow = (uint32_t)(warp_m * 64 + (lane & 15)) * 80u + (uint32_t)(lane >> 4) * 16u;
    const uint32_t b_lrow = (uint32_t)(warp_n * 32 + (lane & 15)) * 80u + (uint32_t)(lane >> 4) * 16u;

    for (int kt = 0; kt < NT; kt++) {
        if (kt + 2 < NT) { ISSUE_STAGE(kt + 2); CP_WAIT(2); }
        else if (kt + 1 < NT) { CP_WAIT(1); }
        else { CP_WAIT(0); }
        __syncthreads();

        const uint32_t stb = sb + (uint32_t)(kt & 3) * GSTG_H;
#pragma unroll
        for (int k16 = 0; k16 < 2; k16++) {
            const uint32_t koff = (uint32_t)k16 * 32u;
            uint32_t ah[4][4], al[4][4];
#pragma unroll
            for (int mt = 0; mt < 4; mt++) {
                uint32_t addr = stb + a_lrow + (uint32_t)mt * (16u * 80u) + koff;
                LDSM4(ah[mt][0], ah[mt][1], ah[mt][2], ah[mt][3], addr);
                LDSM4(al[mt][0], al[mt][1], al[mt][2], al[mt][3], addr + 10240u);
            }
            uint32_t bh[2][4];
#pragma unroll
            for (int bt = 0; bt < 2; bt++) {
                uint32_t addr = stb + 20480u + b_lrow + (uint32_t)bt * (16u * 80u) + koff;
                LDSM4(bh[bt][0], bh[bt][1], bh[bt][2], bh[bt][3], addr);
            }
#pragma unroll
            for (int mt = 0; mt < 4; mt++) {
#pragma unroll
                for (int nt = 0; nt < 4; nt++) {
                    const int bt = nt >> 1, hf = nt & 1;
                    MMA16816(acc[mt][nt], ah[mt], bh[bt][hf], bh[bt][hf + 2]);
                    MMA16816(acc[mt][nt], al[mt], bh[bt][hf], bh[bt][hf + 2]);
                }
            }
        }
    }

#pragma unroll
    for (int mt = 0; mt < 4; mt++) {
        int row = m0 + warp_m * 64 + mt * 16 + (lane >> 2);
#pragma unroll
        for (int nt = 0; nt < 4; nt++) {
            int coll = warp_n * 32 + nt * 8 + (lane & 3) * 2;
            if (n0 < 4096) {
                int col = n0 + coll;
                *(float2*)(g_q + (size_t)row * QW + col) =
                    make_float2(acc[mt][nt][0], acc[mt][nt][1]);
                *(float2*)(g_q + (size_t)(row + 8) * QW + col) =
                    make_float2(acc[mt][nt][2], acc[mt][nt][3]);
            } else if (n0 < 5120) {
                int col = n0 - 4096 + coll;
                *(float2*)(g_k + (size_t)row * KW + col) =
                    make_float2(acc[mt][nt][0], acc[mt][nt][1]);
                *(float2*)(g_k + (size_t)(row + 8) * KW + col) =
                    make_float2(acc[mt][nt][2], acc[mt][nt][3]);
            } else {
                int col = n0 - 5120 + coll;
                uint32_t* vf32 = (uint32_t*)g_vf;
                vf32[((size_t)row * KW + col) >> 1] =
                    hsplit_hi(acc[mt][nt][0], acc[mt][nt][1]);
                vf32[((size_t)(row + 8) * KW + col) >> 1] =
                    hsplit_hi(acc[mt][nt][2], acc[mt][nt][3]);
            }
        }
    }
#undef ISSUE_STAGE
}

// ---------------------------------------------------------------------------
// RoPE + convert: Q -> fp16 hi/lo (g_ah/g_al), K -> fp16 single (g_kf)
// ---------------------------------------------------------------------------
__global__ void rope_split_kernel(const float* __restrict__ fc, const float* __restrict__ fs)
{
    const int QP = MROWS * NH * (HD / 2);
    const int KP = MROWS * NKV * (HD / 2);
    int idx = blockIdx.x * blockDim.x + threadIdx.x;
    if (idx >= QP + KP) return;

    if (idx < QP) {
        int i = idx & 63;
        int rest = idx >> 6;
        int hh = rest & 31, row = rest >> 5;
        int s = row & (SEQ - 1);
        size_t off = ((size_t)row * QW + (size_t)hh * HD) / 2 + i;
        float2 v = ((const float2*)g_q)[off];
        float c = fc[s * 64 + i], sn = fs[s * 64 + i];
        float ox = v.x * c - v.y * sn;
        float oy = v.x * sn + v.y * c;
        ((uint32_t*)g_ah)[off] = hsplit_hi(ox, oy);
        ((uint32_t*)g_al)[off] = hsplit_lo(ox, oy);
    } else {
        int li = idx - QP;
        int i = li & 63;
        int rest = li >> 6;
        int hh = rest & 7, row = rest >> 3;
        int s = row & (SEQ - 1);
        size_t off = ((size_t)row * KW + (size_t)hh * HD) / 2 + i;
        float2 v = ((const float2*)g_k)[off];
        float c = fc[s * 64 + i], sn = fs[s * 64 + i];
        float ox = v.x * c - v.y * sn;
        float oy = v.x * sn + v.y * c;
        ((uint32_t*)g_kf)[off] = hsplit_hi(ox, oy);
    }
}

// ---------------------------------------------------------------------------
// flash_mma2: FA2-style causal attention, fp16 2-term.
// Br=128, Bc=64, 8 warps. Q split (hi/lo), K single, P split in-reg, V single.
// smem: Qh 0 | Ql 34816 | stage s at 69632+s*34816 {K 0, V +17408}. Pitch 272B.
// Total 139264 B.
// ---------------------------------------------------------------------------
#define FA4_SMEM 139264

__global__ __launch_bounds__(256, 1)
void flash_mma2()
{
    extern __shared__ char sm2[];
    const uint32_t sb = smem_u32(sm2);
    const int qb = blockIdx.x, h = blockIdx.y, b = blockIdx.z;
    const int kvh = h >> 2;
    const int tid = threadIdx.x, lane = tid & 31, w = tid >> 5;
    const float SC = 0.08838834764831845f;
    const uint32_t oQl = 34816u, oKV0 = 69632u, KVST = 34816u;

    // ---- Q tile (128 rows x 128 cols, hi+lo) via cp.async ----
    {
        const size_t qrb = (size_t)(b * SEQ + qb * 128) * QW + h * HD;
#pragma unroll
        for (int j = 0; j < 16; j++) {
            int g = tid + 256 * j;
            int buf = g >> 11, idx = g & 2047;
            int row = idx >> 4, c16 = idx & 15;
            const __half* src = (buf ? g_al : g_ah) + qrb + (size_t)row * QW + c16 * 8;
            CP_ASYNC16(sb + (uint32_t)buf * oQl + (uint32_t)row * 272u + (uint32_t)c16 * 16u, src);
        }
    }

#define ISSUE_KV(kb_) do { \
        const size_t rb_ = (size_t)(b * SEQ + (kb_) * 64) * KW + kvh * HD; \
        const uint32_t st_ = sb + oKV0 + (uint32_t)((kb_) & 1) * KVST; \
        _Pragma("unroll") \
        for (int j = 0; j < 8; j++) { \
            int g = tid + 256 * j; \
            int buf = g >> 10, idx = g & 1023; \
            int row = idx >> 4, c16 = idx & 15; \
            const __half* src = (buf ? g_vf : g_kf) + rb_ + (size_t)row * KW + c16 * 8; \
            CP_ASYNC16(st_ + (uint32_t)buf * 17408u + (uint32_t)row * 272u + (uint32_t)c16 * 16u, src); \
        } \
        CP_COMMIT(); \
    } while (0)

    ISSUE_KV(0);   // commits Q loads too

    float acc_o[16][4];
#pragma unroll
    for (int n = 0; n < 16; n++)
#pragma unroll
        for (int d = 0; d < 4; d++) acc_o[n][d] = 0.0f;
    float mA = -CUDART_INF_F, mB = -CUDART_INF_F, lA = 0.0f, lB = 0.0f;

    const int growA = qb * 128 + w * 16 + (lane >> 2);
    const uint32_t qa  = sb + (uint32_t)(w * 16 + (lane & 15)) * 272u + (uint32_t)(lane >> 4) * 16u;
    const uint32_t lrw = (uint32_t)(lane & 15) * 272u + (uint32_t)(lane >> 4) * 16u;

    const int NT = 2 * qb + 2;
    for (int kb = 0; kb < NT; kb++) {
        CP_WAIT(0);
        __syncthreads();
        if (kb + 1 < NT) ISSUE_KV(kb + 1);

        if (kb * 64 > qb * 128 + w * 16 + 15) continue;   // fully masked for this warp

        const uint32_t kvst = sb + oKV0 + (uint32_t)(kb & 1) * KVST;
        const uint32_t kvb  = kvst + lrw;
        const uint32_t vvb  = kvst + 17408u + lrw;

        // ---- S = Q K^T (2-term) ----
        float accs[8][4];
#pragma unroll
        for (int n = 0; n < 8; n++)
#pragma unroll
            for (int d = 0; d < 4; d++) accs[n][d] = 0.0f;

#pragma unroll
        for (int k16 = 0; k16 < 8; k16++) {
            const uint32_t ko = (uint32_t)k16 * 32u;
            uint32_t qh[4], ql[4];
            LDSM4(qh[0], qh[1], qh[2], qh[3], qa + ko);
            LDSM4(ql[0], ql[1], ql[2], ql[3], qa + oQl + ko);
#pragma unroll
            for (int g4 = 0; g4 < 4; g4++) {
                uint32_t ka = kvb + (uint32_t)g4 * (16u * 272u) + ko;
                uint32_t kh[4];
                LDSM4(kh[0], kh[1], kh[2], kh[3], ka);
#pragma unroll
                for (int hf = 0; hf < 2; hf++) {
                    const int nt = g4 * 2 + hf;
                    MMA16816(accs[nt], qh, kh[hf], kh[hf + 2]);
                    MMA16816(accs[nt], ql, kh[hf], kh[hf + 2]);
                }
            }
        }

        // ---- scale + causal mask ----
        const bool need_mask = (kb * 64 + 63 > qb * 128 + w * 16);
#pragma unroll
        for (int nt = 0; nt < 8; nt++) {
            int col = kb * 64 + nt * 8 + (lane & 3) * 2;
            float s0 = accs[nt][0] * SC, s1 = accs[nt][1] * SC;
            float s2 = accs[nt][2] * SC, s3 = accs[nt][3] * SC;
            if (need_mask) {
                if (col     > growA)     s0 = -1e9f;
                if (col + 1 > growA)     s1 = -1e9f;
                if (col     > growA + 8) s2 = -1e9f;
                if (col + 1 > growA + 8) s3 = -1e9f;
            }
            accs[nt][0] = s0; accs[nt][1] = s1; accs[nt][2] = s2; accs[nt][3] = s3;
        }

        // ---- online softmax (quad shuffles) ----
        float mrA = -CUDART_INF_F, mrB = -CUDART_INF_F;
#pragma unroll
        for (int nt = 0; nt < 8; nt++) {
            mrA = fmaxf(mrA, fmaxf(accs[nt][0], accs[nt][1]));
            mrB = fmaxf(mrB, fmaxf(accs[nt][2], accs[nt][3]));
        }
        mrA = fmaxf(mrA, __shfl_xor_sync(0xffffffffu, mrA, 1));
        mrA = fmaxf(mrA, __shfl_xor_sync(0xffffffffu, mrA, 2));
        mrB = fmaxf(mrB, __shfl_xor_sync(0xffffffffu, mrB, 1));
        mrB = fmaxf(mrB, __shfl_xor_sync(0xffffffffu, mrB, 2));
        float mnA = fmaxf(mA, mrA), mnB = fmaxf(mB, mrB);
        float corrA = __expf(mA - mnA), corrB = __expf(mB - mnB);
        mA = mnA; mB = mnB;

        float sumA = 0.0f, sumB = 0.0f;
#pragma unroll
        for (int nt = 0; nt < 8; nt++) {
            float p0 = __expf(accs[nt][0] - mnA);
            float p1 = __expf(accs[nt][1] - mnA);
            float p2 = __expf(accs[nt][2] - mnB);
            float p3 = __expf(accs[nt][3] - mnB);
            sumA += p0 + p1; sumB += p2 + p3;
            accs[nt][0] = p0; accs[nt][1] = p1; accs[nt][2] = p2; accs[nt][3] = p3;
        }
        sumA += __shfl_xor_sync(0xffffffffu, sumA, 1);
        sumA += __shfl_xor_sync(0xffffffffu, sumA, 2);
        sumB += __shfl_xor_sync(0xffffffffu, sumB, 1);
        sumB += __shfl_xor_sync(0xffffffffu, sumB, 2);
        lA = lA * corrA + sumA;
        lB = lB * corrB + sumB;

        // ---- rescale O ----
#pragma unroll
        for (int nt = 0; nt < 16; nt++) {
            acc_o[nt][0] *= corrA; acc_o[nt][1] *= corrA;
            acc_o[nt][2] *= corrB; acc_o[nt][3] *= corrB;
        }

        // ---- O += P V (P split in registers, V single) ----
#pragma unroll
        for (int kk = 0; kk < 4; kk++) {
            uint32_t aH[4], aL[4];
            aH[0] = hsplit_hi(accs[2*kk][0], accs[2*kk][1]);
            aH[1] = hsplit_hi(accs[2*kk][2], accs[2*kk][3]);
            aH[2] = hsplit_hi(accs[2*kk+1][0], accs[2*kk+1][1]);
            aH[3] = hsplit_hi(accs[2*kk+1][2], accs[2*kk+1][3]);
            aL[0] = hsplit_lo(accs[2*kk][0], accs[2*kk][1]);
            aL[1] = hsplit_lo(accs[2*kk][2], accs[2*kk][3]);
            aL[2] = hsplit_lo(accs[2*kk+1][0], accs[2*kk+1][1]);
            aL[3] = hsplit_lo(accs[2*kk+1][2], accs[2*kk+1][3]);
#pragma unroll
            for (int g = 0; g < 8; g++) {
                uint32_t va = vvb + (uint32_t)kk * (16u * 272u) + (uint32_t)g * 32u;
                uint32_t vh[4];
                LDSM4T(vh[0], vh[1], vh[2], vh[3], va);
                MMA16816(acc_o[2*g],   aH, vh[0], vh[1]);
                MMA16816(acc_o[2*g],   aL, vh[0], vh[1]);
                MMA16816(acc_o[2*g+1], aH, vh[2], vh[3]);
                MMA16816(acc_o[2*g+1], aL, vh[2], vh[3]);
            }
        }
    }

    // ---- epilogue: O/l -> fp16 hi/lo split into g_ah/g_al ----
    {
        float invA = 1.0f / lA, invB = 1.0f / lB;
        uint32_t* oh32 = (uint32_t*)g_ah;
        uint32_t* ol32 = (uint32_t*)g_al;
        size_t rowA = (size_t)(b * SEQ + qb * 128 + w * 16 + (lane >> 2));
#pragma unroll
        for (int nt = 0; nt < 16; nt++) {
            int col = h * HD + nt * 8 + (lane & 3) * 2;
            size_t o0 = (rowA * QW + col) >> 1;
            size_t o1 = ((rowA + 8) * QW + col) >> 1;
            float v0 = acc_o[nt][0] * invA, v1 = acc_o[nt][1] * invA;
            float v2 = acc_o[nt][2] * invB, v3 = acc_o[nt][3] * invB;
            oh32[o0] = hsplit_hi(v0, v1);
            ol32[o0] = hsplit_lo(v0, v1);
            oh32[o1] = hsplit_hi(v2, v3);
            ol32[o1] = hsplit_lo(v2, v3);
        }
    }
#undef ISSUE_KV
}

// ---------------------------------------------------------------------------
// Launch
// ---------------------------------------------------------------------------
extern "C" void kernel_launch(void* const* d_in, const int* in_sizes, int n_in,
                              void* d_out, int out_size)
{
    const float* x  = (const float*)d_in[0];
    const float* wq = (const float*)d_in[1];
    const float* wk = (const float*)d_in[2];
    const float* wv = (const float*)d_in[3];
    const float* wo = (const float*)d_in[4];
    const float* fc = (const float*)d_in[7];
    const float* fs = (const float*)d_in[8];
    float* out = (float*)d_out;

    __half *pah, *pal, *pwq, *pwk, *pwv, *pwo;
    cudaGetSymbolAddress((void**)&pah, g_ah);
    cudaGetSymbolAddress((void**)&pal, g_al);
    cudaGetSymbolAddress((void**)&pwq, g_wq);
    cudaGetSymbolAddress((void**)&pwk, g_wk);
    cudaGetSymbolAddress((void**)&pwv, g_wv);
    cudaGetSymbolAddress((void**)&pwo, g_wo);

    cudaFuncSetAttribute(gemm_mma, cudaFuncAttributeMaxDynamicSharedMemorySize, (int)GSMEM_H);
    cudaFuncSetAttribute(gemm_qkv, cudaFuncAttributeMaxDynamicSharedMemorySize, (int)GSMEM_H);
    cudaFuncSetAttribute(flash_mma2, cudaFuncAttributeMaxDynamicSharedMemorySize, FA4_SMEM);

    // split x, transpose weights (single fp16)
    convert_split<<<(MROWS * DIM / 4 + 255) / 256, 256>>>(x, pah, pal, MROWS * DIM / 4);
    transpose_half<<<dim3(QW / 32, DIM / 32), dim3(32, 8)>>>(wq, pwq, DIM, QW);
    transpose_half<<<dim3(KW / 32, DIM / 32), dim3(32, 8)>>>(wk, pwk, DIM, KW);
    transpose_half<<<dim3(KW / 32, DIM / 32), dim3(32, 8)>>>(wv, pwv, DIM, KW);
    transpose_half<<<dim3(DIM / 32, QW / 32), dim3(32, 8)>>>(wo, pwo, QW, DIM);

    // fused QKV projection (V written directly as fp16)
    gemm_qkv<<<dim3(6144 / 128, MROWS / 128), 256, GSMEM_H>>>();

    // RoPE: Q -> split fp16, K -> single fp16
    const int total_pairs = MROWS * NH * (HD / 2) + MROWS * NKV * (HD / 2);
    rope_split_kernel<<<(total_pairs + 255) / 256, 256>>>(fc, fs);

    // flash attention (writes O-split in place into g_ah/g_al)
    flash_mma2<<<dim3(SEQ / 128, NH, BSZ), 256, FA4_SMEM>>>();

    // output projection
    gemm_mma<<<dim3(DIM / 128, MROWS / 128), 256, GSMEM_H>>>(pah, pal, pwo, out, MROWS, DIM, DIM);
}

// round 7
// speedup vs baseline: 3.6859x; 1.0847x over previous
#include <cuda_runtime.h>
#include <cuda_fp16.h>
#include <math_constants.h>
#include <cstdint>

#define BSZ   2
#define SEQ   2048
#define DIM   4096
#define NH    32
#define NKV   8
#define HD    128
#define MROWS (BSZ*SEQ)   /* 4096 */
#define QW    (NH*HD)     /* 4096 */
#define KW    (NKV*HD)    /* 1024 */

// ---------------------------------------------------------------------------
// Static device scratch
// ---------------------------------------------------------------------------
__device__ __half g_ah[(size_t)MROWS * DIM];  // x-split hi (A operand of QKV gemm)
__device__ __half g_al[(size_t)MROWS * DIM];  // x-split lo
__device__ __half g_qh[(size_t)MROWS * QW];   // Q-split (post-RoPE) -> O-split
__device__ __half g_ql[(size_t)MROWS * QW];
__device__ __half g_kf[(size_t)MROWS * KW];   // K post-RoPE, single fp16
__device__ __half g_vf[(size_t)MROWS * KW];   // V, single fp16
__device__ __half g_wq[(size_t)QW * DIM];     // transposed weights, single fp16
__device__ __half g_wk[(size_t)KW * DIM];
__device__ __half g_wv[(size_t)KW * DIM];
__device__ __half g_wo[(size_t)DIM * QW];

// ---------------------------------------------------------------------------
// PTX helpers
// ---------------------------------------------------------------------------
__device__ __forceinline__ uint32_t smem_u32(const void* p) {
    uint32_t a;
    asm("{ .reg .u64 t; cvta.to.shared.u64 t, %1; cvt.u32.u64 %0, t; }" : "=r"(a) : "l"(p));
    return a;
}
#define CP_ASYNC16(dst, src) \
    asm volatile("cp.async.cg.shared.global [%0], [%1], 16;" :: "r"(dst), "l"(src))
#define CP_COMMIT() asm volatile("cp.async.commit_group;" ::: "memory")
#define CP_WAIT(n)  asm volatile("cp.async.wait_group %0;" :: "n"(n) : "memory")

#define LDSM4(R0, R1, R2, R3, addr) \
    asm volatile("ldmatrix.sync.aligned.m8n8.x4.shared.b16 {%0,%1,%2,%3}, [%4];" \
        : "=r"(R0), "=r"(R1), "=r"(R2), "=r"(R3) : "r"(addr))
#define LDSM4T(R0, R1, R2, R3, addr) \
    asm volatile("ldmatrix.sync.aligned.m8n8.x4.trans.shared.b16 {%0,%1,%2,%3}, [%4];" \
        : "=r"(R0), "=r"(R1), "=r"(R2), "=r"(R3) : "r"(addr))

#define MMA16816(D, A, B0, B1) \
    asm volatile("mma.sync.aligned.m16n8k16.row.col.f32.f16.f16.f32 " \
        "{%0,%1,%2,%3},{%4,%5,%6,%7},{%8,%9},{%0,%1,%2,%3};" \
        : "+f"((D)[0]), "+f"((D)[1]), "+f"((D)[2]), "+f"((D)[3]) \
        : "r"((A)[0]), "r"((A)[1]), "r"((A)[2]), "r"((A)[3]), "r"(B0), "r"(B1))

__device__ __forceinline__ uint32_t pack_h(__half a, __half b) {
    union { __half h[2]; uint32_t u; } t;
    t.h[0] = a; t.h[1] = b;
    return t.u;
}
__device__ __forceinline__ uint32_t hsplit_hi(float a, float b) {
    return pack_h(__float2half_rn(a), __float2half_rn(b));
}
__device__ __forceinline__ uint32_t hsplit_lo(float a, float b) {
    __half ha = __float2half_rn(a), hb = __float2half_rn(b);
    return pack_h(__float2half_rn(a - __half2float(ha)),
                  __float2half_rn(b - __half2float(hb)));
}

// ---------------------------------------------------------------------------
// convert_split: fp32 -> fp16 hi + lo
// ---------------------------------------------------------------------------
__global__ void convert_split(const float* __restrict__ in,
                              __half* __restrict__ oh,
                              __half* __restrict__ ol, int n4)
{
    int i = blockIdx.x * blockDim.x + threadIdx.x;
    if (i >= n4) return;
    float4 v = ((const float4*)in)[i];
    uint2 H, L;
    H.x = hsplit_hi(v.x, v.y); H.y = hsplit_hi(v.z, v.w);
    L.x = hsplit_lo(v.x, v.y); L.y = hsplit_lo(v.z, v.w);
    ((uint2*)oh)[i] = H;
    ((uint2*)ol)[i] = L;
}

// ---------------------------------------------------------------------------
// transpose_half: fp32 [R,C] -> fp16 [C,R] single
// ---------------------------------------------------------------------------
__global__ void transpose_half(const float* __restrict__ in,
                               __half* __restrict__ o, int R, int C)
{
    __shared__ float t[32][33];
    int c0 = blockIdx.x * 32, r0 = blockIdx.y * 32;
    int tx = threadIdx.x, ty = threadIdx.y;
#pragma unroll
    for (int i = 0; i < 4; i++)
        t[ty + 8 * i][tx] = in[(size_t)(r0 + ty + 8 * i) * C + c0 + tx];
    __syncthreads();
#pragma unroll
    for (int i = 0; i < 4; i++)
        o[(size_t)(c0 + ty + 8 * i) * R + r0 + tx] = __float2half_rn(t[tx][ty + 8 * i]);
}

// ---------------------------------------------------------------------------
// fp16 2-term GEMM machinery: 128x128 tile, BK=64, 8 warps (2x4), 3 stages.
// A split (hi/lo), B single. Stage: Ah 0 | Al 18432 | B 36864 (pitch 144B).
// 3 stages x 55296 = 165888 B dynamic smem.
// ---------------------------------------------------------------------------
#define GSTG_H  55296u
#define GSMEM_H (3u * GSTG_H)

#define GEMM_PROLOGUE(AHP, ALP, BP) \
    uint32_t dstoff[12]; \
    const __half* srcrow[12]; \
    _Pragma("unroll") \
    for (int j = 0; j < 12; j++) { \
        int c   = tid + 256 * j; \
        int buf = c >> 10; \
        int idx = c & 1023; \
        int row = idx >> 3; \
        int kc  = idx & 7; \
        dstoff[j] = (uint32_t)buf * 18432u + (uint32_t)row * 144u + (uint32_t)kc * 16u; \
        const __half* base = \
            (buf == 0) ? (AHP) + (size_t)(m0 + row) * K : \
            (buf == 1) ? (ALP) + (size_t)(m0 + row) * K : \
                         (BP) + (size_t)row * K; \
        srcrow[j] = base + kc * 8; \
    }

#define ISSUE_STAGE(kt) do { \
        uint32_t stb = sb + (uint32_t)((kt) % 3) * GSTG_H; \
        const int kel = (kt) << 6; \
        _Pragma("unroll") \
        for (int j = 0; j < 12; j++) \
            CP_ASYNC16(stb + dstoff[j], srcrow[j] + kel); \
        CP_COMMIT(); \
    } while (0)

#define GEMM_MAIN_LOOP() \
    float acc[4][4][4]; \
    _Pragma("unroll") \
    for (int a = 0; a < 4; a++) \
        _Pragma("unroll") \
        for (int b2 = 0; b2 < 4; b2++) \
            _Pragma("unroll") \
            for (int d = 0; d < 4; d++) acc[a][b2][d] = 0.0f; \
    ISSUE_STAGE(0); \
    ISSUE_STAGE(1); \
    const uint32_t a_lrow = (uint32_t)(warp_m * 64 + (lane & 15)) * 144u + (uint32_t)(lane >> 4) * 16u; \
    const uint32_t b_lrow = (uint32_t)(warp_n * 32 + (lane & 15)) * 144u + (uint32_t)(lane >> 4) * 16u; \
    for (int kt = 0; kt < NT; kt++) { \
        if (kt + 2 < NT) { ISSUE_STAGE(kt + 2); CP_WAIT(2); } \
        else if (kt + 1 < NT) { CP_WAIT(1); } \
        else { CP_WAIT(0); } \
        __syncthreads(); \
        const uint32_t stb = sb + (uint32_t)(kt % 3) * GSTG_H; \
        _Pragma("unroll") \
        for (int k16 = 0; k16 < 4; k16++) { \
            const uint32_t koff = (uint32_t)k16 * 32u; \
            uint32_t ah[4][4], al[4][4]; \
            _Pragma("unroll") \
            for (int mt = 0; mt < 4; mt++) { \
                uint32_t addr = stb + a_lrow + (uint32_t)mt * (16u * 144u) + koff; \
                LDSM4(ah[mt][0], ah[mt][1], ah[mt][2], ah[mt][3], addr); \
                LDSM4(al[mt][0], al[mt][1], al[mt][2], al[mt][3], addr + 18432u); \
            } \
            uint32_t bh[2][4]; \
            _Pragma("unroll") \
            for (int bt = 0; bt < 2; bt++) { \
                uint32_t addr = stb + 36864u + b_lrow + (uint32_t)bt * (16u * 144u) + koff; \
                LDSM4(bh[bt][0], bh[bt][1], bh[bt][2], bh[bt][3], addr); \
            } \
            _Pragma("unroll") \
            for (int mt = 0; mt < 4; mt++) { \
                _Pragma("unroll") \
                for (int nt = 0; nt < 4; nt++) { \
                    const int bt = nt >> 1, hf = nt & 1; \
                    MMA16816(acc[mt][nt], ah[mt], bh[bt][hf], bh[bt][hf + 2]); \
                    MMA16816(acc[mt][nt], al[mt], bh[bt][hf], bh[bt][hf + 2]); \
                } \
            } \
        } \
    }

// gemm_mma: generic fp32 C output (used for wo projection)
__global__ __launch_bounds__(256, 1)
void gemm_mma(const __half* __restrict__ Ah, const __half* __restrict__ Al,
              const __half* __restrict__ B, float* __restrict__ C,
              int M, int N, int K)
{
    extern __shared__ char smc[];
    const uint32_t sb = smem_u32(smc);
    const int tid  = threadIdx.x;
    const int lane = tid & 31;
    const int wid  = tid >> 5;
    const int warp_m = wid >> 2;
    const int warp_n = wid & 3;
    const int m0 = blockIdx.y * 128;
    const int n0 = blockIdx.x * 128;
    const int NT = K >> 6;

    const __half* Bp = B + (size_t)n0 * K;
    GEMM_PROLOGUE(Ah, Al, Bp)
    GEMM_MAIN_LOOP()

#pragma unroll
    for (int mt = 0; mt < 4; mt++) {
        int row = m0 + warp_m * 64 + mt * 16 + (lane >> 2);
#pragma unroll
        for (int nt = 0; nt < 4; nt++) {
            int col = n0 + warp_n * 32 + nt * 8 + (lane & 3) * 2;
            *(float2*)(C + (size_t)row * N + col) =
                make_float2(acc[mt][nt][0], acc[mt][nt][1]);
            *(float2*)(C + (size_t)(row + 8) * N + col) =
                make_float2(acc[mt][nt][2], acc[mt][nt][3]);
        }
    }
}

// gemm_qkv: fused QKV projection with RoPE fused into the epilogue.
// Virtual N = 6144: cols 0..4095 -> Q (RoPE, fp16 hi/lo split to g_qh/g_ql),
// 4096..5119 -> K (RoPE, single fp16 to g_kf), 5120..6143 -> V (single fp16).
__global__ __launch_bounds__(256, 1)
void gemm_qkv(const float* __restrict__ fc, const float* __restrict__ fs)
{
    extern __shared__ char smc[];
    const uint32_t sb = smem_u32(smc);
    const int tid  = threadIdx.x;
    const int lane = tid & 31;
    const int wid  = tid >> 5;
    const int warp_m = wid >> 2;
    const int warp_n = wid & 3;
    const int m0 = blockIdx.y * 128;
    const int n0 = blockIdx.x * 128;
    const int K = DIM;
    const int NT = K >> 6;

    const __half* Bp;
    if (n0 < 4096)      Bp = g_wq + (size_t)n0 * K;
    else if (n0 < 5120) Bp = g_wk + (size_t)(n0 - 4096) * K;
    else                Bp = g_wv + (size_t)(n0 - 5120) * K;

    GEMM_PROLOGUE(g_ah, g_al, Bp)
    GEMM_MAIN_LOOP()

#pragma unroll
    for (int mt = 0; mt < 4; mt++) {
        int row = m0 + warp_m * 64 + mt * 16 + (lane >> 2);
        int s0 = row & (SEQ - 1);
        int s1 = (row + 8) & (SEQ - 1);
#pragma unroll
        for (int nt = 0; nt < 4; nt++) {
            int coll = warp_n * 32 + nt * 8 + (lane & 3) * 2;
            float v0 = acc[mt][nt][0], v1 = acc[mt][nt][1];
            float v2 = acc[mt][nt][2], v3 = acc[mt][nt][3];
            if (n0 < 5120) {
                // RoPE on (even, odd) pair
                int col = (n0 < 4096) ? (n0 + coll) : (n0 - 4096 + coll);
                int i = (col & (HD - 1)) >> 1;
                float c0 = fc[s0 * 64 + i], sn0 = fs[s0 * 64 + i];
                float c1 = fc[s1 * 64 + i], sn1 = fs[s1 * 64 + i];
                float ox0 = v0 * c0 - v1 * sn0, oy0 = v0 * sn0 + v1 * c0;
                float ox1 = v2 * c1 - v3 * sn1, oy1 = v2 * sn1 + v3 * c1;
                if (n0 < 4096) {
                    size_t o0 = ((size_t)row * QW + col) >> 1;
                    size_t o1 = ((size_t)(row + 8) * QW + col) >> 1;
                    ((uint32_t*)g_qh)[o0] = hsplit_hi(ox0, oy0);
                    ((uint32_t*)g_ql)[o0] = hsplit_lo(ox0, oy0);
                    ((uint32_t*)g_qh)[o1] = hsplit_hi(ox1, oy1);
                    ((uint32_t*)g_ql)[o1] = hsplit_lo(ox1, oy1);
                } else {
                    ((uint32_t*)g_kf)[((size_t)row * KW + col) >> 1] = hsplit_hi(ox0, oy0);
                    ((uint32_t*)g_kf)[((size_t)(row + 8) * KW + col) >> 1] = hsplit_hi(ox1, oy1);
                }
            } else {
                int col = n0 - 5120 + coll;
                ((uint32_t*)g_vf)[((size_t)row * KW + col) >> 1] = hsplit_hi(v0, v1);
                ((uint32_t*)g_vf)[((size_t)(row + 8) * KW + col) >> 1] = hsplit_hi(v2, v3);
            }
        }
    }
}

// ---------------------------------------------------------------------------
// flash_mma2: FA2-style causal attention, fp16 2-term (unchanged logic;
// Q from g_qh/g_ql, O written back in place).
// ---------------------------------------------------------------------------
#define FA4_SMEM 139264

__global__ __launch_bounds__(256, 1)
void flash_mma2()
{
    extern __shared__ char sm2[];
    const uint32_t sb = smem_u32(sm2);
    const int qb = blockIdx.x, h = blockIdx.y, b = blockIdx.z;
    const int kvh = h >> 2;
    const int tid = threadIdx.x, lane = tid & 31, w = tid >> 5;
    const float SC = 0.08838834764831845f;
    const uint32_t oQl = 34816u, oKV0 = 69632u, KVST = 34816u;

    {
        const size_t qrb = (size_t)(b * SEQ + qb * 128) * QW + h * HD;
#pragma unroll
        for (int j = 0; j < 16; j++) {
            int g = tid + 256 * j;
            int buf = g >> 11, idx = g & 2047;
            int row = idx >> 4, c16 = idx & 15;
            const __half* src = (buf ? g_ql : g_qh) + qrb + (size_t)row * QW + c16 * 8;
            CP_ASYNC16(sb + (uint32_t)buf * oQl + (uint32_t)row * 272u + (uint32_t)c16 * 16u, src);
        }
    }

#define ISSUE_KV(kb_) do { \
        const size_t rb_ = (size_t)(b * SEQ + (kb_) * 64) * KW + kvh * HD; \
        const uint32_t st_ = sb + oKV0 + (uint32_t)((kb_) & 1) * KVST; \
        _Pragma("unroll") \
        for (int j = 0; j < 8; j++) { \
            int g = tid + 256 * j; \
            int buf = g >> 10, idx = g & 1023; \
            int row = idx >> 4, c16 = idx & 15; \
            const __half* src = (buf ? g_vf : g_kf) + rb_ + (size_t)row * KW + c16 * 8; \
            CP_ASYNC16(st_ + (uint32_t)buf * 17408u + (uint32_t)row * 272u + (uint32_t)c16 * 16u, src); \
        } \
        CP_COMMIT(); \
    } while (0)

    ISSUE_KV(0);

    float acc_o[16][4];
#pragma unroll
    for (int n = 0; n < 16; n++)
#pragma unroll
        for (int d = 0; d < 4; d++) acc_o[n][d] = 0.0f;
    float mA = -CUDART_INF_F, mB = -CUDART_INF_F, lA = 0.0f, lB = 0.0f;

    const int growA = qb * 128 + w * 16 + (lane >> 2);
    const uint32_t qa  = sb + (uint32_t)(w * 16 + (lane & 15)) * 272u + (uint32_t)(lane >> 4) * 16u;
    const uint32_t lrw = (uint32_t)(lane & 15) * 272u + (uint32_t)(lane >> 4) * 16u;

    const int NT = 2 * qb + 2;
    for (int kb = 0; kb < NT; kb++) {
        CP_WAIT(0);
        __syncthreads();
        if (kb + 1 < NT) ISSUE_KV(kb + 1);

        if (kb * 64 > qb * 128 + w * 16 + 15) continue;

        const uint32_t kvst = sb + oKV0 + (uint32_t)(kb & 1) * KVST;
        const uint32_t kvb  = kvst + lrw;
        const uint32_t vvb  = kvst + 17408u + lrw;

        float accs[8][4];
#pragma unroll
        for (int n = 0; n < 8; n++)
#pragma unroll
            for (int d = 0; d < 4; d++) accs[n][d] = 0.0f;

#pragma unroll
        for (int k16 = 0; k16 < 8; k16++) {
            const uint32_t ko = (uint32_t)k16 * 32u;
            uint32_t qh[4], ql[4];
            LDSM4(qh[0], qh[1], qh[2], qh[3], qa + ko);
            LDSM4(ql[0], ql[1], ql[2], ql[3], qa + oQl + ko);
#pragma unroll
            for (int g4 = 0; g4 < 4; g4++) {
                uint32_t ka = kvb + (uint32_t)g4 * (16u * 272u) + ko;
                uint32_t kh[4];
                LDSM4(kh[0], kh[1], kh[2], kh[3], ka);
#pragma unroll
                for (int hf = 0; hf < 2; hf++) {
                    const int nt = g4 * 2 + hf;
                    MMA16816(accs[nt], qh, kh[hf], kh[hf + 2]);
                    MMA16816(accs[nt], ql, kh[hf], kh[hf + 2]);
                }
            }
        }

        const bool need_mask = (kb * 64 + 63 > qb * 128 + w * 16);
#pragma unroll
        for (int nt = 0; nt < 8; nt++) {
            int col = kb * 64 + nt * 8 + (lane & 3) * 2;
            float s0 = accs[nt][0] * SC, s1 = accs[nt][1] * SC;
            float s2 = accs[nt][2] * SC, s3 = accs[nt][3] * SC;
            if (need_mask) {
                if (col     > growA)     s0 = -1e9f;
                if (col + 1 > growA)     s1 = -1e9f;
                if (col     > growA + 8) s2 = -1e9f;
                if (col + 1 > growA + 8) s3 = -1e9f;
            }
            accs[nt][0] = s0; accs[nt][1] = s1; accs[nt][2] = s2; accs[nt][3] = s3;
        }

        float mrA = -CUDART_INF_F, mrB = -CUDART_INF_F;
#pragma unroll
        for (int nt = 0; nt < 8; nt++) {
            mrA = fmaxf(mrA, fmaxf(accs[nt][0], accs[nt][1]));
            mrB = fmaxf(mrB, fmaxf(accs[nt][2], accs[nt][3]));
        }
        mrA = fmaxf(mrA, __shfl_xor_sync(0xffffffffu, mrA, 1));
        mrA = fmaxf(mrA, __shfl_xor_sync(0xffffffffu, mrA, 2));
        mrB = fmaxf(mrB, __shfl_xor_sync(0xffffffffu, mrB, 1));
        mrB = fmaxf(mrB, __shfl_xor_sync(0xffffffffu, mrB, 2));
        float mnA = fmaxf(mA, mrA), mnB = fmaxf(mB, mrB);
        float corrA = __expf(mA - mnA), corrB = __expf(mB - mnB);
        mA = mnA; mB = mnB;

        float sumA = 0.0f, sumB = 0.0f;
#pragma unroll
        for (int nt = 0; nt < 8; nt++) {
            float p0 = __expf(accs[nt][0] - mnA);
            float p1 = __expf(accs[nt][1] - mnA);
            float p2 = __expf(accs[nt][2] - mnB);
            float p3 = __expf(accs[nt][3] - mnB);
            sumA += p0 + p1; sumB += p2 + p3;
            accs[nt][0] = p0; accs[nt][1] = p1; accs[nt][2] = p2; accs[nt][3] = p3;
        }
        sumA += __shfl_xor_sync(0xffffffffu, sumA, 1);
        sumA += __shfl_xor_sync(0xffffffffu, sumA, 2);
        sumB += __shfl_xor_sync(0xffffffffu, sumB, 1);
        sumB += __shfl_xor_sync(0xffffffffu, sumB, 2);
        lA = lA * corrA + sumA;
        lB = lB * corrB + sumB;

#pragma unroll
        for (int nt = 0; nt < 16; nt++) {
            acc_o[nt][0] *= corrA; acc_o[nt][1] *= corrA;
            acc_o[nt][2] *= corrB; acc_o[nt][3] *= corrB;
        }

#pragma unroll
        for (int kk = 0; kk < 4; kk++) {
            uint32_t aH[4], aL[4];
            aH[0] = hsplit_hi(accs[2*kk][0], accs[2*kk][1]);
            aH[1] = hsplit_hi(accs[2*kk][2], accs[2*kk][3]);
            aH[2] = hsplit_hi(accs[2*kk+1][0], accs[2*kk+1][1]);
            aH[3] = hsplit_hi(accs[2*kk+1][2], accs[2*kk+1][3]);
            aL[0] = hsplit_lo(accs[2*kk][0], accs[2*kk][1]);
            aL[1] = hsplit_lo(accs[2*kk][2], accs[2*kk][3]);
            aL[2] = hsplit_lo(accs[2*kk+1][0], accs[2*kk+1][1]);
            aL[3] = hsplit_lo(accs[2*kk+1][2], accs[2*kk+1][3]);
#pragma unroll
            for (int g = 0; g < 8; g++) {
                uint32_t va = vvb + (uint32_t)kk * (16u * 272u) + (uint32_t)g * 32u;
                uint32_t vh[4];
                LDSM4T(vh[0], vh[1], vh[2], vh[3], va);
                MMA16816(acc_o[2*g],   aH, vh[0], vh[1]);
                MMA16816(acc_o[2*g],   aL, vh[0], vh[1]);
                MMA16816(acc_o[2*g+1], aH, vh[2], vh[3]);
                MMA16816(acc_o[2*g+1], aL, vh[2], vh[3]);
            }
        }
    }

    {
        float invA = 1.0f / lA, invB = 1.0f / lB;
        uint32_t* oh32 = (uint32_t*)g_qh;
        uint32_t* ol32 = (uint32_t*)g_ql;
        size_t rowA = (size_t)(b * SEQ + qb * 128 + w * 16 + (lane >> 2));
#pragma unroll
        for (int nt = 0; nt < 16; nt++) {
            int col = h * HD + nt * 8 + (lane & 3) * 2;
            size_t o0 = (rowA * QW + col) >> 1;
            size_t o1 = ((rowA + 8) * QW + col) >> 1;
            float v0 = acc_o[nt][0] * invA, v1 = acc_o[nt][1] * invA;
            float v2 = acc_o[nt][2] * invB, v3 = acc_o[nt][3] * invB;
            oh32[o0] = hsplit_hi(v0, v1);
            ol32[o0] = hsplit_lo(v0, v1);
            oh32[o1] = hsplit_hi(v2, v3);
            ol32[o1] = hsplit_lo(v2, v3);
        }
    }
#undef ISSUE_KV
}

// ---------------------------------------------------------------------------
// Launch
// ---------------------------------------------------------------------------
extern "C" void kernel_launch(void* const* d_in, const int* in_sizes, int n_in,
                              void* d_out, int out_size)
{
    const float* x  = (const float*)d_in[0];
    const float* wq = (const float*)d_in[1];
    const float* wk = (const float*)d_in[2];
    const float* wv = (const float*)d_in[3];
    const float* wo = (const float*)d_in[4];
    const float* fc = (const float*)d_in[7];
    const float* fs = (const float*)d_in[8];
    float* out = (float*)d_out;

    __half *pah, *pal, *pqh, *pql, *pwq, *pwk, *pwv, *pwo;
    cudaGetSymbolAddress((void**)&pah, g_ah);
    cudaGetSymbolAddress((void**)&pal, g_al);
    cudaGetSymbolAddress((void**)&pqh, g_qh);
    cudaGetSymbolAddress((void**)&pql, g_ql);
    cudaGetSymbolAddress((void**)&pwq, g_wq);
    cudaGetSymbolAddress((void**)&pwk, g_wk);
    cudaGetSymbolAddress((void**)&pwv, g_wv);
    cudaGetSymbolAddress((void**)&pwo, g_wo);

    cudaFuncSetAttribute(gemm_mma, cudaFuncAttributeMaxDynamicSharedMemorySize, (int)GSMEM_H);
    cudaFuncSetAttribute(gemm_qkv, cudaFuncAttributeMaxDynamicSharedMemorySize, (int)GSMEM_H);
    cudaFuncSetAttribute(flash_mma2, cudaFuncAttributeMaxDynamicSharedMemorySize, FA4_SMEM);

    // split x, transpose weights (single fp16)
    convert_split<<<(MROWS * DIM / 4 + 255) / 256, 256>>>(x, pah, pal, MROWS * DIM / 4);
    transpose_half<<<dim3(QW / 32, DIM / 32), dim3(32, 8)>>>(wq, pwq, DIM, QW);
    transpose_half<<<dim3(KW / 32, DIM / 32), dim3(32, 8)>>>(wk, pwk, DIM, KW);
    transpose_half<<<dim3(KW / 32, DIM / 32), dim3(32, 8)>>>(wv, pwv, DIM, KW);
    transpose_half<<<dim3(DIM / 32, QW / 32), dim3(32, 8)>>>(wo, pwo, QW, DIM);

    // fused QKV projection + RoPE (Q split, K/V single fp16)
    gemm_qkv<<<dim3(6144 / 128, MROWS / 128), 256, GSMEM_H>>>(fc, fs);

    // flash attention (reads Q-split, writes O-split in place)
    flash_mma2<<<dim3(SEQ / 128, NH, BSZ), 256, FA4_SMEM>>>();

    // output projection
    gemm_mma<<<dim3(DIM / 128, MROWS / 128), 256, GSMEM_H>>>(pqh, pql, pwo, out, MROWS, DIM, DIM);
}

// round 10
// speedup vs baseline: 4.8811x; 1.3243x over previous
#include <cuda_runtime.h>
#include <cuda_fp16.h>
#include <math_constants.h>
#include <cstdint>

#define BSZ   2
#define SEQ   2048
#define DIM   4096
#define NH    32
#define NKV   8
#define HD    128
#define MROWS (BSZ*SEQ)   /* 4096 */
#define QW    (NH*HD)     /* 4096 */
#define KW    (NKV*HD)    /* 1024 */

// ---------------------------------------------------------------------------
// Static device scratch
// ---------------------------------------------------------------------------
__device__ __half g_xf[(size_t)MROWS * DIM];  // x single fp16 (QKV A operand)
__device__ __half g_qh[(size_t)MROWS * QW];   // Q-split hi (post-RoPE) -> O-split hi
__device__ __half g_ql[(size_t)MROWS * QW];   // Q-split lo -> O-split lo
__device__ __half g_kf[(size_t)MROWS * KW];   // K post-RoPE, single fp16
__device__ __half g_vf[(size_t)MROWS * KW];   // V, single fp16
__device__ __half g_wq[(size_t)QW * DIM];     // transposed weights, single fp16
__device__ __half g_wk[(size_t)KW * DIM];
__device__ __half g_wv[(size_t)KW * DIM];
__device__ __half g_wo[(size_t)DIM * QW];

// ---------------------------------------------------------------------------
// PTX helpers
// ---------------------------------------------------------------------------
__device__ __forceinline__ uint32_t smem_u32(const void* p) {
    uint32_t a;
    asm("{ .reg .u64 t; cvta.to.shared.u64 t, %1; cvt.u32.u64 %0, t; }" : "=r"(a) : "l"(p));
    return a;
}
#define CP_ASYNC16(dst, src) \
    asm volatile("cp.async.cg.shared.global [%0], [%1], 16;" :: "r"(dst), "l"(src))
#define CP_COMMIT() asm volatile("cp.async.commit_group;" ::: "memory")
#define CP_WAIT(n)  asm volatile("cp.async.wait_group %0;" :: "n"(n) : "memory")

#define LDSM4(R0, R1, R2, R3, addr) \
    asm volatile("ldmatrix.sync.aligned.m8n8.x4.shared.b16 {%0,%1,%2,%3}, [%4];" \
        : "=r"(R0), "=r"(R1), "=r"(R2), "=r"(R3) : "r"(addr))
#define LDSM4T(R0, R1, R2, R3, addr) \
    asm volatile("ldmatrix.sync.aligned.m8n8.x4.trans.shared.b16 {%0,%1,%2,%3}, [%4];" \
        : "=r"(R0), "=r"(R1), "=r"(R2), "=r"(R3) : "r"(addr))

#define MMA16816(D, A, B0, B1) \
    asm volatile("mma.sync.aligned.m16n8k16.row.col.f32.f16.f16.f32 " \
        "{%0,%1,%2,%3},{%4,%5,%6,%7},{%8,%9},{%0,%1,%2,%3};" \
        : "+f"((D)[0]), "+f"((D)[1]), "+f"((D)[2]), "+f"((D)[3]) \
        : "r"((A)[0]), "r"((A)[1]), "r"((A)[2]), "r"((A)[3]), "r"(B0), "r"(B1))

__device__ __forceinline__ uint32_t pack_h(__half a, __half b) {
    union { __half h[2]; uint32_t u; } t;
    t.h[0] = a; t.h[1] = b;
    return t.u;
}
__device__ __forceinline__ uint32_t hsplit_hi(float a, float b) {
    return pack_h(__float2half_rn(a), __float2half_rn(b));
}
__device__ __forceinline__ uint32_t hsplit_lo(float a, float b) {
    __half ha = __float2half_rn(a), hb = __float2half_rn(b);
    return pack_h(__float2half_rn(a - __half2float(ha)),
                  __float2half_rn(b - __half2float(hb)));
}

// ---------------------------------------------------------------------------
// convert_half: fp32 -> fp16 single
// ---------------------------------------------------------------------------
__global__ void convert_half(const float* __restrict__ in,
                             __half* __restrict__ o, int n4)
{
    int i = blockIdx.x * blockDim.x + threadIdx.x;
    if (i >= n4) return;
    float4 v = ((const float4*)in)[i];
    uint2 H;
    H.x = hsplit_hi(v.x, v.y); H.y = hsplit_hi(v.z, v.w);
    ((uint2*)o)[i] = H;
}

// ---------------------------------------------------------------------------
// transpose_half: fp32 [R,C] -> fp16 [C,R] single
// ---------------------------------------------------------------------------
__global__ void transpose_half(const float* __restrict__ in,
                               __half* __restrict__ o, int R, int C)
{
    __shared__ float t[32][33];
    int c0 = blockIdx.x * 32, r0 = blockIdx.y * 32;
    int tx = threadIdx.x, ty = threadIdx.y;
#pragma unroll
    for (int i = 0; i < 4; i++)
        t[ty + 8 * i][tx] = in[(size_t)(r0 + ty + 8 * i) * C + c0 + tx];
    __syncthreads();
#pragma unroll
    for (int i = 0; i < 4; i++)
        o[(size_t)(c0 + ty + 8 * i) * R + r0 + tx] = __float2half_rn(t[tx][ty + 8 * i]);
}

// ===========================================================================
// 1-term GEMM machinery (A single, B single). 128x128, BK=64, 3 stages.
// Stage: A 0..18431 | B 18432..36863 (pitch 144B). Used by gemm_qkv.
// RACE-FIXED pipeline: issue of stage kt+2 happens AFTER the barrier, so no
// warp can overwrite ring slot (kt-1)%3 while another still reads it.
// ===========================================================================
#define G1STG  36864u
#define G1SMEM (3u * G1STG)

#define GEMM1_PROLOGUE(AP, BP) \
    uint32_t dstoff[8]; \
    const __half* srcrow[8]; \
    _Pragma("unroll") \
    for (int j = 0; j < 8; j++) { \
        int c   = tid + 256 * j; \
        int buf = c >> 10; \
        int idx = c & 1023; \
        int row = idx >> 3; \
        int kc  = idx & 7; \
        dstoff[j] = (uint32_t)buf * 18432u + (uint32_t)row * 144u + (uint32_t)kc * 16u; \
        const __half* base = \
            (buf == 0) ? (AP) + (size_t)(m0 + row) * K : \
                         (BP) + (size_t)row * K; \
        srcrow[j] = base + kc * 8; \
    }

#define ISSUE1(kt) do { \
        uint32_t stb = sb + (uint32_t)((kt) % 3) * G1STG; \
        const int kel = (kt) << 6; \
        _Pragma("unroll") \
        for (int j = 0; j < 8; j++) \
            CP_ASYNC16(stb + dstoff[j], srcrow[j] + kel); \
        CP_COMMIT(); \
    } while (0)

#define GEMM1_LOOP() \
    float acc[4][4][4]; \
    _Pragma("unroll") \
    for (int a = 0; a < 4; a++) \
        _Pragma("unroll") \
        for (int b2 = 0; b2 < 4; b2++) \
            _Pragma("unroll") \
            for (int d = 0; d < 4; d++) acc[a][b2][d] = 0.0f; \
    ISSUE1(0); \
    ISSUE1(1); \
    const uint32_t a_lrow = (uint32_t)(warp_m * 64 + (lane & 15)) * 144u + (uint32_t)(lane >> 4) * 16u; \
    const uint32_t b_lrow = (uint32_t)(warp_n * 32 + (lane & 15)) * 144u + (uint32_t)(lane >> 4) * 16u; \
    for (int kt = 0; kt < NT; kt++) { \
        if (kt + 1 < NT) { CP_WAIT(1); } else { CP_WAIT(0); } \
        __syncthreads(); \
        if (kt + 2 < NT) ISSUE1(kt + 2); \
        const uint32_t stb = sb + (uint32_t)(kt % 3) * G1STG; \
        _Pragma("unroll") \
        for (int k16 = 0; k16 < 4; k16++) { \
            const uint32_t koff = (uint32_t)k16 * 32u; \
            uint32_t ah[4][4]; \
            _Pragma("unroll") \
            for (int mt = 0; mt < 4; mt++) { \
                uint32_t addr = stb + a_lrow + (uint32_t)mt * (16u * 144u) + koff; \
                LDSM4(ah[mt][0], ah[mt][1], ah[mt][2], ah[mt][3], addr); \
            } \
            uint32_t bh[2][4]; \
            _Pragma("unroll") \
            for (int bt = 0; bt < 2; bt++) { \
                uint32_t addr = stb + 18432u + b_lrow + (uint32_t)bt * (16u * 144u) + koff; \
                LDSM4(bh[bt][0], bh[bt][1], bh[bt][2], bh[bt][3], addr); \
            } \
            _Pragma("unroll") \
            for (int mt = 0; mt < 4; mt++) { \
                _Pragma("unroll") \
                for (int nt = 0; nt < 4; nt++) { \
                    const int bt = nt >> 1, hf = nt & 1; \
                    MMA16816(acc[mt][nt], ah[mt], bh[bt][hf], bh[bt][hf + 2]); \
                } \
            } \
        } \
    }

// gemm_qkv: fused QKV projection (A = x single fp16) with RoPE epilogue.
// Virtual N = 6144: cols 0..4095 -> Q (RoPE, split to g_qh/g_ql),
// 4096..5119 -> K (RoPE, single to g_kf), 5120..6143 -> V (single to g_vf).
__global__ __launch_bounds__(256, 1)
void gemm_qkv(const float* __restrict__ fc, const float* __restrict__ fs)
{
    extern __shared__ char smc[];
    const uint32_t sb = smem_u32(smc);
    const int tid  = threadIdx.x;
    const int lane = tid & 31;
    const int wid  = tid >> 5;
    const int warp_m = wid >> 2;
    const int warp_n = wid & 3;
    const int m0 = blockIdx.y * 128;
    const int n0 = blockIdx.x * 128;
    const int K = DIM;
    const int NT = K >> 6;

    const __half* Bp;
    if (n0 < 4096)      Bp = g_wq + (size_t)n0 * K;
    else if (n0 < 5120) Bp = g_wk + (size_t)(n0 - 4096) * K;
    else                Bp = g_wv + (size_t)(n0 - 5120) * K;

    GEMM1_PROLOGUE(g_xf, Bp)
    GEMM1_LOOP()

#pragma unroll
    for (int mt = 0; mt < 4; mt++) {
        int row = m0 + warp_m * 64 + mt * 16 + (lane >> 2);
        int s0 = row & (SEQ - 1);
        int s1 = (row + 8) & (SEQ - 1);
#pragma unroll
        for (int nt = 0; nt < 4; nt++) {
            int coll = warp_n * 32 + nt * 8 + (lane & 3) * 2;
            float v0 = acc[mt][nt][0], v1 = acc[mt][nt][1];
            float v2 = acc[mt][nt][2], v3 = acc[mt][nt][3];
            if (n0 < 5120) {
                int col = (n0 < 4096) ? (n0 + coll) : (n0 - 4096 + coll);
                int i = (col & (HD - 1)) >> 1;
                float c0 = fc[s0 * 64 + i], sn0 = fs[s0 * 64 + i];
                float c1 = fc[s1 * 64 + i], sn1 = fs[s1 * 64 + i];
                float ox0 = v0 * c0 - v1 * sn0, oy0 = v0 * sn0 + v1 * c0;
                float ox1 = v2 * c1 - v3 * sn1, oy1 = v2 * sn1 + v3 * c1;
                if (n0 < 4096) {
                    size_t o0 = ((size_t)row * QW + col) >> 1;
                    size_t o1 = ((size_t)(row + 8) * QW + col) >> 1;
                    ((uint32_t*)g_qh)[o0] = hsplit_hi(ox0, oy0);
                    ((uint32_t*)g_ql)[o0] = hsplit_lo(ox0, oy0);
                    ((uint32_t*)g_qh)[o1] = hsplit_hi(ox1, oy1);
                    ((uint32_t*)g_ql)[o1] = hsplit_lo(ox1, oy1);
                } else {
                    ((uint32_t*)g_kf)[((size_t)row * KW + col) >> 1] = hsplit_hi(ox0, oy0);
                    ((uint32_t*)g_kf)[((size_t)(row + 8) * KW + col) >> 1] = hsplit_hi(ox1, oy1);
                }
            } else {
                int col = n0 - 5120 + coll;
                ((uint32_t*)g_vf)[((size_t)row * KW + col) >> 1] = hsplit_hi(v0, v1);
                ((uint32_t*)g_vf)[((size_t)(row + 8) * KW + col) >> 1] = hsplit_hi(v2, v3);
            }
        }
    }
}

// ===========================================================================
// 2-term GEMM machinery (A split hi/lo, B single) — RACE-FIXED. Used by WO.
// Stage: Ah 0 | Al 18432 | B 36864 (pitch 144B). 3 x 55296 = 165888 B smem.
// ===========================================================================
#define G2STG  55296u
#define G2SMEM (3u * G2STG)

__global__ __launch_bounds__(256, 1)
void gemm_mma(const __half* __restrict__ Ah, const __half* __restrict__ Al,
              const __half* __restrict__ B, float* __restrict__ C,
              int M, int N, int K)
{
    extern __shared__ char smc[];
    const uint32_t sb = smem_u32(smc);
    const int tid  = threadIdx.x;
    const int lane = tid & 31;
    const int wid  = tid >> 5;
    const int warp_m = wid >> 2;
    const int warp_n = wid & 3;
    const int m0 = blockIdx.y * 128;
    const int n0 = blockIdx.x * 128;
    const int NT = K >> 6;

    uint32_t dstoff[12];
    const __half* srcrow[12];
#pragma unroll
    for (int j = 0; j < 12; j++) {
        int c   = tid + 256 * j;
        int buf = c >> 10;
        int idx = c & 1023;
        int row = idx >> 3;
        int kc  = idx & 7;
        dstoff[j] = (uint32_t)buf * 18432u + (uint32_t)row * 144u + (uint32_t)kc * 16u;
        const __half* base =
            (buf == 0) ? Ah + (size_t)(m0 + row) * K :
            (buf == 1) ? Al + (size_t)(m0 + row) * K :
                         B + (size_t)(n0 + row) * K;
        srcrow[j] = base + kc * 8;
    }

#define ISSUE2(kt) do { \
        uint32_t stb = sb + (uint32_t)((kt) % 3) * G2STG; \
        const int kel = (kt) << 6; \
        _Pragma("unroll") \
        for (int j = 0; j < 12; j++) \
            CP_ASYNC16(stb + dstoff[j], srcrow[j] + kel); \
        CP_COMMIT(); \
    } while (0)

    float acc[4][4][4];
#pragma unroll
    for (int a = 0; a < 4; a++)
#pragma unroll
        for (int b2 = 0; b2 < 4; b2++)
#pragma unroll
            for (int d = 0; d < 4; d++) acc[a][b2][d] = 0.0f;

    ISSUE2(0);
    ISSUE2(1);

    const uint32_t a_lrow = (uint32_t)(warp_m * 64 + (lane & 15)) * 144u + (uint32_t)(lane >> 4) * 16u;
    const uint32_t b_lrow = (uint32_t)(warp_n * 32 + (lane & 15)) * 144u + (uint32_t)(lane >> 4) * 16u;

    for (int kt = 0; kt < NT; kt++) {
        if (kt + 1 < NT) { CP_WAIT(1); } else { CP_WAIT(0); }
        __syncthreads();
        if (kt + 2 < NT) ISSUE2(kt + 2);

        const uint32_t stb = sb + (uint32_t)(kt % 3) * G2STG;
#pragma unroll
        for (int k16 = 0; k16 < 4; k16++) {
            const uint32_t koff = (uint32_t)k16 * 32u;
            uint32_t ah[4][4], al[4][4];
#pragma unroll
            for (int mt = 0; mt < 4; mt++) {
                uint32_t addr = stb + a_lrow + (uint32_t)mt * (16u * 144u) + koff;
                LDSM4(ah[mt][0], ah[mt][1], ah[mt][2], ah[mt][3], addr);
                LDSM4(al[mt][0], al[mt][1], al[mt][2], al[mt][3], addr + 18432u);
            }
            uint32_t bh[2][4];
#pragma unroll
            for (int bt = 0; bt < 2; bt++) {
                uint32_t addr = stb + 36864u + b_lrow + (uint32_t)bt * (16u * 144u) + koff;
                LDSM4(bh[bt][0], bh[bt][1], bh[bt][2], bh[bt][3], addr);
            }
#pragma unroll
            for (int mt = 0; mt < 4; mt++) {
#pragma unroll
                for (int nt = 0; nt < 4; nt++) {
                    const int bt = nt >> 1, hf = nt & 1;
                    MMA16816(acc[mt][nt], ah[mt], bh[bt][hf], bh[bt][hf + 2]);
                    MMA16816(acc[mt][nt], al[mt], bh[bt][hf], bh[bt][hf + 2]);
                }
            }
        }
    }

#pragma unroll
    for (int mt = 0; mt < 4; mt++) {
        int row = m0 + warp_m * 64 + mt * 16 + (lane >> 2);
#pragma unroll
        for (int nt = 0; nt < 4; nt++) {
            int col = n0 + warp_n * 32 + nt * 8 + (lane & 3) * 2;
            *(float2*)(C + (size_t)row * N + col) =
                make_float2(acc[mt][nt][0], acc[mt][nt][1]);
            *(float2*)(C + (size_t)(row + 8) * N + col) =
                make_float2(acc[mt][nt][2], acc[mt][nt][3]);
        }
    }
#undef ISSUE2
}

// ---------------------------------------------------------------------------
// flash_mma2: FA2-style causal attention — R7 EXACT (already race-safe:
// KV issue happens after the barrier). Q split in, O split out in place.
// ---------------------------------------------------------------------------
#define FA4_SMEM 139264

__global__ __launch_bounds__(256, 1)
void flash_mma2()
{
    extern __shared__ char sm2[];
    const uint32_t sb = smem_u32(sm2);
    const int qb = blockIdx.x, h = blockIdx.y, b = blockIdx.z;
    const int kvh = h >> 2;
    const int tid = threadIdx.x, lane = tid & 31, w = tid >> 5;
    const float SC = 0.08838834764831845f;
    const uint32_t oQl = 34816u, oKV0 = 69632u, KVST = 34816u;

    {
        const size_t qrb = (size_t)(b * SEQ + qb * 128) * QW + h * HD;
#pragma unroll
        for (int j = 0; j < 16; j++) {
            int g = tid + 256 * j;
            int buf = g >> 11, idx = g & 2047;
            int row = idx >> 4, c16 = idx & 15;
            const __half* src = (buf ? g_ql : g_qh) + qrb + (size_t)row * QW + c16 * 8;
            CP_ASYNC16(sb + (uint32_t)buf * oQl + (uint32_t)row * 272u + (uint32_t)c16 * 16u, src);
        }
    }

#define ISSUE_KV(kb_) do { \
        const size_t rb_ = (size_t)(b * SEQ + (kb_) * 64) * KW + kvh * HD; \
        const uint32_t st_ = sb + oKV0 + (uint32_t)((kb_) & 1) * KVST; \
        _Pragma("unroll") \
        for (int j = 0; j < 8; j++) { \
            int g = tid + 256 * j; \
            int buf = g >> 10, idx = g & 1023; \
            int row = idx >> 4, c16 = idx & 15; \
            const __half* src = (buf ? g_vf : g_kf) + rb_ + (size_t)row * KW + c16 * 8; \
            CP_ASYNC16(st_ + (uint32_t)buf * 17408u + (uint32_t)row * 272u + (uint32_t)c16 * 16u, src); \
        } \
        CP_COMMIT(); \
    } while (0)

    ISSUE_KV(0);

    float acc_o[16][4];
#pragma unroll
    for (int n = 0; n < 16; n++)
#pragma unroll
        for (int d = 0; d < 4; d++) acc_o[n][d] = 0.0f;
    float mA = -CUDART_INF_F, mB = -CUDART_INF_F, lA = 0.0f, lB = 0.0f;

    const int growA = qb * 128 + w * 16 + (lane >> 2);
    const uint32_t qa  = sb + (uint32_t)(w * 16 + (lane & 15)) * 272u + (uint32_t)(lane >> 4) * 16u;
    const uint32_t lrw = (uint32_t)(lane & 15) * 272u + (uint32_t)(lane >> 4) * 16u;

    const int NT = 2 * qb + 2;
    for (int kb = 0; kb < NT; kb++) {
        CP_WAIT(0);
        __syncthreads();
        if (kb + 1 < NT) ISSUE_KV(kb + 1);

        if (kb * 64 > qb * 128 + w * 16 + 15) continue;

        const uint32_t kvst = sb + oKV0 + (uint32_t)(kb & 1) * KVST;
        const uint32_t kvb  = kvst + lrw;
        const uint32_t vvb  = kvst + 17408u + lrw;

        float accs[8][4];
#pragma unroll
        for (int n = 0; n < 8; n++)
#pragma unroll
            for (int d = 0; d < 4; d++) accs[n][d] = 0.0f;

#pragma unroll
        for (int k16 = 0; k16 < 8; k16++) {
            const uint32_t ko = (uint32_t)k16 * 32u;
            uint32_t qh[4], ql[4];
            LDSM4(qh[0], qh[1], qh[2], qh[3], qa + ko);
            LDSM4(ql[0], ql[1], ql[2], ql[3], qa + oQl + ko);
#pragma unroll
            for (int g4 = 0; g4 < 4; g4++) {
                uint32_t ka = kvb + (uint32_t)g4 * (16u * 272u) + ko;
                uint32_t kh[4];
                LDSM4(kh[0], kh[1], kh[2], kh[3], ka);
#pragma unroll
                for (int hf = 0; hf < 2; hf++) {
                    const int nt = g4 * 2 + hf;
                    MMA16816(accs[nt], qh, kh[hf], kh[hf + 2]);
                    MMA16816(accs[nt], ql, kh[hf], kh[hf + 2]);
                }
            }
        }

        const bool need_mask = (kb * 64 + 63 > qb * 128 + w * 16);
#pragma unroll
        for (int nt = 0; nt < 8; nt++) {
            int col = kb * 64 + nt * 8 + (lane & 3) * 2;
            float s0 = accs[nt][0] * SC, s1 = accs[nt][1] * SC;
            float s2 = accs[nt][2] * SC, s3 = accs[nt][3] * SC;
            if (need_mask) {
                if (col     > growA)     s0 = -1e9f;
                if (col + 1 > growA)     s1 = -1e9f;
                if (col     > growA + 8) s2 = -1e9f;
                if (col + 1 > growA + 8) s3 = -1e9f;
            }
            accs[nt][0] = s0; accs[nt][1] = s1; accs[nt][2] = s2; accs[nt][3] = s3;
        }

        float mrA = -CUDART_INF_F, mrB = -CUDART_INF_F;
#pragma unroll
        for (int nt = 0; nt < 8; nt++) {
            mrA = fmaxf(mrA, fmaxf(accs[nt][0], accs[nt][1]));
            mrB = fmaxf(mrB, fmaxf(accs[nt][2], accs[nt][3]));
        }
        mrA = fmaxf(mrA, __shfl_xor_sync(0xffffffffu, mrA, 1));
        mrA = fmaxf(mrA, __shfl_xor_sync(0xffffffffu, mrA, 2));
        mrB = fmaxf(mrB, __shfl_xor_sync(0xffffffffu, mrB, 1));
        mrB = fmaxf(mrB, __shfl_xor_sync(0xffffffffu, mrB, 2));
        float mnA = fmaxf(mA, mrA), mnB = fmaxf(mB, mrB);
        float corrA = __expf(mA - mnA), corrB = __expf(mB - mnB);
        mA = mnA; mB = mnB;

        float sumA = 0.0f, sumB = 0.0f;
#pragma unroll
        for (int nt = 0; nt < 8; nt++) {
            float p0 = __expf(accs[nt][0] - mnA);
            float p1 = __expf(accs[nt][1] - mnA);
            float p2 = __expf(accs[nt][2] - mnB);
            float p3 = __expf(accs[nt][3] - mnB);
            sumA += p0 + p1; sumB += p2 + p3;
            accs[nt][0] = p0; accs[nt][1] = p1; accs[nt][2] = p2; accs[nt][3] = p3;
        }
        sumA += __shfl_xor_sync(0xffffffffu, sumA, 1);
        sumA += __shfl_xor_sync(0xffffffffu, sumA, 2);
        sumB += __shfl_xor_sync(0xffffffffu, sumB, 1);
        sumB += __shfl_xor_sync(0xffffffffu, sumB, 2);
        lA = lA * corrA + sumA;
        lB = lB * corrB + sumB;

#pragma unroll
        for (int nt = 0; nt < 16; nt++) {
            acc_o[nt][0] *= corrA; acc_o[nt][1] *= corrA;
            acc_o[nt][2] *= corrB; acc_o[nt][3] *= corrB;
        }

#pragma unroll
        for (int kk = 0; kk < 4; kk++) {
            uint32_t aH[4], aL[4];
            aH[0] = hsplit_hi(accs[2*kk][0], accs[2*kk][1]);
            aH[1] = hsplit_hi(accs[2*kk][2], accs[2*kk][3]);
            aH[2] = hsplit_hi(accs[2*kk+1][0], accs[2*kk+1][1]);
            aH[3] = hsplit_hi(accs[2*kk+1][2], accs[2*kk+1][3]);
            aL[0] = hsplit_lo(accs[2*kk][0], accs[2*kk][1]);
            aL[1] = hsplit_lo(accs[2*kk][2], accs[2*kk][3]);
            aL[2] = hsplit_lo(accs[2*kk+1][0], accs[2*kk+1][1]);
            aL[3] = hsplit_lo(accs[2*kk+1][2], accs[2*kk+1][3]);
#pragma unroll
            for (int g = 0; g < 8; g++) {
                uint32_t va = vvb + (uint32_t)kk * (16u * 272u) + (uint32_t)g * 32u;
                uint32_t vh[4];
                LDSM4T(vh[0], vh[1], vh[2], vh[3], va);
                MMA16816(acc_o[2*g],   aH, vh[0], vh[1]);
                MMA16816(acc_o[2*g],   aL, vh[0], vh[1]);
                MMA16816(acc_o[2*g+1], aH, vh[2], vh[3]);
                MMA16816(acc_o[2*g+1], aL, vh[2], vh[3]);
            }
        }
    }

    // ---- epilogue: O/l -> fp16 hi/lo split in place into g_qh/g_ql ----
    {
        float invA = 1.0f / lA, invB = 1.0f / lB;
        uint32_t* oh32 = (uint32_t*)g_qh;
        uint32_t* ol32 = (uint32_t*)g_ql;
        size_t rowA = (size_t)(b * SEQ + qb * 128 + w * 16 + (lane >> 2));
#pragma unroll
        for (int nt = 0; nt < 16; nt++) {
            int col = h * HD + nt * 8 + (lane & 3) * 2;
            size_t o0 = (rowA * QW + col) >> 1;
            size_t o1 = ((rowA + 8) * QW + col) >> 1;
            float v0 = acc_o[nt][0] * invA, v1 = acc_o[nt][1] * invA;
            float v2 = acc_o[nt][2] * invB, v3 = acc_o[nt][3] * invB;
            oh32[o0] = hsplit_hi(v0, v1);
            ol32[o0] = hsplit_lo(v0, v1);
            oh32[o1] = hsplit_hi(v2, v3);
            ol32[o1] = hsplit_lo(v2, v3);
        }
    }
#undef ISSUE_KV
}

// ---------------------------------------------------------------------------
// Launch
// ---------------------------------------------------------------------------
extern "C" void kernel_launch(void* const* d_in, const int* in_sizes, int n_in,
                              void* d_out, int out_size)
{
    const float* x  = (const float*)d_in[0];
    const float* wq = (const float*)d_in[1];
    const float* wk = (const float*)d_in[2];
    const float* wv = (const float*)d_in[3];
    const float* wo = (const float*)d_in[4];
    const float* fc = (const float*)d_in[7];
    const float* fs = (const float*)d_in[8];
    float* out = (float*)d_out;

    __half *pxf, *pqh, *pql, *pwq, *pwk, *pwv, *pwo;
    cudaGetSymbolAddress((void**)&pxf, g_xf);
    cudaGetSymbolAddress((void**)&pqh, g_qh);
    cudaGetSymbolAddress((void**)&pql, g_ql);
    cudaGetSymbolAddress((void**)&pwq, g_wq);
    cudaGetSymbolAddress((void**)&pwk, g_wk);
    cudaGetSymbolAddress((void**)&pwv, g_wv);
    cudaGetSymbolAddress((void**)&pwo, g_wo);

    cudaFuncSetAttribute(gemm_qkv, cudaFuncAttributeMaxDynamicSharedMemorySize, (int)G1SMEM);
    cudaFuncSetAttribute(gemm_mma, cudaFuncAttributeMaxDynamicSharedMemorySize, (int)G2SMEM);
    cudaFuncSetAttribute(flash_mma2, cudaFuncAttributeMaxDynamicSharedMemorySize, FA4_SMEM);

    // convert x to single fp16, transpose weights (single fp16)
    convert_half<<<(MROWS * DIM / 4 + 255) / 256, 256>>>(x, pxf, MROWS * DIM / 4);
    transpose_half<<<dim3(QW / 32, DIM / 32), dim3(32, 8)>>>(wq, pwq, DIM, QW);
    transpose_half<<<dim3(KW / 32, DIM / 32), dim3(32, 8)>>>(wk, pwk, DIM, KW);
    transpose_half<<<dim3(KW / 32, DIM / 32), dim3(32, 8)>>>(wv, pwv, DIM, KW);
    transpose_half<<<dim3(DIM / 32, QW / 32), dim3(32, 8)>>>(wo, pwo, QW, DIM);

    // fused QKV projection (x single) + RoPE epilogue
    gemm_qkv<<<dim3(6144 / 128, MROWS / 128), 256, G1SMEM>>>(fc, fs);

    // flash attention (Q split in, O split out in place)
    flash_mma2<<<dim3(SEQ / 128, NH, BSZ), 256, FA4_SMEM>>>();

    // output projection: 2-term (O split)
    gemm_mma<<<dim3(DIM / 128, MROWS / 128), 256, G2SMEM>>>(pqh, pql, pwo, out, MROWS, DIM, DIM);
}

// round 11
// speedup vs baseline: 5.6593x; 1.1594x over previous
#include <cuda_runtime.h>
#include <cuda_fp16.h>
#include <math_constants.h>
#include <cstdint>

#define BSZ   2
#define SEQ   2048
#define DIM   4096
#define NH    32
#define NKV   8
#define HD    128
#define MROWS (BSZ*SEQ)   /* 4096 */
#define QW    (NH*HD)     /* 4096 */
#define KW    (NKV*HD)    /* 1024 */

// ---------------------------------------------------------------------------
// Static device scratch
// ---------------------------------------------------------------------------
__device__ __half g_xf[(size_t)MROWS * DIM];  // x single fp16 -> later O single fp16
__device__ __half g_qh[(size_t)MROWS * QW];   // Q-split hi (post-RoPE)
__device__ __half g_ql[(size_t)MROWS * QW];   // Q-split lo
__device__ __half g_kf[(size_t)MROWS * KW];   // K post-RoPE, single fp16
__device__ __half g_vf[(size_t)MROWS * KW];   // V, single fp16
__device__ __half g_wq[(size_t)QW * DIM];     // transposed weights, single fp16
__device__ __half g_wk[(size_t)KW * DIM];
__device__ __half g_wv[(size_t)KW * DIM];
__device__ __half g_wo[(size_t)DIM * QW];

// ---------------------------------------------------------------------------
// PTX helpers
// ---------------------------------------------------------------------------
__device__ __forceinline__ uint32_t smem_u32(const void* p) {
    uint32_t a;
    asm("{ .reg .u64 t; cvta.to.shared.u64 t, %1; cvt.u32.u64 %0, t; }" : "=r"(a) : "l"(p));
    return a;
}
#define CP_ASYNC16(dst, src) \
    asm volatile("cp.async.cg.shared.global [%0], [%1], 16;" :: "r"(dst), "l"(src))
#define CP_COMMIT() asm volatile("cp.async.commit_group;" ::: "memory")
#define CP_WAIT(n)  asm volatile("cp.async.wait_group %0;" :: "n"(n) : "memory")

#define LDSM4(R0, R1, R2, R3, addr) \
    asm volatile("ldmatrix.sync.aligned.m8n8.x4.shared.b16 {%0,%1,%2,%3}, [%4];" \
        : "=r"(R0), "=r"(R1), "=r"(R2), "=r"(R3) : "r"(addr))
#define LDSM4T(R0, R1, R2, R3, addr) \
    asm volatile("ldmatrix.sync.aligned.m8n8.x4.trans.shared.b16 {%0,%1,%2,%3}, [%4];" \
        : "=r"(R0), "=r"(R1), "=r"(R2), "=r"(R3) : "r"(addr))

#define MMA16816(D, A, B0, B1) \
    asm volatile("mma.sync.aligned.m16n8k16.row.col.f32.f16.f16.f32 " \
        "{%0,%1,%2,%3},{%4,%5,%6,%7},{%8,%9},{%0,%1,%2,%3};" \
        : "+f"((D)[0]), "+f"((D)[1]), "+f"((D)[2]), "+f"((D)[3]) \
        : "r"((A)[0]), "r"((A)[1]), "r"((A)[2]), "r"((A)[3]), "r"(B0), "r"(B1))

__device__ __forceinline__ uint32_t pack_h(__half a, __half b) {
    union { __half h[2]; uint32_t u; } t;
    t.h[0] = a; t.h[1] = b;
    return t.u;
}
__device__ __forceinline__ uint32_t hsplit_hi(float a, float b) {
    return pack_h(__float2half_rn(a), __float2half_rn(b));
}
__device__ __forceinline__ uint32_t hsplit_lo(float a, float b) {
    __half ha = __float2half_rn(a), hb = __float2half_rn(b);
    return pack_h(__float2half_rn(a - __half2float(ha)),
                  __float2half_rn(b - __half2float(hb)));
}

// ---------------------------------------------------------------------------
// convert_half: fp32 -> fp16 single
// ---------------------------------------------------------------------------
__global__ void convert_half(const float* __restrict__ in,
                             __half* __restrict__ o, int n4)
{
    int i = blockIdx.x * blockDim.x + threadIdx.x;
    if (i >= n4) return;
    float4 v = ((const float4*)in)[i];
    uint2 H;
    H.x = hsplit_hi(v.x, v.y); H.y = hsplit_hi(v.z, v.w);
    ((uint2*)o)[i] = H;
}

// ---------------------------------------------------------------------------
// transpose_half: fp32 [R,C] -> fp16 [C,R] single
// ---------------------------------------------------------------------------
__global__ void transpose_half(const float* __restrict__ in,
                               __half* __restrict__ o, int R, int C)
{
    __shared__ float t[32][33];
    int c0 = blockIdx.x * 32, r0 = blockIdx.y * 32;
    int tx = threadIdx.x, ty = threadIdx.y;
#pragma unroll
    for (int i = 0; i < 4; i++)
        t[ty + 8 * i][tx] = in[(size_t)(r0 + ty + 8 * i) * C + c0 + tx];
    __syncthreads();
#pragma unroll
    for (int i = 0; i < 4; i++)
        o[(size_t)(c0 + ty + 8 * i) * R + r0 + tx] = __float2half_rn(t[tx][ty + 8 * i]);
}

// ===========================================================================
// 1-term GEMM machinery (A single, B single). 128x128, BK=64, 4 stages.
// Stage: A 0..18431 | B 18432..36863 (pitch 144B). 4 x 36864 = 147456 B smem.
// Race-safe: stage kt+3 (ring slot (kt-1)%4) is issued AFTER the barrier at
// iteration kt, by which point every warp has finished reading slot kt-1.
// ===========================================================================
#define G1STG  36864u
#define G1SMEM (4u * G1STG)

#define GEMM1_PROLOGUE(AP, BP) \
    uint32_t dstoff[8]; \
    const __half* srcrow[8]; \
    _Pragma("unroll") \
    for (int j = 0; j < 8; j++) { \
        int c   = tid + 256 * j; \
        int buf = c >> 10; \
        int idx = c & 1023; \
        int row = idx >> 3; \
        int kc  = idx & 7; \
        dstoff[j] = (uint32_t)buf * 18432u + (uint32_t)row * 144u + (uint32_t)kc * 16u; \
        const __half* base = \
            (buf == 0) ? (AP) + (size_t)(m0 + row) * K : \
                         (BP) + (size_t)row * K; \
        srcrow[j] = base + kc * 8; \
    }

#define ISSUE1(kt) do { \
        uint32_t stb = sb + (uint32_t)((kt) & 3) * G1STG; \
        const int kel = (kt) << 6; \
        _Pragma("unroll") \
        for (int j = 0; j < 8; j++) \
            CP_ASYNC16(stb + dstoff[j], srcrow[j] + kel); \
        CP_COMMIT(); \
    } while (0)

#define GEMM1_LOOP() \
    float acc[4][4][4]; \
    _Pragma("unroll") \
    for (int a = 0; a < 4; a++) \
        _Pragma("unroll") \
        for (int b2 = 0; b2 < 4; b2++) \
            _Pragma("unroll") \
            for (int d = 0; d < 4; d++) acc[a][b2][d] = 0.0f; \
    ISSUE1(0); \
    ISSUE1(1); \
    ISSUE1(2); \
    const uint32_t a_lrow = (uint32_t)(warp_m * 64 + (lane & 15)) * 144u + (uint32_t)(lane >> 4) * 16u; \
    const uint32_t b_lrow = (uint32_t)(warp_n * 32 + (lane & 15)) * 144u + (uint32_t)(lane >> 4) * 16u; \
    for (int kt = 0; kt < NT; kt++) { \
        if (kt + 2 < NT)      { CP_WAIT(2); } \
        else if (kt + 1 < NT) { CP_WAIT(1); } \
        else                  { CP_WAIT(0); } \
        __syncthreads(); \
        if (kt + 3 < NT) ISSUE1(kt + 3); \
        const uint32_t stb = sb + (uint32_t)(kt & 3) * G1STG; \
        _Pragma("unroll") \
        for (int k16 = 0; k16 < 4; k16++) { \
            const uint32_t koff = (uint32_t)k16 * 32u; \
            uint32_t ah[4][4]; \
            _Pragma("unroll") \
            for (int mt = 0; mt < 4; mt++) { \
                uint32_t addr = stb + a_lrow + (uint32_t)mt * (16u * 144u) + koff; \
                LDSM4(ah[mt][0], ah[mt][1], ah[mt][2], ah[mt][3], addr); \
            } \
            uint32_t bh[2][4]; \
            _Pragma("unroll") \
            for (int bt = 0; bt < 2; bt++) { \
                uint32_t addr = stb + 18432u + b_lrow + (uint32_t)bt * (16u * 144u) + koff; \
                LDSM4(bh[bt][0], bh[bt][1], bh[bt][2], bh[bt][3], addr); \
            } \
            _Pragma("unroll") \
            for (int mt = 0; mt < 4; mt++) { \
                _Pragma("unroll") \
                for (int nt = 0; nt < 4; nt++) { \
                    const int bt = nt >> 1, hf = nt & 1; \
                    MMA16816(acc[mt][nt], ah[mt], bh[bt][hf], bh[bt][hf + 2]); \
                } \
            } \
        } \
    }

// gemm_qkv: fused QKV projection (A = x single fp16) with RoPE epilogue.
// Virtual N = 6144: cols 0..4095 -> Q (RoPE, split to g_qh/g_ql),
// 4096..5119 -> K (RoPE, single to g_kf), 5120..6143 -> V (single to g_vf).
__global__ __launch_bounds__(256, 1)
void gemm_qkv(const float* __restrict__ fc, const float* __restrict__ fs)
{
    extern __shared__ char smc[];
    const uint32_t sb = smem_u32(smc);
    const int tid  = threadIdx.x;
    const int lane = tid & 31;
    const int wid  = tid >> 5;
    const int warp_m = wid >> 2;
    const int warp_n = wid & 3;
    const int m0 = blockIdx.y * 128;
    const int n0 = blockIdx.x * 128;
    const int K = DIM;
    const int NT = K >> 6;

    const __half* Bp;
    if (n0 < 4096)      Bp = g_wq + (size_t)n0 * K;
    else if (n0 < 5120) Bp = g_wk + (size_t)(n0 - 4096) * K;
    else                Bp = g_wv + (size_t)(n0 - 5120) * K;

    GEMM1_PROLOGUE(g_xf, Bp)
    GEMM1_LOOP()

#pragma unroll
    for (int mt = 0; mt < 4; mt++) {
        int row = m0 + warp_m * 64 + mt * 16 + (lane >> 2);
        int s0 = row & (SEQ - 1);
        int s1 = (row + 8) & (SEQ - 1);
#pragma unroll
        for (int nt = 0; nt < 4; nt++) {
            int coll = warp_n * 32 + nt * 8 + (lane & 3) * 2;
            float v0 = acc[mt][nt][0], v1 = acc[mt][nt][1];
            float v2 = acc[mt][nt][2], v3 = acc[mt][nt][3];
            if (n0 < 5120) {
                int col = (n0 < 4096) ? (n0 + coll) : (n0 - 4096 + coll);
                int i = (col & (HD - 1)) >> 1;
                float c0 = fc[s0 * 64 + i], sn0 = fs[s0 * 64 + i];
                float c1 = fc[s1 * 64 + i], sn1 = fs[s1 * 64 + i];
                float ox0 = v0 * c0 - v1 * sn0, oy0 = v0 * sn0 + v1 * c0;
                float ox1 = v2 * c1 - v3 * sn1, oy1 = v2 * sn1 + v3 * c1;
                if (n0 < 4096) {
                    size_t o0 = ((size_t)row * QW + col) >> 1;
                    size_t o1 = ((size_t)(row + 8) * QW + col) >> 1;
                    ((uint32_t*)g_qh)[o0] = hsplit_hi(ox0, oy0);
                    ((uint32_t*)g_ql)[o0] = hsplit_lo(ox0, oy0);
                    ((uint32_t*)g_qh)[o1] = hsplit_hi(ox1, oy1);
                    ((uint32_t*)g_ql)[o1] = hsplit_lo(ox1, oy1);
                } else {
                    ((uint32_t*)g_kf)[((size_t)row * KW + col) >> 1] = hsplit_hi(ox0, oy0);
                    ((uint32_t*)g_kf)[((size_t)(row + 8) * KW + col) >> 1] = hsplit_hi(ox1, oy1);
                }
            } else {
                int col = n0 - 5120 + coll;
                ((uint32_t*)g_vf)[((size_t)row * KW + col) >> 1] = hsplit_hi(v0, v1);
                ((uint32_t*)g_vf)[((size_t)(row + 8) * KW + col) >> 1] = hsplit_hi(v2, v3);
            }
        }
    }
}

// gemm_wo: output projection, 1-term (A = O single fp16 in g_xf), fp32 C out.
__global__ __launch_bounds__(256, 1)
void gemm_wo(float* __restrict__ C)
{
    extern __shared__ char smc[];
    const uint32_t sb = smem_u32(smc);
    const int tid  = threadIdx.x;
    const int lane = tid & 31;
    const int wid  = tid >> 5;
    const int warp_m = wid >> 2;
    const int warp_n = wid & 3;
    const int m0 = blockIdx.y * 128;
    const int n0 = blockIdx.x * 128;
    const int K = QW;
    const int NT = K >> 6;
    const int N = DIM;

    const __half* Bp = g_wo + (size_t)n0 * K;
    GEMM1_PROLOGUE(g_xf, Bp)
    GEMM1_LOOP()

#pragma unroll
    for (int mt = 0; mt < 4; mt++) {
        int row = m0 + warp_m * 64 + mt * 16 + (lane >> 2);
#pragma unroll
        for (int nt = 0; nt < 4; nt++) {
            int col = n0 + warp_n * 32 + nt * 8 + (lane & 3) * 2;
            *(float2*)(C + (size_t)row * N + col) =
                make_float2(acc[mt][nt][0], acc[mt][nt][1]);
            *(float2*)(C + (size_t)(row + 8) * N + col) =
                make_float2(acc[mt][nt][2], acc[mt][nt][3]);
        }
    }
}

// ---------------------------------------------------------------------------
// flash_mma2: FA2-style causal attention (Q split, K/V single, P split).
// O written as single fp16 into g_xf (x is dead after the QKV gemm).
// ---------------------------------------------------------------------------
#define FA4_SMEM 139264

__global__ __launch_bounds__(256, 1)
void flash_mma2()
{
    extern __shared__ char sm2[];
    const uint32_t sb = smem_u32(sm2);
    const int qb = blockIdx.x, h = blockIdx.y, b = blockIdx.z;
    const int kvh = h >> 2;
    const int tid = threadIdx.x, lane = tid & 31, w = tid >> 5;
    const float SC = 0.08838834764831845f;
    const uint32_t oQl = 34816u, oKV0 = 69632u, KVST = 34816u;

    {
        const size_t qrb = (size_t)(b * SEQ + qb * 128) * QW + h * HD;
#pragma unroll
        for (int j = 0; j < 16; j++) {
            int g = tid + 256 * j;
            int buf = g >> 11, idx = g & 2047;
            int row = idx >> 4, c16 = idx & 15;
            const __half* src = (buf ? g_ql : g_qh) + qrb + (size_t)row * QW + c16 * 8;
            CP_ASYNC16(sb + (uint32_t)buf * oQl + (uint32_t)row * 272u + (uint32_t)c16 * 16u, src);
        }
    }

#define ISSUE_KV(kb_) do { \
        const size_t rb_ = (size_t)(b * SEQ + (kb_) * 64) * KW + kvh * HD; \
        const uint32_t st_ = sb + oKV0 + (uint32_t)((kb_) & 1) * KVST; \
        _Pragma("unroll") \
        for (int j = 0; j < 8; j++) { \
            int g = tid + 256 * j; \
            int buf = g >> 10, idx = g & 1023; \
            int row = idx >> 4, c16 = idx & 15; \
            const __half* src = (buf ? g_vf : g_kf) + rb_ + (size_t)row * KW + c16 * 8; \
            CP_ASYNC16(st_ + (uint32_t)buf * 17408u + (uint32_t)row * 272u + (uint32_t)c16 * 16u, src); \
        } \
        CP_COMMIT(); \
    } while (0)

    ISSUE_KV(0);

    float acc_o[16][4];
#pragma unroll
    for (int n = 0; n < 16; n++)
#pragma unroll
        for (int d = 0; d < 4; d++) acc_o[n][d] = 0.0f;
    float mA = -CUDART_INF_F, mB = -CUDART_INF_F, lA = 0.0f, lB = 0.0f;

    const int growA = qb * 128 + w * 16 + (lane >> 2);
    const uint32_t qa  = sb + (uint32_t)(w * 16 + (lane & 15)) * 272u + (uint32_t)(lane >> 4) * 16u;
    const uint32_t lrw = (uint32_t)(lane & 15) * 272u + (uint32_t)(lane >> 4) * 16u;

    const int NT = 2 * qb + 2;
    for (int kb = 0; kb < NT; kb++) {
        CP_WAIT(0);
        __syncthreads();
        if (kb + 1 < NT) ISSUE_KV(kb + 1);

        if (kb * 64 > qb * 128 + w * 16 + 15) continue;

        const uint32_t kvst = sb + oKV0 + (uint32_t)(kb & 1) * KVST;
        const uint32_t kvb  = kvst + lrw;
        const uint32_t vvb  = kvst + 17408u + lrw;

        float accs[8][4];
#pragma unroll
        for (int n = 0; n < 8; n++)
#pragma unroll
            for (int d = 0; d < 4; d++) accs[n][d] = 0.0f;

#pragma unroll
        for (int k16 = 0; k16 < 8; k16++) {
            const uint32_t ko = (uint32_t)k16 * 32u;
            uint32_t qh[4], ql[4];
            LDSM4(qh[0], qh[1], qh[2], qh[3], qa + ko);
            LDSM4(ql[0], ql[1], ql[2], ql[3], qa + oQl + ko);
#pragma unroll
            for (int g4 = 0; g4 < 4; g4++) {
                uint32_t ka = kvb + (uint32_t)g4 * (16u * 272u) + ko;
                uint32_t kh[4];
                LDSM4(kh[0], kh[1], kh[2], kh[3], ka);
#pragma unroll
                for (int hf = 0; hf < 2; hf++) {
                    const int nt = g4 * 2 + hf;
                    MMA16816(accs[nt], qh, kh[hf], kh[hf + 2]);
                    MMA16816(accs[nt], ql, kh[hf], kh[hf + 2]);
                }
            }
        }

        const bool need_mask = (kb * 64 + 63 > qb * 128 + w * 16);
#pragma unroll
        for (int nt = 0; nt < 8; nt++) {
            int col = kb * 64 + nt * 8 + (lane & 3) * 2;
            float s0 = accs[nt][0] * SC, s1 = accs[nt][1] * SC;
            float s2 = accs[nt][2] * SC, s3 = accs[nt][3] * SC;
            if (need_mask) {
                if (col     > growA)     s0 = -1e9f;
                if (col + 1 > growA)     s1 = -1e9f;
                if (col     > growA + 8) s2 = -1e9f;
                if (col + 1 > growA + 8) s3 = -1e9f;
            }
            accs[nt][0] = s0; accs[nt][1] = s1; accs[nt][2] = s2; accs[nt][3] = s3;
        }

        float mrA = -CUDART_INF_F, mrB = -CUDART_INF_F;
#pragma unroll
        for (int nt = 0; nt < 8; nt++) {
            mrA = fmaxf(mrA, fmaxf(accs[nt][0], accs[nt][1]));
            mrB = fmaxf(mrB, fmaxf(accs[nt][2], accs[nt][3]));
        }
        mrA = fmaxf(mrA, __shfl_xor_sync(0xffffffffu, mrA, 1));
        mrA = fmaxf(mrA, __shfl_xor_sync(0xffffffffu, mrA, 2));
        mrB = fmaxf(mrB, __shfl_xor_sync(0xffffffffu, mrB, 1));
        mrB = fmaxf(mrB, __shfl_xor_sync(0xffffffffu, mrB, 2));
        float mnA = fmaxf(mA, mrA), mnB = fmaxf(mB, mrB);
        float corrA = __expf(mA - mnA), corrB = __expf(mB - mnB);
        mA = mnA; mB = mnB;

        float sumA = 0.0f, sumB = 0.0f;
#pragma unroll
        for (int nt = 0; nt < 8; nt++) {
            float p0 = __expf(accs[nt][0] - mnA);
            float p1 = __expf(accs[nt][1] - mnA);
            float p2 = __expf(accs[nt][2] - mnB);
            float p3 = __expf(accs[nt][3] - mnB);
            sumA += p0 + p1; sumB += p2 + p3;
            accs[nt][0] = p0; accs[nt][1] = p1; accs[nt][2] = p2; accs[nt][3] = p3;
        }
        sumA += __shfl_xor_sync(0xffffffffu, sumA, 1);
        sumA += __shfl_xor_sync(0xffffffffu, sumA, 2);
        sumB += __shfl_xor_sync(0xffffffffu, sumB, 1);
        sumB += __shfl_xor_sync(0xffffffffu, sumB, 2);
        lA = lA * corrA + sumA;
        lB = lB * corrB + sumB;

#pragma unroll
        for (int nt = 0; nt < 16; nt++) {
            acc_o[nt][0] *= corrA; acc_o[nt][1] *= corrA;
            acc_o[nt][2] *= corrB; acc_o[nt][3] *= corrB;
        }

#pragma unroll
        for (int kk = 0; kk < 4; kk++) {
            uint32_t aH[4], aL[4];
            aH[0] = hsplit_hi(accs[2*kk][0], accs[2*kk][1]);
            aH[1] = hsplit_hi(accs[2*kk][2], accs[2*kk][3]);
            aH[2] = hsplit_hi(accs[2*kk+1][0], accs[2*kk+1][1]);
            aH[3] = hsplit_hi(accs[2*kk+1][2], accs[2*kk+1][3]);
            aL[0] = hsplit_lo(accs[2*kk][0], accs[2*kk][1]);
            aL[1] = hsplit_lo(accs[2*kk][2], accs[2*kk][3]);
            aL[2] = hsplit_lo(accs[2*kk+1][0], accs[2*kk+1][1]);
            aL[3] = hsplit_lo(accs[2*kk+1][2], accs[2*kk+1][3]);
#pragma unroll
            for (int g = 0; g < 8; g++) {
                uint32_t va = vvb + (uint32_t)kk * (16u * 272u) + (uint32_t)g * 32u;
                uint32_t vh[4];
                LDSM4T(vh[0], vh[1], vh[2], vh[3], va);
                MMA16816(acc_o[2*g],   aH, vh[0], vh[1]);
                MMA16816(acc_o[2*g],   aL, vh[0], vh[1]);
                MMA16816(acc_o[2*g+1], aH, vh[2], vh[3]);
                MMA16816(acc_o[2*g+1], aL, vh[2], vh[3]);
            }
        }
    }

    // ---- epilogue: O/l -> single fp16 into g_xf ----
    {
        float invA = 1.0f / lA, invB = 1.0f / lB;
        uint32_t* of32 = (uint32_t*)g_xf;
        size_t rowA = (size_t)(b * SEQ + qb * 128 + w * 16 + (lane >> 2));
#pragma unroll
        for (int nt = 0; nt < 16; nt++) {
            int col = h * HD + nt * 8 + (lane & 3) * 2;
            of32[(rowA * QW + col) >> 1] =
                hsplit_hi(acc_o[nt][0] * invA, acc_o[nt][1] * invA);
            of32[((rowA + 8) * QW + col) >> 1] =
                hsplit_hi(acc_o[nt][2] * invB, acc_o[nt][3] * invB);
        }
    }
#undef ISSUE_KV
}

// ---------------------------------------------------------------------------
// Launch
// ---------------------------------------------------------------------------
extern "C" void kernel_launch(void* const* d_in, const int* in_sizes, int n_in,
                              void* d_out, int out_size)
{
    const float* x  = (const float*)d_in[0];
    const float* wq = (const float*)d_in[1];
    const float* wk = (const float*)d_in[2];
    const float* wv = (const float*)d_in[3];
    const float* wo = (const float*)d_in[4];
    const float* fc = (const float*)d_in[7];
    const float* fs = (const float*)d_in[8];
    float* out = (float*)d_out;

    __half *pxf, *pwq, *pwk, *pwv, *pwo;
    cudaGetSymbolAddress((void**)&pxf, g_xf);
    cudaGetSymbolAddress((void**)&pwq, g_wq);
    cudaGetSymbolAddress((void**)&pwk, g_wk);
    cudaGetSymbolAddress((void**)&pwv, g_wv);
    cudaGetSymbolAddress((void**)&pwo, g_wo);

    cudaFuncSetAttribute(gemm_qkv, cudaFuncAttributeMaxDynamicSharedMemorySize, (int)G1SMEM);
    cudaFuncSetAttribute(gemm_wo, cudaFuncAttributeMaxDynamicSharedMemorySize, (int)G1SMEM);
    cudaFuncSetAttribute(flash_mma2, cudaFuncAttributeMaxDynamicSharedMemorySize, FA4_SMEM);

    // convert x to single fp16, transpose weights (single fp16)
    convert_half<<<(MROWS * DIM / 4 + 255) / 256, 256>>>(x, pxf, MROWS * DIM / 4);
    transpose_half<<<dim3(QW / 32, DIM / 32), dim3(32, 8)>>>(wq, pwq, DIM, QW);
    transpose_half<<<dim3(KW / 32, DIM / 32), dim3(32, 8)>>>(wk, pwk, DIM, KW);
    transpose_half<<<dim3(KW / 32, DIM / 32), dim3(32, 8)>>>(wv, pwv, DIM, KW);
    transpose_half<<<dim3(DIM / 32, QW / 32), dim3(32, 8)>>>(wo, pwo, QW, DIM);

    // fused QKV projection (x single) + RoPE epilogue
    gemm_qkv<<<dim3(6144 / 128, MROWS / 128), 256, G1SMEM>>>(fc, fs);

    // flash attention (Q split in; O single fp16 out into g_xf)
    flash_mma2<<<dim3(SEQ / 128, NH, BSZ), 256, FA4_SMEM>>>();

    // output projection (single x single)
    gemm_wo<<<dim3(DIM / 128, MROWS / 128), 256, G1SMEM>>>(out);
}

// round 12
// speedup vs baseline: 5.8768x; 1.0384x over previous
#include <cuda_runtime.h>
#include <cuda_fp16.h>
#include <math_constants.h>
#include <cstdint>

#define BSZ   2
#define SEQ   2048
#define DIM   4096
#define NH    32
#define NKV   8
#define HD    128
#define MROWS (BSZ*SEQ)   /* 4096 */
#define QW    (NH*HD)     /* 4096 */
#define KW    (NKV*HD)    /* 1024 */

// ---------------------------------------------------------------------------
// Static device scratch
// ---------------------------------------------------------------------------
__device__ __half g_xf[(size_t)MROWS * DIM];  // x single fp16 -> later O single fp16
__device__ __half g_qh[(size_t)MROWS * QW];   // Q-split hi (post-RoPE)
__device__ __half g_ql[(size_t)MROWS * QW];   // Q-split lo
__device__ __half g_kf[(size_t)MROWS * KW];   // K post-RoPE, single fp16
__device__ __half g_vf[(size_t)MROWS * KW];   // V, single fp16
__device__ __half g_wq[(size_t)QW * DIM];     // transposed weights, single fp16
__device__ __half g_wk[(size_t)KW * DIM];
__device__ __half g_wv[(size_t)KW * DIM];
__device__ __half g_wo[(size_t)DIM * QW];

// ---------------------------------------------------------------------------
// PTX helpers
// ---------------------------------------------------------------------------
__device__ __forceinline__ uint32_t smem_u32(const void* p) {
    uint32_t a;
    asm("{ .reg .u64 t; cvta.to.shared.u64 t, %1; cvt.u32.u64 %0, t; }" : "=r"(a) : "l"(p));
    return a;
}
#define CP_ASYNC16(dst, src) \
    asm volatile("cp.async.cg.shared.global [%0], [%1], 16;" :: "r"(dst), "l"(src))
#define CP_COMMIT() asm volatile("cp.async.commit_group;" ::: "memory")
#define CP_WAIT(n)  asm volatile("cp.async.wait_group %0;" :: "n"(n) : "memory")

#define LDSM4(R0, R1, R2, R3, addr) \
    asm volatile("ldmatrix.sync.aligned.m8n8.x4.shared.b16 {%0,%1,%2,%3}, [%4];" \
        : "=r"(R0), "=r"(R1), "=r"(R2), "=r"(R3) : "r"(addr))
#define LDSM4T(R0, R1, R2, R3, addr) \
    asm volatile("ldmatrix.sync.aligned.m8n8.x4.trans.shared.b16 {%0,%1,%2,%3}, [%4];" \
        : "=r"(R0), "=r"(R1), "=r"(R2), "=r"(R3) : "r"(addr))

#define MMA16816(D, A, B0, B1) \
    asm volatile("mma.sync.aligned.m16n8k16.row.col.f32.f16.f16.f32 " \
        "{%0,%1,%2,%3},{%4,%5,%6,%7},{%8,%9},{%0,%1,%2,%3};" \
        : "+f"((D)[0]), "+f"((D)[1]), "+f"((D)[2]), "+f"((D)[3]) \
        : "r"((A)[0]), "r"((A)[1]), "r"((A)[2]), "r"((A)[3]), "r"(B0), "r"(B1))

__device__ __forceinline__ uint32_t pack_h(__half a, __half b) {
    union { __half h[2]; uint32_t u; } t;
    t.h[0] = a; t.h[1] = b;
    return t.u;
}
__device__ __forceinline__ uint32_t hsplit_hi(float a, float b) {
    return pack_h(__float2half_rn(a), __float2half_rn(b));
}
__device__ __forceinline__ uint32_t hsplit_lo(float a, float b) {
    __half ha = __float2half_rn(a), hb = __float2half_rn(b);
    return pack_h(__float2half_rn(a - __half2float(ha)),
                  __float2half_rn(b - __half2float(hb)));
}

// ---------------------------------------------------------------------------
// convert_half: fp32 -> fp16 single
// ---------------------------------------------------------------------------
__global__ void convert_half(const float* __restrict__ in,
                             __half* __restrict__ o, int n4)
{
    int i = blockIdx.x * blockDim.x + threadIdx.x;
    if (i >= n4) return;
    float4 v = ((const float4*)in)[i];
    uint2 H;
    H.x = hsplit_hi(v.x, v.y); H.y = hsplit_hi(v.z, v.w);
    ((uint2*)o)[i] = H;
}

// ---------------------------------------------------------------------------
// transpose_half: fp32 [R,C] -> fp16 [C,R] single
// ---------------------------------------------------------------------------
__global__ void transpose_half(const float* __restrict__ in,
                               __half* __restrict__ o, int R, int C)
{
    __shared__ float t[32][33];
    int c0 = blockIdx.x * 32, r0 = blockIdx.y * 32;
    int tx = threadIdx.x, ty = threadIdx.y;
#pragma unroll
    for (int i = 0; i < 4; i++)
        t[ty + 8 * i][tx] = in[(size_t)(r0 + ty + 8 * i) * C + c0 + tx];
    __syncthreads();
#pragma unroll
    for (int i = 0; i < 4; i++)
        o[(size_t)(c0 + ty + 8 * i) * R + r0 + tx] = __float2half_rn(t[tx][ty + 8 * i]);
}

// ===========================================================================
// 1-term GEMM machinery (A single, B single). 256x128 block tile, BK=64,
// 512 threads = 16 warps (4m x 4n), warp tile 64x32, 4 stages.
// Stage: A 0..36863 (256 rows x 144B) | B 36864..55295 (128 rows x 144B).
// 4 x 55296 = 221184 B smem. 16 warps -> 4 warps/SMSP for latency hiding.
// Race-safe: stage kt+3 (ring slot (kt-1)%4) issued AFTER the barrier.
// ===========================================================================
#define G1STG  55296u
#define G1SMEM (4u * G1STG)

#define GEMM1_PROLOGUE(AP, BP) \
    uint32_t dstoff[6]; \
    const __half* srcrow[6]; \
    _Pragma("unroll") \
    for (int j = 0; j < 6; j++) { \
        int c   = tid + 512 * j;          /* 0..3071 */ \
        int bufB = (c >= 2048); \
        int idx = bufB ? (c - 2048) : c; \
        int row = idx >> 3; \
        int kc  = idx & 7; \
        dstoff[j] = (uint32_t)bufB * 36864u + (uint32_t)row * 144u + (uint32_t)kc * 16u; \
        const __half* base = bufB ? (BP) + (size_t)row * K \
                                  : (AP) + (size_t)(m0 + row) * K; \
        srcrow[j] = base + kc * 8; \
    }

#define ISSUE1(kt) do { \
        uint32_t stb = sb + (uint32_t)((kt) & 3) * G1STG; \
        const int kel = (kt) << 6; \
        _Pragma("unroll") \
        for (int j = 0; j < 6; j++) \
            CP_ASYNC16(stb + dstoff[j], srcrow[j] + kel); \
        CP_COMMIT(); \
    } while (0)

#define GEMM1_LOOP() \
    float acc[4][4][4]; \
    _Pragma("unroll") \
    for (int a = 0; a < 4; a++) \
        _Pragma("unroll") \
        for (int b2 = 0; b2 < 4; b2++) \
            _Pragma("unroll") \
            for (int d = 0; d < 4; d++) acc[a][b2][d] = 0.0f; \
    ISSUE1(0); \
    ISSUE1(1); \
    ISSUE1(2); \
    const uint32_t a_lrow = (uint32_t)(warp_m * 64 + (lane & 15)) * 144u + (uint32_t)(lane >> 4) * 16u; \
    const uint32_t b_lrow = 36864u + (uint32_t)(warp_n * 32 + (lane & 15)) * 144u + (uint32_t)(lane >> 4) * 16u; \
    for (int kt = 0; kt < NT; kt++) { \
        if (kt + 2 < NT)      { CP_WAIT(2); } \
        else if (kt + 1 < NT) { CP_WAIT(1); } \
        else                  { CP_WAIT(0); } \
        __syncthreads(); \
        if (kt + 3 < NT) ISSUE1(kt + 3); \
        const uint32_t stb = sb + (uint32_t)(kt & 3) * G1STG; \
        _Pragma("unroll") \
        for (int k16 = 0; k16 < 4; k16++) { \
            const uint32_t koff = (uint32_t)k16 * 32u; \
            uint32_t ah[4][4]; \
            _Pragma("unroll") \
            for (int mt = 0; mt < 4; mt++) { \
                uint32_t addr = stb + a_lrow + (uint32_t)mt * (16u * 144u) + koff; \
                LDSM4(ah[mt][0], ah[mt][1], ah[mt][2], ah[mt][3], addr); \
            } \
            uint32_t bh[2][4]; \
            _Pragma("unroll") \
            for (int bt = 0; bt < 2; bt++) { \
                uint32_t addr = stb + b_lrow + (uint32_t)bt * (16u * 144u) + koff; \
                LDSM4(bh[bt][0], bh[bt][1], bh[bt][2], bh[bt][3], addr); \
            } \
            _Pragma("unroll") \
            for (int mt = 0; mt < 4; mt++) { \
                _Pragma("unroll") \
                for (int nt = 0; nt < 4; nt++) { \
                    const int bt = nt >> 1, hf = nt & 1; \
                    MMA16816(acc[mt][nt], ah[mt], bh[bt][hf], bh[bt][hf + 2]); \
                } \
            } \
        } \
    }

// gemm_qkv: fused QKV projection (A = x single fp16) with RoPE epilogue.
// Virtual N = 6144: cols 0..4095 -> Q (RoPE, split to g_qh/g_ql),
// 4096..5119 -> K (RoPE, single to g_kf), 5120..6143 -> V (single to g_vf).
__global__ __launch_bounds__(512, 1)
void gemm_qkv(const float* __restrict__ fc, const float* __restrict__ fs)
{
    extern __shared__ char smc[];
    const uint32_t sb = smem_u32(smc);
    const int tid  = threadIdx.x;
    const int lane = tid & 31;
    const int wid  = tid >> 5;
    const int warp_m = wid >> 2;     // 0..3
    const int warp_n = wid & 3;      // 0..3
    const int m0 = blockIdx.y * 256;
    const int n0 = blockIdx.x * 128;
    const int K = DIM;
    const int NT = K >> 6;

    const __half* Bp;
    if (n0 < 4096)      Bp = g_wq + (size_t)n0 * K;
    else if (n0 < 5120) Bp = g_wk + (size_t)(n0 - 4096) * K;
    else                Bp = g_wv + (size_t)(n0 - 5120) * K;

    GEMM1_PROLOGUE(g_xf, Bp)
    GEMM1_LOOP()

#pragma unroll
    for (int mt = 0; mt < 4; mt++) {
        int row = m0 + warp_m * 64 + mt * 16 + (lane >> 2);
        int s0 = row & (SEQ - 1);
        int s1 = (row + 8) & (SEQ - 1);
#pragma unroll
        for (int nt = 0; nt < 4; nt++) {
            int coll = warp_n * 32 + nt * 8 + (lane & 3) * 2;
            float v0 = acc[mt][nt][0], v1 = acc[mt][nt][1];
            float v2 = acc[mt][nt][2], v3 = acc[mt][nt][3];
            if (n0 < 5120) {
                int col = (n0 < 4096) ? (n0 + coll) : (n0 - 4096 + coll);
                int i = (col & (HD - 1)) >> 1;
                float c0 = fc[s0 * 64 + i], sn0 = fs[s0 * 64 + i];
                float c1 = fc[s1 * 64 + i], sn1 = fs[s1 * 64 + i];
                float ox0 = v0 * c0 - v1 * sn0, oy0 = v0 * sn0 + v1 * c0;
                float ox1 = v2 * c1 - v3 * sn1, oy1 = v2 * sn1 + v3 * c1;
                if (n0 < 4096) {
                    size_t o0 = ((size_t)row * QW + col) >> 1;
                    size_t o1 = ((size_t)(row + 8) * QW + col) >> 1;
                    ((uint32_t*)g_qh)[o0] = hsplit_hi(ox0, oy0);
                    ((uint32_t*)g_ql)[o0] = hsplit_lo(ox0, oy0);
                    ((uint32_t*)g_qh)[o1] = hsplit_hi(ox1, oy1);
                    ((uint32_t*)g_ql)[o1] = hsplit_lo(ox1, oy1);
                } else {
                    ((uint32_t*)g_kf)[((size_t)row * KW + col) >> 1] = hsplit_hi(ox0, oy0);
                    ((uint32_t*)g_kf)[((size_t)(row + 8) * KW + col) >> 1] = hsplit_hi(ox1, oy1);
                }
            } else {
                int col = n0 - 5120 + coll;
                ((uint32_t*)g_vf)[((size_t)row * KW + col) >> 1] = hsplit_hi(v0, v1);
                ((uint32_t*)g_vf)[((size_t)(row + 8) * KW + col) >> 1] = hsplit_hi(v2, v3);
            }
        }
    }
}

// gemm_wo: output projection, 1-term (A = O single fp16 in g_xf), fp32 C out.
__global__ __launch_bounds__(512, 1)
void gemm_wo(float* __restrict__ C)
{
    extern __shared__ char smc[];
    const uint32_t sb = smem_u32(smc);
    const int tid  = threadIdx.x;
    const int lane = tid & 31;
    const int wid  = tid >> 5;
    const int warp_m = wid >> 2;
    const int warp_n = wid & 3;
    const int m0 = blockIdx.y * 256;
    const int n0 = blockIdx.x * 128;
    const int K = QW;
    const int NT = K >> 6;
    const int N = DIM;

    const __half* Bp = g_wo + (size_t)n0 * K;
    GEMM1_PROLOGUE(g_xf, Bp)
    GEMM1_LOOP()

#pragma unroll
    for (int mt = 0; mt < 4; mt++) {
        int row = m0 + warp_m * 64 + mt * 16 + (lane >> 2);
#pragma unroll
        for (int nt = 0; nt < 4; nt++) {
            int col = n0 + warp_n * 32 + nt * 8 + (lane & 3) * 2;
            *(float2*)(C + (size_t)row * N + col) =
                make_float2(acc[mt][nt][0], acc[mt][nt][1]);
            *(float2*)(C + (size_t)(row + 8) * N + col) =
                make_float2(acc[mt][nt][2], acc[mt][nt][3]);
        }
    }
}

// ---------------------------------------------------------------------------
// flash_mma2: FA2-style causal attention (Q split, K/V single, P split).
// O written as single fp16 into g_xf. qb processed DESCENDING for wave packing.
// ---------------------------------------------------------------------------
#define FA4_SMEM 139264

__global__ __launch_bounds__(256, 1)
void flash_mma2()
{
    extern __shared__ char sm2[];
    const uint32_t sb = smem_u32(sm2);
    const int qb = (int)gridDim.x - 1 - (int)blockIdx.x;   // heavy blocks first
    const int h = blockIdx.y, b = blockIdx.z;
    const int kvh = h >> 2;
    const int tid = threadIdx.x, lane = tid & 31, w = tid >> 5;
    const float SC = 0.08838834764831845f;
    const uint32_t oQl = 34816u, oKV0 = 69632u, KVST = 34816u;

    {
        const size_t qrb = (size_t)(b * SEQ + qb * 128) * QW + h * HD;
#pragma unroll
        for (int j = 0; j < 16; j++) {
            int g = tid + 256 * j;
            int buf = g >> 11, idx = g & 2047;
            int row = idx >> 4, c16 = idx & 15;
            const __half* src = (buf ? g_ql : g_qh) + qrb + (size_t)row * QW + c16 * 8;
            CP_ASYNC16(sb + (uint32_t)buf * oQl + (uint32_t)row * 272u + (uint32_t)c16 * 16u, src);
        }
    }

#define ISSUE_KV(kb_) do { \
        const size_t rb_ = (size_t)(b * SEQ + (kb_) * 64) * KW + kvh * HD; \
        const uint32_t st_ = sb + oKV0 + (uint32_t)((kb_) & 1) * KVST; \
        _Pragma("unroll") \
        for (int j = 0; j < 8; j++) { \
            int g = tid + 256 * j; \
            int buf = g >> 10, idx = g & 1023; \
            int row = idx >> 4, c16 = idx & 15; \
            const __half* src = (buf ? g_vf : g_kf) + rb_ + (size_t)row * KW + c16 * 8; \
            CP_ASYNC16(st_ + (uint32_t)buf * 17408u + (uint32_t)row * 272u + (uint32_t)c16 * 16u, src); \
        } \
        CP_COMMIT(); \
    } while (0)

    ISSUE_KV(0);

    float acc_o[16][4];
#pragma unroll
    for (int n = 0; n < 16; n++)
#pragma unroll
        for (int d = 0; d < 4; d++) acc_o[n][d] = 0.0f;
    float mA = -CUDART_INF_F, mB = -CUDART_INF_F, lA = 0.0f, lB = 0.0f;

    const int growA = qb * 128 + w * 16 + (lane >> 2);
    const uint32_t qa  = sb + (uint32_t)(w * 16 + (lane & 15)) * 272u + (uint32_t)(lane >> 4) * 16u;
    const uint32_t lrw = (uint32_t)(lane & 15) * 272u + (uint32_t)(lane >> 4) * 16u;

    const int NT = 2 * qb + 2;
    for (int kb = 0; kb < NT; kb++) {
        CP_WAIT(0);
        __syncthreads();
        if (kb + 1 < NT) ISSUE_KV(kb + 1);

        if (kb * 64 > qb * 128 + w * 16 + 15) continue;

        const uint32_t kvst = sb + oKV0 + (uint32_t)(kb & 1) * KVST;
        const uint32_t kvb  = kvst + lrw;
        const uint32_t vvb  = kvst + 17408u + lrw;

        float accs[8][4];
#pragma unroll
        for (int n = 0; n < 8; n++)
#pragma unroll
            for (int d = 0; d < 4; d++) accs[n][d] = 0.0f;

#pragma unroll
        for (int k16 = 0; k16 < 8; k16++) {
            const uint32_t ko = (uint32_t)k16 * 32u;
            uint32_t qh[4], ql[4];
            LDSM4(qh[0], qh[1], qh[2], qh[3], qa + ko);
            LDSM4(ql[0], ql[1], ql[2], ql[3], qa + oQl + ko);
#pragma unroll
            for (int g4 = 0; g4 < 4; g4++) {
                uint32_t ka = kvb + (uint32_t)g4 * (16u * 272u) + ko;
                uint32_t kh[4];
                LDSM4(kh[0], kh[1], kh[2], kh[3], ka);
#pragma unroll
                for (int hf = 0; hf < 2; hf++) {
                    const int nt = g4 * 2 + hf;
                    MMA16816(accs[nt], qh, kh[hf], kh[hf + 2]);
                    MMA16816(accs[nt], ql, kh[hf], kh[hf + 2]);
                }
            }
        }

        const bool need_mask = (kb * 64 + 63 > qb * 128 + w * 16);
#pragma unroll
        for (int nt = 0; nt < 8; nt++) {
            int col = kb * 64 + nt * 8 + (lane & 3) * 2;
            float s0 = accs[nt][0] * SC, s1 = accs[nt][1] * SC;
            float s2 = accs[nt][2] * SC, s3 = accs[nt][3] * SC;
            if (need_mask) {
                if (col     > growA)     s0 = -1e9f;
                if (col + 1 > growA)     s1 = -1e9f;
                if (col     > growA + 8) s2 = -1e9f;
                if (col + 1 > growA + 8) s3 = -1e9f;
            }
            accs[nt][0] = s0; accs[nt][1] = s1; accs[nt][2] = s2; accs[nt][3] = s3;
        }

        float mrA = -CUDART_INF_F, mrB = -CUDART_INF_F;
#pragma unroll
        for (int nt = 0; nt < 8; nt++) {
            mrA = fmaxf(mrA, fmaxf(accs[nt][0], accs[nt][1]));
            mrB = fmaxf(mrB, fmaxf(accs[nt][2], accs[nt][3]));
        }
        mrA = fmaxf(mrA, __shfl_xor_sync(0xffffffffu, mrA, 1));
        mrA = fmaxf(mrA, __shfl_xor_sync(0xffffffffu, mrA, 2));
        mrB = fmaxf(mrB, __shfl_xor_sync(0xffffffffu, mrB, 1));
        mrB = fmaxf(mrB, __shfl_xor_sync(0xffffffffu, mrB, 2));
        float mnA = fmaxf(mA, mrA), mnB = fmaxf(mB, mrB);
        float corrA = __expf(mA - mnA), corrB = __expf(mB - mnB);
        mA = mnA; mB = mnB;

        float sumA = 0.0f, sumB = 0.0f;
#pragma unroll
        for (int nt = 0; nt < 8; nt++) {
            float p0 = __expf(accs[nt][0] - mnA);
            float p1 = __expf(accs[nt][1] - mnA);
            float p2 = __expf(accs[nt][2] - mnB);
            float p3 = __expf(accs[nt][3] - mnB);
            sumA += p0 + p1; sumB += p2 + p3;
            accs[nt][0] = p0; accs[nt][1] = p1; accs[nt][2] = p2; accs[nt][3] = p3;
        }
        sumA += __shfl_xor_sync(0xffffffffu, sumA, 1);
        sumA += __shfl_xor_sync(0xffffffffu, sumA, 2);
        sumB += __shfl_xor_sync(0xffffffffu, sumB, 1);
        sumB += __shfl_xor_sync(0xffffffffu, sumB, 2);
        lA = lA * corrA + sumA;
        lB = lB * corrB + sumB;

#pragma unroll
        for (int nt = 0; nt < 16; nt++) {
            acc_o[nt][0] *= corrA; acc_o[nt][1] *= corrA;
            acc_o[nt][2] *= corrB; acc_o[nt][3] *= corrB;
        }

#pragma unroll
        for (int kk = 0; kk < 4; kk++) {
            uint32_t aH[4], aL[4];
            aH[0] = hsplit_hi(accs[2*kk][0], accs[2*kk][1]);
            aH[1] = hsplit_hi(accs[2*kk][2], accs[2*kk][3]);
            aH[2] = hsplit_hi(accs[2*kk+1][0], accs[2*kk+1][1]);
            aH[3] = hsplit_hi(accs[2*kk+1][2], accs[2*kk+1][3]);
            aL[0] = hsplit_lo(accs[2*kk][0], accs[2*kk][1]);
            aL[1] = hsplit_lo(accs[2*kk][2], accs[2*kk][3]);
            aL[2] = hsplit_lo(accs[2*kk+1][0], accs[2*kk+1][1]);
            aL[3] = hsplit_lo(accs[2*kk+1][2], accs[2*kk+1][3]);
#pragma unroll
            for (int g = 0; g < 8; g++) {
                uint32_t va = vvb + (uint32_t)kk * (16u * 272u) + (uint32_t)g * 32u;
                uint32_t vh[4];
                LDSM4T(vh[0], vh[1], vh[2], vh[3], va);
                MMA16816(acc_o[2*g],   aH, vh[0], vh[1]);
                MMA16816(acc_o[2*g],   aL, vh[0], vh[1]);
                MMA16816(acc_o[2*g+1], aH, vh[2], vh[3]);
                MMA16816(acc_o[2*g+1], aL, vh[2], vh[3]);
            }
        }
    }

    // ---- epilogue: O/l -> single fp16 into g_xf ----
    {
        float invA = 1.0f / lA, invB = 1.0f / lB;
        uint32_t* of32 = (uint32_t*)g_xf;
        size_t rowA = (size_t)(b * SEQ + qb * 128 + w * 16 + (lane >> 2));
#pragma unroll
        for (int nt = 0; nt < 16; nt++) {
            int col = h * HD + nt * 8 + (lane & 3) * 2;
            of32[(rowA * QW + col) >> 1] =
                hsplit_hi(acc_o[nt][0] * invA, acc_o[nt][1] * invA);
            of32[((rowA + 8) * QW + col) >> 1] =
                hsplit_hi(acc_o[nt][2] * invB, acc_o[nt][3] * invB);
        }
    }
#undef ISSUE_KV
}

// ---------------------------------------------------------------------------
// Launch
// ---------------------------------------------------------------------------
extern "C" void kernel_launch(void* const* d_in, const int* in_sizes, int n_in,
                              void* d_out, int out_size)
{
    const float* x  = (const float*)d_in[0];
    const float* wq = (const float*)d_in[1];
    const float* wk = (const float*)d_in[2];
    const float* wv = (const float*)d_in[3];
    const float* wo = (const float*)d_in[4];
    const float* fc = (const float*)d_in[7];
    const float* fs = (const float*)d_in[8];
    float* out = (float*)d_out;

    __half *pxf, *pwq, *pwk, *pwv, *pwo;
    cudaGetSymbolAddress((void**)&pxf, g_xf);
    cudaGetSymbolAddress((void**)&pwq, g_wq);
    cudaGetSymbolAddress((void**)&pwk, g_wk);
    cudaGetSymbolAddress((void**)&pwv, g_wv);
    cudaGetSymbolAddress((void**)&pwo, g_wo);

    cudaFuncSetAttribute(gemm_qkv, cudaFuncAttributeMaxDynamicSharedMemorySize, (int)G1SMEM);
    cudaFuncSetAttribute(gemm_wo, cudaFuncAttributeMaxDynamicSharedMemorySize, (int)G1SMEM);
    cudaFuncSetAttribute(flash_mma2, cudaFuncAttributeMaxDynamicSharedMemorySize, FA4_SMEM);

    // convert x to single fp16, transpose weights (single fp16)
    convert_half<<<(MROWS * DIM / 4 + 255) / 256, 256>>>(x, pxf, MROWS * DIM / 4);
    transpose_half<<<dim3(QW / 32, DIM / 32), dim3(32, 8)>>>(wq, pwq, DIM, QW);
    transpose_half<<<dim3(KW / 32, DIM / 32), dim3(32, 8)>>>(wk, pwk, DIM, KW);
    transpose_half<<<dim3(KW / 32, DIM / 32), dim3(32, 8)>>>(wv, pwv, DIM, KW);
    transpose_half<<<dim3(DIM / 32, QW / 32), dim3(32, 8)>>>(wo, pwo, QW, DIM);

    // fused QKV projection (x single) + RoPE epilogue — 256x128 tiles
    gemm_qkv<<<dim3(6144 / 128, MROWS / 256), 512, G1SMEM>>>(fc, fs);

    // flash attention (Q split in; O single fp16 out into g_xf)
    flash_mma2<<<dim3(SEQ / 128, NH, BSZ), 256, FA4_SMEM>>>();

    // output projection (single x single) — 256x128 tiles
    gemm_wo<<<dim3(DIM / 128, MROWS / 256), 512, G1SMEM>>>(out);
}

// round 13
// speedup vs baseline: 6.4950x; 1.1052x over previous
#include <cuda_runtime.h>
#include <cuda_fp16.h>
#include <math_constants.h>
#include <cstdint>

#define BSZ   2
#define SEQ   2048
#define DIM   4096
#define NH    32
#define NKV   8
#define HD    128
#define MROWS (BSZ*SEQ)   /* 4096 */
#define QW    (NH*HD)     /* 4096 */
#define KW    (NKV*HD)    /* 1024 */

// ---------------------------------------------------------------------------
// Static device scratch
// ---------------------------------------------------------------------------
__device__ __half g_xf[(size_t)MROWS * DIM];  // x single fp16 -> later O single fp16
__device__ __half g_qf[(size_t)MROWS * QW];   // Q post-RoPE, single fp16
__device__ __half g_kf[(size_t)MROWS * KW];   // K post-RoPE, single fp16
__device__ __half g_vf[(size_t)MROWS * KW];   // V, single fp16
__device__ __half g_wq[(size_t)QW * DIM];     // transposed weights, single fp16
__device__ __half g_wk[(size_t)KW * DIM];
__device__ __half g_wv[(size_t)KW * DIM];
__device__ __half g_wo[(size_t)DIM * QW];

// ---------------------------------------------------------------------------
// PTX helpers
// ---------------------------------------------------------------------------
__device__ __forceinline__ uint32_t smem_u32(const void* p) {
    uint32_t a;
    asm("{ .reg .u64 t; cvta.to.shared.u64 t, %1; cvt.u32.u64 %0, t; }" : "=r"(a) : "l"(p));
    return a;
}
#define CP_ASYNC16(dst, src) \
    asm volatile("cp.async.cg.shared.global [%0], [%1], 16;" :: "r"(dst), "l"(src))
#define CP_COMMIT() asm volatile("cp.async.commit_group;" ::: "memory")
#define CP_WAIT(n)  asm volatile("cp.async.wait_group %0;" :: "n"(n) : "memory")

#define LDSM4(R0, R1, R2, R3, addr) \
    asm volatile("ldmatrix.sync.aligned.m8n8.x4.shared.b16 {%0,%1,%2,%3}, [%4];" \
        : "=r"(R0), "=r"(R1), "=r"(R2), "=r"(R3) : "r"(addr))
#define LDSM4T(R0, R1, R2, R3, addr) \
    asm volatile("ldmatrix.sync.aligned.m8n8.x4.trans.shared.b16 {%0,%1,%2,%3}, [%4];" \
        : "=r"(R0), "=r"(R1), "=r"(R2), "=r"(R3) : "r"(addr))

#define MMA16816(D, A, B0, B1) \
    asm volatile("mma.sync.aligned.m16n8k16.row.col.f32.f16.f16.f32 " \
        "{%0,%1,%2,%3},{%4,%5,%6,%7},{%8,%9},{%0,%1,%2,%3};" \
        : "+f"((D)[0]), "+f"((D)[1]), "+f"((D)[2]), "+f"((D)[3]) \
        : "r"((A)[0]), "r"((A)[1]), "r"((A)[2]), "r"((A)[3]), "r"(B0), "r"(B1))

__device__ __forceinline__ uint32_t pack_h(__half a, __half b) {
    union { __half h[2]; uint32_t u; } t;
    t.h[0] = a; t.h[1] = b;
    return t.u;
}
__device__ __forceinline__ uint32_t hsplit_hi(float a, float b) {
    return pack_h(__float2half_rn(a), __float2half_rn(b));
}

// ---------------------------------------------------------------------------
// convert_half: fp32 -> fp16 single
// ---------------------------------------------------------------------------
__global__ void convert_half(const float* __restrict__ in,
                             __half* __restrict__ o, int n4)
{
    int i = blockIdx.x * blockDim.x + threadIdx.x;
    if (i >= n4) return;
    float4 v = ((const float4*)in)[i];
    uint2 H;
    H.x = hsplit_hi(v.x, v.y); H.y = hsplit_hi(v.z, v.w);
    ((uint2*)o)[i] = H;
}

// ---------------------------------------------------------------------------
// transpose_half: fp32 [R,C] -> fp16 [C,R] single
// ---------------------------------------------------------------------------
__global__ void transpose_half(const float* __restrict__ in,
                               __half* __restrict__ o, int R, int C)
{
    __shared__ float t[32][33];
    int c0 = blockIdx.x * 32, r0 = blockIdx.y * 32;
    int tx = threadIdx.x, ty = threadIdx.y;
#pragma unroll
    for (int i = 0; i < 4; i++)
        t[ty + 8 * i][tx] = in[(size_t)(r0 + ty + 8 * i) * C + c0 + tx];
    __syncthreads();
#pragma unroll
    for (int i = 0; i < 4; i++)
        o[(size_t)(c0 + ty + 8 * i) * R + r0 + tx] = __float2half_rn(t[tx][ty + 8 * i]);
}

// ===========================================================================
// 1-term GEMM machinery (A single, B single). 256x128 block tile, BK=64,
// 512 threads = 16 warps (4m x 4n), warp tile 64x32, 4 stages.
// Stage: A 0..36863 (256 rows x 144B) | B 36864..55295 (128 rows x 144B).
// Race-safe: stage kt+3 (ring slot (kt-1)%4) issued AFTER the barrier.
// ===========================================================================
#define G1STG  55296u
#define G1SMEM (4u * G1STG)

#define GEMM1_PROLOGUE(AP, BP) \
    uint32_t dstoff[6]; \
    const __half* srcrow[6]; \
    _Pragma("unroll") \
    for (int j = 0; j < 6; j++) { \
        int c   = tid + 512 * j; \
        int bufB = (c >= 2048); \
        int idx = bufB ? (c - 2048) : c; \
        int row = idx >> 3; \
        int kc  = idx & 7; \
        dstoff[j] = (uint32_t)bufB * 36864u + (uint32_t)row * 144u + (uint32_t)kc * 16u; \
        const __half* base = bufB ? (BP) + (size_t)row * K \
                                  : (AP) + (size_t)(m0 + row) * K; \
        srcrow[j] = base + kc * 8; \
    }

#define ISSUE1(kt) do { \
        uint32_t stb = sb + (uint32_t)((kt) & 3) * G1STG; \
        const int kel = (kt) << 6; \
        _Pragma("unroll") \
        for (int j = 0; j < 6; j++) \
            CP_ASYNC16(stb + dstoff[j], srcrow[j] + kel); \
        CP_COMMIT(); \
    } while (0)

#define GEMM1_LOOP() \
    float acc[4][4][4]; \
    _Pragma("unroll") \
    for (int a = 0; a < 4; a++) \
        _Pragma("unroll") \
        for (int b2 = 0; b2 < 4; b2++) \
            _Pragma("unroll") \
            for (int d = 0; d < 4; d++) acc[a][b2][d] = 0.0f; \
    ISSUE1(0); \
    ISSUE1(1); \
    ISSUE1(2); \
    const uint32_t a_lrow = (uint32_t)(warp_m * 64 + (lane & 15)) * 144u + (uint32_t)(lane >> 4) * 16u; \
    const uint32_t b_lrow = 36864u + (uint32_t)(warp_n * 32 + (lane & 15)) * 144u + (uint32_t)(lane >> 4) * 16u; \
    for (int kt = 0; kt < NT; kt++) { \
        if (kt + 2 < NT)      { CP_WAIT(2); } \
        else if (kt + 1 < NT) { CP_WAIT(1); } \
        else                  { CP_WAIT(0); } \
        __syncthreads(); \
        if (kt + 3 < NT) ISSUE1(kt + 3); \
        const uint32_t stb = sb + (uint32_t)(kt & 3) * G1STG; \
        _Pragma("unroll") \
        for (int k16 = 0; k16 < 4; k16++) { \
            const uint32_t koff = (uint32_t)k16 * 32u; \
            uint32_t ah[4][4]; \
            _Pragma("unroll") \
            for (int mt = 0; mt < 4; mt++) { \
                uint32_t addr = stb + a_lrow + (uint32_t)mt * (16u * 144u) + koff; \
                LDSM4(ah[mt][0], ah[mt][1], ah[mt][2], ah[mt][3], addr); \
            } \
            uint32_t bh[2][4]; \
            _Pragma("unroll") \
            for (int bt = 0; bt < 2; bt++) { \
                uint32_t addr = stb + b_lrow + (uint32_t)bt * (16u * 144u) + koff; \
                LDSM4(bh[bt][0], bh[bt][1], bh[bt][2], bh[bt][3], addr); \
            } \
            _Pragma("unroll") \
            for (int mt = 0; mt < 4; mt++) { \
                _Pragma("unroll") \
                for (int nt = 0; nt < 4; nt++) { \
                    const int bt = nt >> 1, hf = nt & 1; \
                    MMA16816(acc[mt][nt], ah[mt], bh[bt][hf], bh[bt][hf + 2]); \
                } \
            } \
        } \
    }

// gemm_qkv: fused QKV projection (A = x single fp16) with RoPE epilogue.
// Virtual N = 6144: cols 0..4095 -> Q (RoPE, single to g_qf),
// 4096..5119 -> K (RoPE, single to g_kf), 5120..6143 -> V (single to g_vf).
__global__ __launch_bounds__(512, 1)
void gemm_qkv(const float* __restrict__ fc, const float* __restrict__ fs)
{
    extern __shared__ char smc[];
    const uint32_t sb = smem_u32(smc);
    const int tid  = threadIdx.x;
    const int lane = tid & 31;
    const int wid  = tid >> 5;
    const int warp_m = wid >> 2;
    const int warp_n = wid & 3;
    const int m0 = blockIdx.y * 256;
    const int n0 = blockIdx.x * 128;
    const int K = DIM;
    const int NT = K >> 6;

    const __half* Bp;
    if (n0 < 4096)      Bp = g_wq + (size_t)n0 * K;
    else if (n0 < 5120) Bp = g_wk + (size_t)(n0 - 4096) * K;
    else                Bp = g_wv + (size_t)(n0 - 5120) * K;

    GEMM1_PROLOGUE(g_xf, Bp)
    GEMM1_LOOP()

#pragma unroll
    for (int mt = 0; mt < 4; mt++) {
        int row = m0 + warp_m * 64 + mt * 16 + (lane >> 2);
        int s0 = row & (SEQ - 1);
        int s1 = (row + 8) & (SEQ - 1);
#pragma unroll
        for (int nt = 0; nt < 4; nt++) {
            int coll = warp_n * 32 + nt * 8 + (lane & 3) * 2;
            float v0 = acc[mt][nt][0], v1 = acc[mt][nt][1];
            float v2 = acc[mt][nt][2], v3 = acc[mt][nt][3];
            if (n0 < 5120) {
                int col = (n0 < 4096) ? (n0 + coll) : (n0 - 4096 + coll);
                int i = (col & (HD - 1)) >> 1;
                float c0 = fc[s0 * 64 + i], sn0 = fs[s0 * 64 + i];
                float c1 = fc[s1 * 64 + i], sn1 = fs[s1 * 64 + i];
                float ox0 = v0 * c0 - v1 * sn0, oy0 = v0 * sn0 + v1 * c0;
                float ox1 = v2 * c1 - v3 * sn1, oy1 = v2 * sn1 + v3 * c1;
                if (n0 < 4096) {
                    ((uint32_t*)g_qf)[((size_t)row * QW + col) >> 1] = hsplit_hi(ox0, oy0);
                    ((uint32_t*)g_qf)[((size_t)(row + 8) * QW + col) >> 1] = hsplit_hi(ox1, oy1);
                } else {
                    ((uint32_t*)g_kf)[((size_t)row * KW + col) >> 1] = hsplit_hi(ox0, oy0);
                    ((uint32_t*)g_kf)[((size_t)(row + 8) * KW + col) >> 1] = hsplit_hi(ox1, oy1);
                }
            } else {
                int col = n0 - 5120 + coll;
                ((uint32_t*)g_vf)[((size_t)row * KW + col) >> 1] = hsplit_hi(v0, v1);
                ((uint32_t*)g_vf)[((size_t)(row + 8) * KW + col) >> 1] = hsplit_hi(v2, v3);
            }
        }
    }
}

// gemm_wo: output projection, 1-term (A = O single fp16 in g_xf), fp32 C out.
__global__ __launch_bounds__(512, 1)
void gemm_wo(float* __restrict__ C)
{
    extern __shared__ char smc[];
    const uint32_t sb = smem_u32(smc);
    const int tid  = threadIdx.x;
    const int lane = tid & 31;
    const int wid  = tid >> 5;
    const int warp_m = wid >> 2;
    const int warp_n = wid & 3;
    const int m0 = blockIdx.y * 256;
    const int n0 = blockIdx.x * 128;
    const int K = QW;
    const int NT = K >> 6;
    const int N = DIM;

    const __half* Bp = g_wo + (size_t)n0 * K;
    GEMM1_PROLOGUE(g_xf, Bp)
    GEMM1_LOOP()

#pragma unroll
    for (int mt = 0; mt < 4; mt++) {
        int row = m0 + warp_m * 64 + mt * 16 + (lane >> 2);
#pragma unroll
        for (int nt = 0; nt < 4; nt++) {
            int col = n0 + warp_n * 32 + nt * 8 + (lane & 3) * 2;
            *(float2*)(C + (size_t)row * N + col) =
                make_float2(acc[mt][nt][0], acc[mt][nt][1]);
            *(float2*)(C + (size_t)(row + 8) * N + col) =
                make_float2(acc[mt][nt][2], acc[mt][nt][3]);
        }
    }
}

// ---------------------------------------------------------------------------
// flash_mma2: FA2-style causal attention, ALL single fp16 (Q, K, V, P).
// 1-term QK^T + 1-term PV = 2 MMAs per logical tile. O single fp16 to g_xf.
// smem: Q 0..34815 | stage s at 34816+s*34816 {K 0, V +17408}. Pitch 272B.
// Total 104448 B. qb processed DESCENDING for wave packing.
// ---------------------------------------------------------------------------
#define FA5_SMEM 104448

__global__ __launch_bounds__(256, 1)
void flash_mma2()
{
    extern __shared__ char sm2[];
    const uint32_t sb = smem_u32(sm2);
    const int qb = (int)gridDim.x - 1 - (int)blockIdx.x;   // heavy blocks first
    const int h = blockIdx.y, b = blockIdx.z;
    const int kvh = h >> 2;
    const int tid = threadIdx.x, lane = tid & 31, w = tid >> 5;
    const float SC = 0.08838834764831845f;
    const uint32_t oKV0 = 34816u, KVST = 34816u;

    // ---- Q tile (128 rows x 128 cols, single fp16) via cp.async ----
    {
        const size_t qrb = (size_t)(b * SEQ + qb * 128) * QW + h * HD;
#pragma unroll
        for (int j = 0; j < 8; j++) {
            int g = tid + 256 * j;
            int row = g >> 4, c16 = g & 15;
            const __half* src = g_qf + qrb + (size_t)row * QW + c16 * 8;
            CP_ASYNC16(sb + (uint32_t)row * 272u + (uint32_t)c16 * 16u, src);
        }
    }

#define ISSUE_KV(kb_) do { \
        const size_t rb_ = (size_t)(b * SEQ + (kb_) * 64) * KW + kvh * HD; \
        const uint32_t st_ = sb + oKV0 + (uint32_t)((kb_) & 1) * KVST; \
        _Pragma("unroll") \
        for (int j = 0; j < 8; j++) { \
            int g = tid + 256 * j; \
            int buf = g >> 10, idx = g & 1023; \
            int row = idx >> 4, c16 = idx & 15; \
            const __half* src = (buf ? g_vf : g_kf) + rb_ + (size_t)row * KW + c16 * 8; \
            CP_ASYNC16(st_ + (uint32_t)buf * 17408u + (uint32_t)row * 272u + (uint32_t)c16 * 16u, src); \
        } \
        CP_COMMIT(); \
    } while (0)

    ISSUE_KV(0);   // commits Q loads too

    float acc_o[16][4];
#pragma unroll
    for (int n = 0; n < 16; n++)
#pragma unroll
        for (int d = 0; d < 4; d++) acc_o[n][d] = 0.0f;
    float mA = -CUDART_INF_F, mB = -CUDART_INF_F, lA = 0.0f, lB = 0.0f;

    const int growA = qb * 128 + w * 16 + (lane >> 2);
    const uint32_t qa  = sb + (uint32_t)(w * 16 + (lane & 15)) * 272u + (uint32_t)(lane >> 4) * 16u;
    const uint32_t lrw = (uint32_t)(lane & 15) * 272u + (uint32_t)(lane >> 4) * 16u;

    const int NT = 2 * qb + 2;
    for (int kb = 0; kb < NT; kb++) {
        CP_WAIT(0);
        __syncthreads();
        if (kb + 1 < NT) ISSUE_KV(kb + 1);

        if (kb * 64 > qb * 128 + w * 16 + 15) continue;   // fully masked for this warp

        const uint32_t kvst = sb + oKV0 + (uint32_t)(kb & 1) * KVST;
        const uint32_t kvb  = kvst + lrw;
        const uint32_t vvb  = kvst + 17408u + lrw;

        // ---- S = Q K^T (single fp16, 1-term) ----
        float accs[8][4];
#pragma unroll
        for (int n = 0; n < 8; n++)
#pragma unroll
            for (int d = 0; d < 4; d++) accs[n][d] = 0.0f;

#pragma unroll
        for (int k16 = 0; k16 < 8; k16++) {
            const uint32_t ko = (uint32_t)k16 * 32u;
            uint32_t qh[4];
            LDSM4(qh[0], qh[1], qh[2], qh[3], qa + ko);
#pragma unroll
            for (int g4 = 0; g4 < 4; g4++) {
                uint32_t ka = kvb + (uint32_t)g4 * (16u * 272u) + ko;
                uint32_t kh[4];
                LDSM4(kh[0], kh[1], kh[2], kh[3], ka);
                MMA16816(accs[g4 * 2],     qh, kh[0], kh[2]);
                MMA16816(accs[g4 * 2 + 1], qh, kh[1], kh[3]);
            }
        }

        // ---- scale + causal mask ----
        const bool need_mask = (kb * 64 + 63 > qb * 128 + w * 16);
#pragma unroll
        for (int nt = 0; nt < 8; nt++) {
            int col = kb * 64 + nt * 8 + (lane & 3) * 2;
            float s0 = accs[nt][0] * SC, s1 = accs[nt][1] * SC;
            float s2 = accs[nt][2] * SC, s3 = accs[nt][3] * SC;
            if (need_mask) {
                if (col     > growA)     s0 = -1e9f;
                if (col + 1 > growA)     s1 = -1e9f;
                if (col     > growA + 8) s2 = -1e9f;
                if (col + 1 > growA + 8) s3 = -1e9f;
            }
            accs[nt][0] = s0; accs[nt][1] = s1; accs[nt][2] = s2; accs[nt][3] = s3;
        }

        // ---- online softmax (quad shuffles) ----
        float mrA = -CUDART_INF_F, mrB = -CUDART_INF_F;
#pragma unroll
        for (int nt = 0; nt < 8; nt++) {
            mrA = fmaxf(mrA, fmaxf(accs[nt][0], accs[nt][1]));
            mrB = fmaxf(mrB, fmaxf(accs[nt][2], accs[nt][3]));
        }
        mrA = fmaxf(mrA, __shfl_xor_sync(0xffffffffu, mrA, 1));
        mrA = fmaxf(mrA, __shfl_xor_sync(0xffffffffu, mrA, 2));
        mrB = fmaxf(mrB, __shfl_xor_sync(0xffffffffu, mrB, 1));
        mrB = fmaxf(mrB, __shfl_xor_sync(0xffffffffu, mrB, 2));
        float mnA = fmaxf(mA, mrA), mnB = fmaxf(mB, mrB);
        float corrA = __expf(mA - mnA), corrB = __expf(mB - mnB);
        mA = mnA; mB = mnB;

        float sumA = 0.0f, sumB = 0.0f;
#pragma unroll
        for (int nt = 0; nt < 8; nt++) {
            float p0 = __expf(accs[nt][0] - mnA);
            float p1 = __expf(accs[nt][1] - mnA);
            float p2 = __expf(accs[nt][2] - mnB);
            float p3 = __expf(accs[nt][3] - mnB);
            sumA += p0 + p1; sumB += p2 + p3;
            accs[nt][0] = p0; accs[nt][1] = p1; accs[nt][2] = p2; accs[nt][3] = p3;
        }
        sumA += __shfl_xor_sync(0xffffffffu, sumA, 1);
        sumA += __shfl_xor_sync(0xffffffffu, sumA, 2);
        sumB += __shfl_xor_sync(0xffffffffu, sumB, 1);
        sumB += __shfl_xor_sync(0xffffffffu, sumB, 2);
        lA = lA * corrA + sumA;
        lB = lB * corrB + sumB;

        // ---- rescale O ----
#pragma unroll
        for (int nt = 0; nt < 16; nt++) {
            acc_o[nt][0] *= corrA; acc_o[nt][1] *= corrA;
            acc_o[nt][2] *= corrB; acc_o[nt][3] *= corrB;
        }

        // ---- O += P V (P single fp16 in registers, V single) ----
#pragma unroll
        for (int kk = 0; kk < 4; kk++) {
            uint32_t aH[4];
            aH[0] = hsplit_hi(accs[2*kk][0],   accs[2*kk][1]);
            aH[1] = hsplit_hi(accs[2*kk][2],   accs[2*kk][3]);
            aH[2] = hsplit_hi(accs[2*kk+1][0], accs[2*kk+1][1]);
            aH[3] = hsplit_hi(accs[2*kk+1][2], accs[2*kk+1][3]);
#pragma unroll
            for (int g = 0; g < 8; g++) {
                uint32_t va = vvb + (uint32_t)kk * (16u * 272u) + (uint32_t)g * 32u;
                uint32_t vh[4];
                LDSM4T(vh[0], vh[1], vh[2], vh[3], va);
                MMA16816(acc_o[2*g],   aH, vh[0], vh[1]);
                MMA16816(acc_o[2*g+1], aH, vh[2], vh[3]);
            }
        }
    }

    // ---- epilogue: O/l -> single fp16 into g_xf ----
    {
        float invA = 1.0f / lA, invB = 1.0f / lB;
        uint32_t* of32 = (uint32_t*)g_xf;
        size_t rowA = (size_t)(b * SEQ + qb * 128 + w * 16 + (lane >> 2));
#pragma unroll
        for (int nt = 0; nt < 16; nt++) {
            int col = h * HD + nt * 8 + (lane & 3) * 2;
            of32[(rowA * QW + col) >> 1] =
                hsplit_hi(acc_o[nt][0] * invA, acc_o[nt][1] * invA);
            of32[((rowA + 8) * QW + col) >> 1] =
                hsplit_hi(acc_o[nt][2] * invB, acc_o[nt][3] * invB);
        }
    }
#undef ISSUE_KV
}

// ---------------------------------------------------------------------------
// Launch
// ---------------------------------------------------------------------------
extern "C" void kernel_launch(void* const* d_in, const int* in_sizes, int n_in,
                              void* d_out, int out_size)
{
    const float* x  = (const float*)d_in[0];
    const float* wq = (const float*)d_in[1];
    const float* wk = (const float*)d_in[2];
    const float* wv = (const float*)d_in[3];
    const float* wo = (const float*)d_in[4];
    const float* fc = (const float*)d_in[7];
    const float* fs = (const float*)d_in[8];
    float* out = (float*)d_out;

    __half *pxf, *pwq, *pwk, *pwv, *pwo;
    cudaGetSymbolAddress((void**)&pxf, g_xf);
    cudaGetSymbolAddress((void**)&pwq, g_wq);
    cudaGetSymbolAddress((void**)&pwk, g_wk);
    cudaGetSymbolAddress((void**)&pwv, g_wv);
    cudaGetSymbolAddress((void**)&pwo, g_wo);

    cudaFuncSetAttribute(gemm_qkv, cudaFuncAttributeMaxDynamicSharedMemorySize, (int)G1SMEM);
    cudaFuncSetAttribute(gemm_wo, cudaFuncAttributeMaxDynamicSharedMemorySize, (int)G1SMEM);
    cudaFuncSetAttribute(flash_mma2, cudaFuncAttributeMaxDynamicSharedMemorySize, FA5_SMEM);

    // convert x to single fp16, transpose weights (single fp16)
    convert_half<<<(MROWS * DIM / 4 + 255) / 256, 256>>>(x, pxf, MROWS * DIM / 4);
    transpose_half<<<dim3(QW / 32, DIM / 32), dim3(32, 8)>>>(wq, pwq, DIM, QW);
    transpose_half<<<dim3(KW / 32, DIM / 32), dim3(32, 8)>>>(wk, pwk, DIM, KW);
    transpose_half<<<dim3(KW / 32, DIM / 32), dim3(32, 8)>>>(wv, pwv, DIM, KW);
    transpose_half<<<dim3(DIM / 32, QW / 32), dim3(32, 8)>>>(wo, pwo, QW, DIM);

    // fused QKV projection (x single) + RoPE epilogue — 256x128 tiles
    gemm_qkv<<<dim3(6144 / 128, MROWS / 256), 512, G1SMEM>>>(fc, fs);

    // flash attention (all single fp16; O single fp16 out into g_xf)
    flash_mma2<<<dim3(SEQ / 128, NH, BSZ), 256, FA5_SMEM>>>();

    // output projection (single x single) — 256x128 tiles
    gemm_wo<<<dim3(DIM / 128, MROWS / 256), 512, G1SMEM>>>(out);
}